// round 4
// baseline (speedup 1.0000x reference)
#include <cuda_runtime.h>
#include <cstdint>

#define N_NODES 50000
#define N_EDGES 800000
#define HID 128

// Persistent scratch (allocation-free rule: __device__ globals)
__device__ float g_hA[(size_t)N_NODES * HID];
__device__ float g_hB[(size_t)N_NODES * HID];
__device__ int   g_deg[N_NODES];
__device__ int   g_off[N_NODES];
__device__ int   g_cursor[N_NODES];
__device__ int   g_csr[N_EDGES];
__device__ int   g_total;
__device__ int   g_is64;

// f32x2 packed-FMA helpers (sm_100+; ptxas never emits these from C++)
#define FMA2(d, a, b) asm("fma.rn.f32x2 %0,%1,%2,%0;" : "+l"(d) : "l"(a), "l"(b))
#define PACK2(d, x, y) asm("mov.b64 %0,{%1,%2};" : "=l"(d) : "f"(x), "f"(y))
#define UNPACK2(x, y, d) asm("mov.b64 {%0,%1},%2;" : "=f"(x), "=f"(y) : "l"(d))

__device__ __forceinline__ void cp_async16(uint32_t saddr, const void* gptr) {
    asm volatile("cp.async.cg.shared.global [%0], [%1], 16;" ::"r"(saddr), "l"(gptr));
}
#define CP_COMMIT() asm volatile("cp.async.commit_group;")
#define CP_WAIT0()  asm volatile("cp.async.wait_group 0;")

// ---------------------------------------------------------------------------
// CSR build (no scan): zero+detect -> histogram -> warp-agg base alloc -> fill
// ---------------------------------------------------------------------------
__global__ void zero_deg_kernel(const long long* __restrict__ ei) {
    int i = blockIdx.x * blockDim.x + threadIdx.x;
    if (i < N_NODES) g_deg[i] = 0;
    if (i == 0) {
        g_total = 0;
        int ok = 1;
        for (int k = 0; k < 64; k++) {
            long long v = ei[k];
            if (v < 0 || v >= N_NODES) { ok = 0; break; }
        }
        g_is64 = ok;
    }
}

__global__ void hist_kernel(const void* __restrict__ ei) {
    const int is64 = g_is64;
    const long long* e64 = (const long long*)ei;
    const int* e32 = (const int*)ei;
    size_t i = (size_t)blockIdx.x * blockDim.x + threadIdx.x;
    const size_t stride = (size_t)gridDim.x * blockDim.x;
    for (size_t e = i; e < (size_t)N_EDGES; e += stride) {
        int dst = is64 ? (int)e64[N_EDGES + e] : e32[N_EDGES + e];
        atomicAdd(&g_deg[dst], 1);
    }
}

// Segment bases need only be disjoint, not ordered: warp shfl-scan + one
// atomicAdd per warp on a global cursor.
__global__ void alloc_kernel() {
    int i = blockIdx.x * blockDim.x + threadIdx.x;
    int lane = threadIdx.x & 31;
    int valid = (i < N_NODES);
    int d = valid ? g_deg[i] : 0;
    int inc = d;
#pragma unroll
    for (int o = 1; o < 32; o <<= 1) {
        int n = __shfl_up_sync(0xffffffffu, inc, o);
        if (lane >= o) inc += n;
    }
    int wsum = __shfl_sync(0xffffffffu, inc, 31);
    int base = 0;
    if (lane == 31) base = atomicAdd(&g_total, wsum);
    base = __shfl_sync(0xffffffffu, base, 31);
    if (valid) {
        int b = base + inc - d;
        g_off[i] = b;
        g_cursor[i] = b;
    }
}

__global__ void fill_kernel(const void* __restrict__ ei) {
    const int is64 = g_is64;
    const long long* e64 = (const long long*)ei;
    const int* e32 = (const int*)ei;
    size_t i = (size_t)blockIdx.x * blockDim.x + threadIdx.x;
    const size_t stride = (size_t)gridDim.x * blockDim.x;
    for (size_t e = i; e < (size_t)N_EDGES; e += stride) {
        int src, dst;
        if (is64) { src = (int)e64[e]; dst = (int)e64[N_EDGES + e]; }
        else      { src = e32[e];      dst = e32[N_EDGES + e]; }
        int pos = atomicAdd(&g_cursor[dst], 1);
        g_csr[pos] = src;
    }
}

// ---------------------------------------------------------------------------
// Fused GIN layer: gather + 2-layer MLP, ping-pong h buffers (no in-place
// hazard: reads only hin, writes only hout rows owned by this block).
//   z[n] = (1+eps[l])*hin[n] + sum_{s in N(n)} hin[s]     (gather -> smem)
//   t = relu(z @ Wa + ba);  hout[n] = relu(t @ Wb + bb)
// Block: 128 rows, 256 threads (8 warps, 16 nodes/warp for gather);
// GEMM: 8 rows x 8 cols (4 f32x2 pairs) per thread.
// ---------------------------------------------------------------------------
#define ZPAD 136   // zs row stride (floats): 544B, 16B-aligned rows
#define MLP_SMEM (size_t)((128 * ZPAD + 2 * 128 * 128) * sizeof(float))  // 196.6KB

__global__ __launch_bounds__(256) void layer_kernel(
    const float* __restrict__ hin, float* __restrict__ hout,
    const float* __restrict__ eps, int l,
    const float* __restrict__ Wa, const float* __restrict__ ba,
    const float* __restrict__ Wb, const float* __restrict__ bb) {
    extern __shared__ float sm[];
    float* zs  = sm;               // 128 x 136
    float* wsa = sm + 128 * ZPAD;  // 128 x 128 (Wa)
    float* wsb = wsa + 128 * 128;  // 128 x 128 (Wb)

    const int tid = threadIdx.x;
    const int warp = tid >> 5;
    const int lane = tid & 31;
    const int tx = tid & 15, ty = tid >> 4;
    const int row0 = blockIdx.x * 128;

    // Kick off weight loads first; they stream in under the gather.
    const float4* wa4 = (const float4*)Wa;
    const float4* wb4 = (const float4*)Wb;
    for (int i = tid; i < 128 * 32; i += 256) {
        uint32_t dst = (uint32_t)__cvta_generic_to_shared(&wsa[(i >> 5) * 128 + (i & 31) * 4]);
        cp_async16(dst, &wa4[i]);
    }
    for (int i = tid; i < 128 * 32; i += 256) {
        uint32_t dst = (uint32_t)__cvta_generic_to_shared(&wsb[(i >> 5) * 128 + (i & 31) * 4]);
        cp_async16(dst, &wb4[i]);
    }
    CP_COMMIT();

    // Gather: warp w handles node rows [row0+w*16, row0+w*16+16)
    const float sc_ = 1.0f + eps[l];
    const float4* h4 = (const float4*)hin;
    for (int n = 0; n < 16; n++) {
        const int r = warp * 16 + n;
        const int node = row0 + r;
        float4 a0 = make_float4(0.f, 0.f, 0.f, 0.f);
        if (node < N_NODES) {
            const int s0 = __ldg(&g_off[node]);
            const int s1 = s0 + __ldg(&g_deg[node]);
            float4 a1 = make_float4(0.f, 0.f, 0.f, 0.f);
            float4 a2 = make_float4(0.f, 0.f, 0.f, 0.f);
            float4 a3 = make_float4(0.f, 0.f, 0.f, 0.f);
            int i = s0;
            for (; i + 3 < s1; i += 4) {
                int sa = __ldg(&g_csr[i]);
                int sb = __ldg(&g_csr[i + 1]);
                int sc = __ldg(&g_csr[i + 2]);
                int sd = __ldg(&g_csr[i + 3]);
                float4 va = __ldg(&h4[(size_t)sa * 32 + lane]);
                float4 vb = __ldg(&h4[(size_t)sb * 32 + lane]);
                float4 vc = __ldg(&h4[(size_t)sc * 32 + lane]);
                float4 vd = __ldg(&h4[(size_t)sd * 32 + lane]);
                a0.x += va.x; a0.y += va.y; a0.z += va.z; a0.w += va.w;
                a1.x += vb.x; a1.y += vb.y; a1.z += vb.z; a1.w += vb.w;
                a2.x += vc.x; a2.y += vc.y; a2.z += vc.z; a2.w += vc.w;
                a3.x += vd.x; a3.y += vd.y; a3.z += vd.z; a3.w += vd.w;
            }
            for (; i < s1; i++) {
                int sa = __ldg(&g_csr[i]);
                float4 va = __ldg(&h4[(size_t)sa * 32 + lane]);
                a0.x += va.x; a0.y += va.y; a0.z += va.z; a0.w += va.w;
            }
            a0.x += a1.x + a2.x + a3.x;
            a0.y += a1.y + a2.y + a3.y;
            a0.z += a1.z + a2.z + a3.z;
            a0.w += a1.w + a2.w + a3.w;
            float4 hv = __ldg(&h4[(size_t)node * 32 + lane]);
            a0.x = fmaf(sc_, hv.x, a0.x);
            a0.y = fmaf(sc_, hv.y, a0.y);
            a0.z = fmaf(sc_, hv.z, a0.z);
            a0.w = fmaf(sc_, hv.w, a0.w);
        }
        *(float4*)&zs[r * ZPAD + lane * 4] = a0;
    }
    CP_WAIT0();
    __syncthreads();

    unsigned long long acc[8][4];
#pragma unroll
    for (int i = 0; i < 8; i++)
#pragma unroll
        for (int j = 0; j < 4; j++) acc[i][j] = 0ull;

    // Stage 1: z @ Wa
#pragma unroll 2
    for (int k4 = 0; k4 < 32; k4++) {
        float4 a4[8];
#pragma unroll
        for (int i = 0; i < 8; i++)
            a4[i] = *(const float4*)&zs[(ty * 8 + i) * ZPAD + k4 * 4];
#pragma unroll
        for (int kk = 0; kk < 4; kk++) {
            const float* wr = &wsa[(k4 * 4 + kk) * 128 + tx * 8];
            float4 bA = *(const float4*)&wr[0];
            float4 bB = *(const float4*)&wr[4];
            unsigned long long b0, b1, b2, b3;
            PACK2(b0, bA.x, bA.y); PACK2(b1, bA.z, bA.w);
            PACK2(b2, bB.x, bB.y); PACK2(b3, bB.z, bB.w);
#pragma unroll
            for (int i = 0; i < 8; i++) {
                float a = (kk == 0) ? a4[i].x : (kk == 1) ? a4[i].y
                        : (kk == 2) ? a4[i].z : a4[i].w;
                unsigned long long a2; PACK2(a2, a, a);
                FMA2(acc[i][0], a2, b0); FMA2(acc[i][1], a2, b1);
                FMA2(acc[i][2], a2, b2); FMA2(acc[i][3], a2, b3);
            }
        }
    }
    float bi[8];
    *(float4*)&bi[0] = *(const float4*)&ba[tx * 8];
    *(float4*)&bi[4] = *(const float4*)&ba[tx * 8 + 4];
    __syncthreads();

    // t = relu(acc + ba) -> zs
#pragma unroll
    for (int i = 0; i < 8; i++) {
        float t[8];
        UNPACK2(t[0], t[1], acc[i][0]);
        UNPACK2(t[2], t[3], acc[i][1]);
        UNPACK2(t[4], t[5], acc[i][2]);
        UNPACK2(t[6], t[7], acc[i][3]);
#pragma unroll
        for (int j = 0; j < 8; j++) t[j] = fmaxf(t[j] + bi[j], 0.f);
        *(float4*)&zs[(ty * 8 + i) * ZPAD + tx * 8] = *(float4*)&t[0];
        *(float4*)&zs[(ty * 8 + i) * ZPAD + tx * 8 + 4] = *(float4*)&t[4];
    }
    __syncthreads();

#pragma unroll
    for (int i = 0; i < 8; i++)
#pragma unroll
        for (int j = 0; j < 4; j++) acc[i][j] = 0ull;

    // Stage 2: t @ Wb
#pragma unroll 2
    for (int k4 = 0; k4 < 32; k4++) {
        float4 a4[8];
#pragma unroll
        for (int i = 0; i < 8; i++)
            a4[i] = *(const float4*)&zs[(ty * 8 + i) * ZPAD + k4 * 4];
#pragma unroll
        for (int kk = 0; kk < 4; kk++) {
            const float* wr = &wsb[(k4 * 4 + kk) * 128 + tx * 8];
            float4 bA = *(const float4*)&wr[0];
            float4 bB = *(const float4*)&wr[4];
            unsigned long long b0, b1, b2, b3;
            PACK2(b0, bA.x, bA.y); PACK2(b1, bA.z, bA.w);
            PACK2(b2, bB.x, bB.y); PACK2(b3, bB.z, bB.w);
#pragma unroll
            for (int i = 0; i < 8; i++) {
                float a = (kk == 0) ? a4[i].x : (kk == 1) ? a4[i].y
                        : (kk == 2) ? a4[i].z : a4[i].w;
                unsigned long long a2; PACK2(a2, a, a);
                FMA2(acc[i][0], a2, b0); FMA2(acc[i][1], a2, b1);
                FMA2(acc[i][2], a2, b2); FMA2(acc[i][3], a2, b3);
            }
        }
    }
    *(float4*)&bi[0] = *(const float4*)&bb[tx * 8];
    *(float4*)&bi[4] = *(const float4*)&bb[tx * 8 + 4];

    // hout = relu(acc + bb)
#pragma unroll
    for (int i = 0; i < 8; i++) {
        int gr = row0 + ty * 8 + i;
        if (gr < N_NODES) {
            float t[8];
            UNPACK2(t[0], t[1], acc[i][0]);
            UNPACK2(t[2], t[3], acc[i][1]);
            UNPACK2(t[4], t[5], acc[i][2]);
            UNPACK2(t[6], t[7], acc[i][3]);
#pragma unroll
            for (int j = 0; j < 8; j++) t[j] = fmaxf(t[j] + bi[j], 0.f);
            float* o = hout + (size_t)gr * 128 + tx * 8;
            *(float4*)&o[0] = *(float4*)&t[0];
            *(float4*)&o[4] = *(float4*)&t[4];
        }
    }
}

// ---------------------------------------------------------------------------
// Head: out = relu(h @ W1 + b1) @ W2 + b2    (128 -> 64 -> 2), f32x2 stage 1
// ---------------------------------------------------------------------------
#define HPAD 136
#define HEAD_SMEM (size_t)((64 * HPAD + 128 * 64 + 64 * 68) * sizeof(float))

__global__ __launch_bounds__(256) void head_kernel(
    const float* __restrict__ W1, const float* __restrict__ b1,
    const float* __restrict__ W2, const float* __restrict__ b2,
    float* __restrict__ out) {
    extern __shared__ float sm[];
    float* hs = sm;               // 64 x 136
    float* w1 = sm + 64 * HPAD;   // 128 x 64
    float* hid = w1 + 128 * 64;   // 64 x 68

    const int tid = threadIdx.x;
    const int tx = tid & 15, ty = tid >> 4;
    const int row0 = blockIdx.x * 64;

    const float4* h4 = (const float4*)g_hA;
    for (int i = tid; i < 64 * 32; i += 256) {
        int r = i >> 5, c = i & 31;
        int gr = row0 + r;
        float4 v = make_float4(0.f, 0.f, 0.f, 0.f);
        if (gr < N_NODES) v = h4[(size_t)gr * 32 + c];
        *(float4*)&hs[r * HPAD + c * 4] = v;
    }
    const float4* w14 = (const float4*)W1;
    for (int i = tid; i < 128 * 16; i += 256)
        *(float4*)&w1[(i >> 4) * 64 + (i & 15) * 4] = w14[i];
    __syncthreads();

    unsigned long long acc[4][2];
#pragma unroll
    for (int i = 0; i < 4; i++) { acc[i][0] = 0ull; acc[i][1] = 0ull; }

#pragma unroll 2
    for (int k4 = 0; k4 < 32; k4++) {
        float4 a4[4];
#pragma unroll
        for (int i = 0; i < 4; i++)
            a4[i] = *(const float4*)&hs[(ty * 4 + i) * HPAD + k4 * 4];
#pragma unroll
        for (int kk = 0; kk < 4; kk++) {
            float4 bA = *(const float4*)&w1[(k4 * 4 + kk) * 64 + tx * 4];
            unsigned long long b0, b1;
            PACK2(b0, bA.x, bA.y); PACK2(b1, bA.z, bA.w);
#pragma unroll
            for (int i = 0; i < 4; i++) {
                float a = (kk == 0) ? a4[i].x : (kk == 1) ? a4[i].y
                        : (kk == 2) ? a4[i].z : a4[i].w;
                unsigned long long a2; PACK2(a2, a, a);
                FMA2(acc[i][0], a2, b0); FMA2(acc[i][1], a2, b1);
            }
        }
    }
    float bi[4];
    *(float4*)&bi[0] = *(const float4*)&b1[tx * 4];
#pragma unroll
    for (int i = 0; i < 4; i++) {
        float t[4];
        UNPACK2(t[0], t[1], acc[i][0]);
        UNPACK2(t[2], t[3], acc[i][1]);
#pragma unroll
        for (int j = 0; j < 4; j++) t[j] = fmaxf(t[j] + bi[j], 0.f);
        *(float4*)&hid[(ty * 4 + i) * 68 + tx * 4] = *(float4*)&t[0];
    }
    __syncthreads();

    if (tid < 128) {
        int r = tid >> 1, c = tid & 1;
        int gr = row0 + r;
        if (gr < N_NODES) {
            float s = __ldg(&b2[c]);
#pragma unroll 8
            for (int k = 0; k < 64; k++)
                s = fmaf(hid[r * 68 + k], __ldg(&W2[k * 2 + c]), s);
            out[(size_t)gr * 2 + c] = s;
        }
    }
}

// ---------------------------------------------------------------------------
extern "C" void kernel_launch(void* const* d_in, const int* in_sizes, int n_in,
                              void* d_out, int out_size) {
    const float* x   = (const float*)d_in[0];
    const void*  ei  = d_in[1];
    const float* eps = (const float*)d_in[2];
    const float* Wa  = (const float*)d_in[3];
    const float* ba  = (const float*)d_in[4];
    const float* Wb  = (const float*)d_in[5];
    const float* bb  = (const float*)d_in[6];
    const float* W1  = (const float*)d_in[7];
    const float* b1  = (const float*)d_in[8];
    const float* W2  = (const float*)d_in[9];
    const float* b2  = (const float*)d_in[10];
    float* out = (float*)d_out;

    cudaFuncSetAttribute(layer_kernel, cudaFuncAttributeMaxDynamicSharedMemorySize,
                         (int)MLP_SMEM);
    cudaFuncSetAttribute(head_kernel, cudaFuncAttributeMaxDynamicSharedMemorySize,
                         (int)HEAD_SMEM);

    // Per-launch CSR build (edges constant across layers); no scan needed.
    zero_deg_kernel<<<(N_NODES + 255) / 256, 256>>>((const long long*)ei);
    hist_kernel<<<512, 256>>>(ei);
    alloc_kernel<<<(N_NODES + 255) / 256, 256>>>();
    fill_kernel<<<512, 256>>>(ei);

    const int blocks = (N_NODES + 127) / 128;        // 391
    const int head_blocks = (N_NODES + 63) / 64;     // 782

    // Ping-pong: x -> A -> B -> A
    const float* hin[3] = {x, g_hA, g_hB};
    float* hout[3];
    // device-symbol addresses are host-usable with __device__ globals via
    // direct symbol reference in kernel args (we pass pointers):
    // (g_hA / g_hB decay to device pointers inside kernel launches only, so
    //  we pass them via the kernels' parameters using cudaGetSymbolAddress-free
    //  trick: reference them directly — nvcc resolves __device__ arrays in
    //  host code as handles; instead we just launch with explicit pointers)
    // Simplest: obtain addresses once via cudaGetSymbolAddress (allowed; no alloc).
    static float* pA = nullptr; static float* pB = nullptr;
    if (!pA) { cudaGetSymbolAddress((void**)&pA, g_hA); cudaGetSymbolAddress((void**)&pB, g_hB); }
    hout[0] = pA; hin[1] = pA;
    hout[1] = pB; hin[2] = pB;
    hout[2] = pA;

    for (int l = 0; l < 3; l++) {
        layer_kernel<<<blocks, 256, MLP_SMEM>>>(
            hin[l], hout[l], eps, l,
            Wa + (size_t)l * HID * HID, ba + (size_t)l * HID,
            Wb + (size_t)l * HID * HID, bb + (size_t)l * HID);
    }
    head_kernel<<<head_blocks, 256, HEAD_SMEM>>>(W1, b1, W2, b2, out);
}

// round 5
// speedup vs baseline: 1.1546x; 1.1546x over previous
#include <cuda_runtime.h>
#include <cstdint>

#define N_NODES 50000
#define N_EDGES 800000
#define HID 128

// Persistent scratch (allocation-free rule: __device__ globals)
__device__ float g_agg[(size_t)N_NODES * HID];   // holds z = (1+eps)h + agg
__device__ float g_h[(size_t)N_NODES * HID];
__device__ int   g_deg[N_NODES];
__device__ int   g_off[N_NODES];
__device__ int   g_cursor[N_NODES];
__device__ int   g_csr[N_EDGES];
__device__ int   g_total;
__device__ int   g_is64;

// f32x2 packed-FMA helpers (sm_100+; ptxas never emits these from C++)
#define FMA2(d, a, b) asm("fma.rn.f32x2 %0,%1,%2,%0;" : "+l"(d) : "l"(a), "l"(b))
#define PACK2(d, x, y) asm("mov.b64 %0,{%1,%2};" : "=l"(d) : "f"(x), "f"(y))
#define UNPACK2(x, y, d) asm("mov.b64 {%0,%1},%2;" : "=f"(x), "=f"(y) : "l"(d))

__device__ __forceinline__ void cp_async16(uint32_t saddr, const void* gptr) {
    asm volatile("cp.async.cg.shared.global [%0], [%1], 16;" ::"r"(saddr), "l"(gptr));
}
#define CP_COMMIT() asm volatile("cp.async.commit_group;")
#define CP_WAIT0()  asm volatile("cp.async.wait_group 0;")

// ---------------------------------------------------------------------------
// CSR build (no scan): zero+detect -> histogram -> warp-agg base alloc -> fill
// ---------------------------------------------------------------------------
__global__ void zero_deg_kernel(const long long* __restrict__ ei) {
    int i = blockIdx.x * blockDim.x + threadIdx.x;
    if (i < N_NODES) g_deg[i] = 0;
    if (i == 0) {
        g_total = 0;
        int ok = 1;
        for (int k = 0; k < 64; k++) {
            long long v = ei[k];
            if (v < 0 || v >= N_NODES) { ok = 0; break; }
        }
        g_is64 = ok;
    }
}

__global__ void hist_kernel(const void* __restrict__ ei) {
    const int is64 = g_is64;
    const long long* e64 = (const long long*)ei;
    const int* e32 = (const int*)ei;
    size_t i = (size_t)blockIdx.x * blockDim.x + threadIdx.x;
    const size_t stride = (size_t)gridDim.x * blockDim.x;
    for (size_t e = i; e < (size_t)N_EDGES; e += stride) {
        int dst = is64 ? (int)e64[N_EDGES + e] : e32[N_EDGES + e];
        atomicAdd(&g_deg[dst], 1);
    }
}

// Segment bases need only be disjoint, not ordered: warp shfl-scan + one
// atomicAdd per warp on a global cursor.
__global__ void alloc_kernel() {
    int i = blockIdx.x * blockDim.x + threadIdx.x;
    int lane = threadIdx.x & 31;
    int valid = (i < N_NODES);
    int d = valid ? g_deg[i] : 0;
    int inc = d;
#pragma unroll
    for (int o = 1; o < 32; o <<= 1) {
        int n = __shfl_up_sync(0xffffffffu, inc, o);
        if (lane >= o) inc += n;
    }
    int wsum = __shfl_sync(0xffffffffu, inc, 31);
    int base = 0;
    if (lane == 31) base = atomicAdd(&g_total, wsum);
    base = __shfl_sync(0xffffffffu, base, 31);
    if (valid) {
        int b = base + inc - d;
        g_off[i] = b;
        g_cursor[i] = b;
    }
}

__global__ void fill_kernel(const void* __restrict__ ei) {
    const int is64 = g_is64;
    const long long* e64 = (const long long*)ei;
    const int* e32 = (const int*)ei;
    size_t i = (size_t)blockIdx.x * blockDim.x + threadIdx.x;
    const size_t stride = (size_t)gridDim.x * blockDim.x;
    for (size_t e = i; e < (size_t)N_EDGES; e += stride) {
        int src, dst;
        if (is64) { src = (int)e64[e]; dst = (int)e64[N_EDGES + e]; }
        else      { src = e32[e];      dst = e32[N_EDGES + e]; }
        int pos = atomicAdd(&g_cursor[dst], 1);
        g_csr[pos] = src;
    }
}

// ---------------------------------------------------------------------------
// Gather (atomic-free, high occupancy): one warp per node.
//   z[node] = (1+eps[l]) * h[node] + sum_{s in N(node)} h[s]   -> g_agg
// ---------------------------------------------------------------------------
__global__ __launch_bounds__(256) void gather_kernel(
    const float* __restrict__ x, int use_gh,
    const float* __restrict__ eps, int l) {
    const float* h = use_gh ? g_h : x;
    const int node = (int)(((size_t)blockIdx.x * blockDim.x + threadIdx.x) >> 5);
    const int lane = threadIdx.x & 31;
    if (node >= N_NODES) return;
    const int s0 = g_off[node];
    const int s1 = s0 + g_deg[node];
    const float4* h4 = (const float4*)h;

    float4 a0 = make_float4(0.f, 0.f, 0.f, 0.f);
    float4 a1 = make_float4(0.f, 0.f, 0.f, 0.f);
    float4 a2 = make_float4(0.f, 0.f, 0.f, 0.f);
    float4 a3 = make_float4(0.f, 0.f, 0.f, 0.f);
    int i = s0;
    for (; i + 3 < s1; i += 4) {
        int sa = __ldg(&g_csr[i]);
        int sb = __ldg(&g_csr[i + 1]);
        int sc = __ldg(&g_csr[i + 2]);
        int sd = __ldg(&g_csr[i + 3]);
        float4 va = __ldg(&h4[(size_t)sa * 32 + lane]);
        float4 vb = __ldg(&h4[(size_t)sb * 32 + lane]);
        float4 vc = __ldg(&h4[(size_t)sc * 32 + lane]);
        float4 vd = __ldg(&h4[(size_t)sd * 32 + lane]);
        a0.x += va.x; a0.y += va.y; a0.z += va.z; a0.w += va.w;
        a1.x += vb.x; a1.y += vb.y; a1.z += vb.z; a1.w += vb.w;
        a2.x += vc.x; a2.y += vc.y; a2.z += vc.z; a2.w += vc.w;
        a3.x += vd.x; a3.y += vd.y; a3.z += vd.z; a3.w += vd.w;
    }
    for (; i < s1; i++) {
        int sa = __ldg(&g_csr[i]);
        float4 va = __ldg(&h4[(size_t)sa * 32 + lane]);
        a0.x += va.x; a0.y += va.y; a0.z += va.z; a0.w += va.w;
    }
    a0.x += a1.x + a2.x + a3.x;
    a0.y += a1.y + a2.y + a3.y;
    a0.z += a1.z + a2.z + a3.z;
    a0.w += a1.w + a2.w + a3.w;

    const float sc_ = 1.0f + eps[l];
    float4 hv = h4[(size_t)node * 32 + lane];
    a0.x = fmaf(sc_, hv.x, a0.x);
    a0.y = fmaf(sc_, hv.y, a0.y);
    a0.z = fmaf(sc_, hv.z, a0.z);
    a0.w = fmaf(sc_, hv.w, a0.w);
    *(float4*)&g_agg[(size_t)node * 128 + lane * 4] = a0;
}

// ---------------------------------------------------------------------------
// GIN MLP, 64-row tile, 2 CTAs/SM (smem 99.3KB):
//   t = relu(z @ Wa + ba);  h_out = relu(t @ Wb + bb)  -> g_h
// 256 threads; per-thread 4 rows x 8 cols (4 f32x2 pairs). Single W buffer,
// Wb reloaded between stages (co-resident CTA hides the stall).
// ---------------------------------------------------------------------------
#define ZPAD 132   // 132*4=528B rows, 16B-aligned
#define MLP_SMEM (size_t)((64 * ZPAD + 128 * 128) * sizeof(float))  // 99328B

__global__ __launch_bounds__(256) void mlp_kernel(
    const float* __restrict__ Wa, const float* __restrict__ ba,
    const float* __restrict__ Wb, const float* __restrict__ bb) {
    extern __shared__ float sm[];
    float* zs = sm;             // 64 x 132
    float* ws = sm + 64 * ZPAD; // 128 x 128 (Wa then Wb)

    const int tid = threadIdx.x;
    const int tx = tid & 15, ty = tid >> 4;
    const int row0 = blockIdx.x * 64;

    // Async load z tile + Wa
    const float4* z4 = (const float4*)g_agg;
    for (int i = tid; i < 64 * 32; i += 256) {
        int r = i >> 5, c = i & 31;
        int gr = row0 + r;
        uint32_t dst = (uint32_t)__cvta_generic_to_shared(&zs[r * ZPAD + c * 4]);
        if (gr < N_NODES) cp_async16(dst, &z4[(size_t)gr * 32 + c]);
        else *(float4*)&zs[r * ZPAD + c * 4] = make_float4(0.f, 0.f, 0.f, 0.f);
    }
    const float4* wa4 = (const float4*)Wa;
    for (int i = tid; i < 128 * 32; i += 256) {
        uint32_t dst = (uint32_t)__cvta_generic_to_shared(&ws[(i >> 5) * 128 + (i & 31) * 4]);
        cp_async16(dst, &wa4[i]);
    }
    CP_COMMIT();

    float bi[8];
    *(float4*)&bi[0] = __ldg((const float4*)&ba[tx * 8]);
    *(float4*)&bi[4] = __ldg((const float4*)&ba[tx * 8 + 4]);
    float bi2[8];
    *(float4*)&bi2[0] = __ldg((const float4*)&bb[tx * 8]);
    *(float4*)&bi2[4] = __ldg((const float4*)&bb[tx * 8 + 4]);

    CP_WAIT0();
    __syncthreads();

    unsigned long long acc[4][4];
#pragma unroll
    for (int i = 0; i < 4; i++)
#pragma unroll
        for (int j = 0; j < 4; j++) acc[i][j] = 0ull;

    // Stage 1: z @ Wa
#pragma unroll 2
    for (int k4 = 0; k4 < 32; k4++) {
        float4 a4[4];
#pragma unroll
        for (int i = 0; i < 4; i++)
            a4[i] = *(const float4*)&zs[(ty * 4 + i) * ZPAD + k4 * 4];
#pragma unroll
        for (int kk = 0; kk < 4; kk++) {
            const float* wr = &ws[(k4 * 4 + kk) * 128 + tx * 8];
            float4 bA = *(const float4*)&wr[0];
            float4 bB = *(const float4*)&wr[4];
            unsigned long long b0, b1, b2, b3;
            PACK2(b0, bA.x, bA.y); PACK2(b1, bA.z, bA.w);
            PACK2(b2, bB.x, bB.y); PACK2(b3, bB.z, bB.w);
#pragma unroll
            for (int i = 0; i < 4; i++) {
                float a = (kk == 0) ? a4[i].x : (kk == 1) ? a4[i].y
                        : (kk == 2) ? a4[i].z : a4[i].w;
                unsigned long long a2; PACK2(a2, a, a);
                FMA2(acc[i][0], a2, b0); FMA2(acc[i][1], a2, b1);
                FMA2(acc[i][2], a2, b2); FMA2(acc[i][3], a2, b3);
            }
        }
    }
    __syncthreads();   // all stage-1 reads of zs/ws complete

    // t = relu(acc + ba) -> zs ; reload W buffer with Wb
#pragma unroll
    for (int i = 0; i < 4; i++) {
        float t[8];
        UNPACK2(t[0], t[1], acc[i][0]);
        UNPACK2(t[2], t[3], acc[i][1]);
        UNPACK2(t[4], t[5], acc[i][2]);
        UNPACK2(t[6], t[7], acc[i][3]);
#pragma unroll
        for (int j = 0; j < 8; j++) t[j] = fmaxf(t[j] + bi[j], 0.f);
        *(float4*)&zs[(ty * 4 + i) * ZPAD + tx * 8] = *(float4*)&t[0];
        *(float4*)&zs[(ty * 4 + i) * ZPAD + tx * 8 + 4] = *(float4*)&t[4];
    }
    const float4* wb4 = (const float4*)Wb;
    for (int i = tid; i < 128 * 32; i += 256) {
        uint32_t dst = (uint32_t)__cvta_generic_to_shared(&ws[(i >> 5) * 128 + (i & 31) * 4]);
        cp_async16(dst, &wb4[i]);
    }
    CP_COMMIT();
    CP_WAIT0();
    __syncthreads();

#pragma unroll
    for (int i = 0; i < 4; i++)
#pragma unroll
        for (int j = 0; j < 4; j++) acc[i][j] = 0ull;

    // Stage 2: t @ Wb
#pragma unroll 2
    for (int k4 = 0; k4 < 32; k4++) {
        float4 a4[4];
#pragma unroll
        for (int i = 0; i < 4; i++)
            a4[i] = *(const float4*)&zs[(ty * 4 + i) * ZPAD + k4 * 4];
#pragma unroll
        for (int kk = 0; kk < 4; kk++) {
            const float* wr = &ws[(k4 * 4 + kk) * 128 + tx * 8];
            float4 bA = *(const float4*)&wr[0];
            float4 bB = *(const float4*)&wr[4];
            unsigned long long b0, b1, b2, b3;
            PACK2(b0, bA.x, bA.y); PACK2(b1, bA.z, bA.w);
            PACK2(b2, bB.x, bB.y); PACK2(b3, bB.z, bB.w);
#pragma unroll
            for (int i = 0; i < 4; i++) {
                float a = (kk == 0) ? a4[i].x : (kk == 1) ? a4[i].y
                        : (kk == 2) ? a4[i].z : a4[i].w;
                unsigned long long a2; PACK2(a2, a, a);
                FMA2(acc[i][0], a2, b0); FMA2(acc[i][1], a2, b1);
                FMA2(acc[i][2], a2, b2); FMA2(acc[i][3], a2, b3);
            }
        }
    }

    // h_out = relu(acc + bb) -> g_h
#pragma unroll
    for (int i = 0; i < 4; i++) {
        int gr = row0 + ty * 4 + i;
        if (gr < N_NODES) {
            float t[8];
            UNPACK2(t[0], t[1], acc[i][0]);
            UNPACK2(t[2], t[3], acc[i][1]);
            UNPACK2(t[4], t[5], acc[i][2]);
            UNPACK2(t[6], t[7], acc[i][3]);
#pragma unroll
            for (int j = 0; j < 8; j++) t[j] = fmaxf(t[j] + bi2[j], 0.f);
            float* o = g_h + (size_t)gr * 128 + tx * 8;
            *(float4*)&o[0] = *(float4*)&t[0];
            *(float4*)&o[4] = *(float4*)&t[4];
        }
    }
}

// ---------------------------------------------------------------------------
// Head: out = relu(h @ W1 + b1) @ W2 + b2    (128 -> 64 -> 2), f32x2 stage 1
// ---------------------------------------------------------------------------
#define HPAD 132
#define HEAD_SMEM (size_t)((64 * HPAD + 128 * 64 + 64 * 68) * sizeof(float))

__global__ __launch_bounds__(256) void head_kernel(
    const float* __restrict__ W1, const float* __restrict__ b1,
    const float* __restrict__ W2, const float* __restrict__ b2,
    float* __restrict__ out) {
    extern __shared__ float sm[];
    float* hs = sm;               // 64 x 132
    float* w1 = sm + 64 * HPAD;   // 128 x 64
    float* hid = w1 + 128 * 64;   // 64 x 68

    const int tid = threadIdx.x;
    const int tx = tid & 15, ty = tid >> 4;
    const int row0 = blockIdx.x * 64;

    const float4* h4 = (const float4*)g_h;
    for (int i = tid; i < 64 * 32; i += 256) {
        int r = i >> 5, c = i & 31;
        int gr = row0 + r;
        float4 v = make_float4(0.f, 0.f, 0.f, 0.f);
        if (gr < N_NODES) v = h4[(size_t)gr * 32 + c];
        *(float4*)&hs[r * HPAD + c * 4] = v;
    }
    const float4* w14 = (const float4*)W1;
    for (int i = tid; i < 128 * 16; i += 256)
        *(float4*)&w1[(i >> 4) * 64 + (i & 15) * 4] = w14[i];
    __syncthreads();

    unsigned long long acc[4][2];
#pragma unroll
    for (int i = 0; i < 4; i++) { acc[i][0] = 0ull; acc[i][1] = 0ull; }

#pragma unroll 2
    for (int k4 = 0; k4 < 32; k4++) {
        float4 a4[4];
#pragma unroll
        for (int i = 0; i < 4; i++)
            a4[i] = *(const float4*)&hs[(ty * 4 + i) * HPAD + k4 * 4];
#pragma unroll
        for (int kk = 0; kk < 4; kk++) {
            float4 bA = *(const float4*)&w1[(k4 * 4 + kk) * 64 + tx * 4];
            unsigned long long b0, b1;
            PACK2(b0, bA.x, bA.y); PACK2(b1, bA.z, bA.w);
#pragma unroll
            for (int i = 0; i < 4; i++) {
                float a = (kk == 0) ? a4[i].x : (kk == 1) ? a4[i].y
                        : (kk == 2) ? a4[i].z : a4[i].w;
                unsigned long long a2; PACK2(a2, a, a);
                FMA2(acc[i][0], a2, b0); FMA2(acc[i][1], a2, b1);
            }
        }
    }
    float bi[4];
    *(float4*)&bi[0] = *(const float4*)&b1[tx * 4];
#pragma unroll
    for (int i = 0; i < 4; i++) {
        float t[4];
        UNPACK2(t[0], t[1], acc[i][0]);
        UNPACK2(t[2], t[3], acc[i][1]);
#pragma unroll
        for (int j = 0; j < 4; j++) t[j] = fmaxf(t[j] + bi[j], 0.f);
        *(float4*)&hid[(ty * 4 + i) * 68 + tx * 4] = *(float4*)&t[0];
    }
    __syncthreads();

    if (tid < 128) {
        int r = tid >> 1, c = tid & 1;
        int gr = row0 + r;
        if (gr < N_NODES) {
            float s = __ldg(&b2[c]);
#pragma unroll 8
            for (int k = 0; k < 64; k++)
                s = fmaf(hid[r * 68 + k], __ldg(&W2[k * 2 + c]), s);
            out[(size_t)gr * 2 + c] = s;
        }
    }
}

// ---------------------------------------------------------------------------
extern "C" void kernel_launch(void* const* d_in, const int* in_sizes, int n_in,
                              void* d_out, int out_size) {
    const float* x   = (const float*)d_in[0];
    const void*  ei  = d_in[1];
    const float* eps = (const float*)d_in[2];
    const float* Wa  = (const float*)d_in[3];
    const float* ba  = (const float*)d_in[4];
    const float* Wb  = (const float*)d_in[5];
    const float* bb  = (const float*)d_in[6];
    const float* W1  = (const float*)d_in[7];
    const float* b1  = (const float*)d_in[8];
    const float* W2  = (const float*)d_in[9];
    const float* b2  = (const float*)d_in[10];
    float* out = (float*)d_out;

    cudaFuncSetAttribute(mlp_kernel, cudaFuncAttributeMaxDynamicSharedMemorySize,
                         (int)MLP_SMEM);
    cudaFuncSetAttribute(head_kernel, cudaFuncAttributeMaxDynamicSharedMemorySize,
                         (int)HEAD_SMEM);

    // Per-launch CSR build (edges constant across layers); no scan needed.
    zero_deg_kernel<<<(N_NODES + 255) / 256, 256>>>((const long long*)ei);
    hist_kernel<<<512, 256>>>(ei);
    alloc_kernel<<<(N_NODES + 255) / 256, 256>>>();
    fill_kernel<<<512, 256>>>(ei);

    const int gather_blocks = (N_NODES * 32 + 255) / 256;  // warp per node
    const int mlp_blocks = (N_NODES + 63) / 64;            // 782
    const int head_blocks = (N_NODES + 63) / 64;           // 782

    for (int l = 0; l < 3; l++) {
        gather_kernel<<<gather_blocks, 256>>>(x, l > 0 ? 1 : 0, eps, l);
        mlp_kernel<<<mlp_blocks, 256, MLP_SMEM>>>(
            Wa + (size_t)l * HID * HID, ba + (size_t)l * HID,
            Wb + (size_t)l * HID * HID, bb + (size_t)l * HID);
    }
    head_kernel<<<head_blocks, 256, HEAD_SMEM>>>(W1, b1, W2, b2, out);
}

// round 6
// speedup vs baseline: 1.6196x; 1.4027x over previous
#include <cuda_runtime.h>
#include <cstdint>

#define N_NODES 50000
#define N_EDGES 800000
#define HID 128

// Persistent scratch (allocation-free rule: __device__ globals)
__device__ float g_agg[(size_t)N_NODES * HID];   // holds z = (1+eps)h + agg
__device__ float g_h[(size_t)N_NODES * HID];
__device__ int   g_deg[N_NODES];
__device__ int   g_off[N_NODES];
__device__ int   g_cursor[N_NODES];
__device__ int   g_csr[N_EDGES];
__device__ int   g_total;
__device__ int   g_is64;

// f32x2 packed-FMA helpers (sm_100+; ptxas never emits these from C++)
#define FMA2(d, a, b) asm("fma.rn.f32x2 %0,%1,%2,%0;" : "+l"(d) : "l"(a), "l"(b))
#define PACK2(d, x, y) asm("mov.b64 %0,{%1,%2};" : "=l"(d) : "f"(x), "f"(y))
#define UNPACK2(x, y, d) asm("mov.b64 {%0,%1},%2;" : "=f"(x), "=f"(y) : "l"(d))

__device__ __forceinline__ void cp_async16(uint32_t saddr, const void* gptr) {
    asm volatile("cp.async.cg.shared.global [%0], [%1], 16;" ::"r"(saddr), "l"(gptr));
}
#define CP_COMMIT() asm volatile("cp.async.commit_group;")
#define CP_WAIT0()  asm volatile("cp.async.wait_group 0;")

// ---------------------------------------------------------------------------
// CSR build (no scan): zero+detect -> histogram -> warp-agg base alloc -> fill
// ---------------------------------------------------------------------------
__global__ void zero_deg_kernel(const long long* __restrict__ ei) {
    int i = blockIdx.x * blockDim.x + threadIdx.x;
    if (i < N_NODES) g_deg[i] = 0;
    if (i == 0) {
        g_total = 0;
        int ok = 1;
        for (int k = 0; k < 64; k++) {
            long long v = ei[k];
            if (v < 0 || v >= N_NODES) { ok = 0; break; }
        }
        g_is64 = ok;
    }
}

__global__ void hist_kernel(const void* __restrict__ ei) {
    const int is64 = g_is64;
    const long long* e64 = (const long long*)ei;
    const int* e32 = (const int*)ei;
    size_t i = (size_t)blockIdx.x * blockDim.x + threadIdx.x;
    const size_t stride = (size_t)gridDim.x * blockDim.x;
    for (size_t e = i; e < (size_t)N_EDGES; e += stride) {
        int dst = is64 ? (int)e64[N_EDGES + e] : e32[N_EDGES + e];
        atomicAdd(&g_deg[dst], 1);
    }
}

// Segment bases need only be disjoint, not ordered: warp shfl-scan + one
// atomicAdd per warp on a global cursor.
__global__ void alloc_kernel() {
    int i = blockIdx.x * blockDim.x + threadIdx.x;
    int lane = threadIdx.x & 31;
    int valid = (i < N_NODES);
    int d = valid ? g_deg[i] : 0;
    int inc = d;
#pragma unroll
    for (int o = 1; o < 32; o <<= 1) {
        int n = __shfl_up_sync(0xffffffffu, inc, o);
        if (lane >= o) inc += n;
    }
    int wsum = __shfl_sync(0xffffffffu, inc, 31);
    int base = 0;
    if (lane == 31) base = atomicAdd(&g_total, wsum);
    base = __shfl_sync(0xffffffffu, base, 31);
    if (valid) {
        int b = base + inc - d;
        g_off[i] = b;
        g_cursor[i] = b;
    }
}

__global__ void fill_kernel(const void* __restrict__ ei) {
    const int is64 = g_is64;
    const long long* e64 = (const long long*)ei;
    const int* e32 = (const int*)ei;
    size_t i = (size_t)blockIdx.x * blockDim.x + threadIdx.x;
    const size_t stride = (size_t)gridDim.x * blockDim.x;
    for (size_t e = i; e < (size_t)N_EDGES; e += stride) {
        int src, dst;
        if (is64) { src = (int)e64[e]; dst = (int)e64[N_EDGES + e]; }
        else      { src = e32[e];      dst = e32[N_EDGES + e]; }
        int pos = atomicAdd(&g_cursor[dst], 1);
        g_csr[pos] = src;
    }
}

// ---------------------------------------------------------------------------
// Gather (atomic-free, high occupancy): one warp per node.
//   z[node] = (1+eps[l]) * h[node] + sum_{s in N(node)} h[s]   -> g_agg
// ---------------------------------------------------------------------------
__global__ __launch_bounds__(256) void gather_kernel(
    const float* __restrict__ x, int use_gh,
    const float* __restrict__ eps, int l) {
    const float* h = use_gh ? g_h : x;
    const int node = (int)(((size_t)blockIdx.x * blockDim.x + threadIdx.x) >> 5);
    const int lane = threadIdx.x & 31;
    if (node >= N_NODES) return;
    const int s0 = g_off[node];
    const int s1 = s0 + g_deg[node];
    const float4* h4 = (const float4*)h;

    float4 a0 = make_float4(0.f, 0.f, 0.f, 0.f);
    float4 a1 = make_float4(0.f, 0.f, 0.f, 0.f);
    float4 a2 = make_float4(0.f, 0.f, 0.f, 0.f);
    float4 a3 = make_float4(0.f, 0.f, 0.f, 0.f);
    int i = s0;
    for (; i + 3 < s1; i += 4) {
        int sa = __ldg(&g_csr[i]);
        int sb = __ldg(&g_csr[i + 1]);
        int sc = __ldg(&g_csr[i + 2]);
        int sd = __ldg(&g_csr[i + 3]);
        float4 va = __ldg(&h4[(size_t)sa * 32 + lane]);
        float4 vb = __ldg(&h4[(size_t)sb * 32 + lane]);
        float4 vc = __ldg(&h4[(size_t)sc * 32 + lane]);
        float4 vd = __ldg(&h4[(size_t)sd * 32 + lane]);
        a0.x += va.x; a0.y += va.y; a0.z += va.z; a0.w += va.w;
        a1.x += vb.x; a1.y += vb.y; a1.z += vb.z; a1.w += vb.w;
        a2.x += vc.x; a2.y += vc.y; a2.z += vc.z; a2.w += vc.w;
        a3.x += vd.x; a3.y += vd.y; a3.z += vd.z; a3.w += vd.w;
    }
    for (; i < s1; i++) {
        int sa = __ldg(&g_csr[i]);
        float4 va = __ldg(&h4[(size_t)sa * 32 + lane]);
        a0.x += va.x; a0.y += va.y; a0.z += va.z; a0.w += va.w;
    }
    a0.x += a1.x + a2.x + a3.x;
    a0.y += a1.y + a2.y + a3.y;
    a0.z += a1.z + a2.z + a3.z;
    a0.w += a1.w + a2.w + a3.w;

    const float sc_ = 1.0f + eps[l];
    float4 hv = h4[(size_t)node * 32 + lane];
    a0.x = fmaf(sc_, hv.x, a0.x);
    a0.y = fmaf(sc_, hv.y, a0.y);
    a0.z = fmaf(sc_, hv.z, a0.z);
    a0.w = fmaf(sc_, hv.w, a0.w);
    *(float4*)&g_agg[(size_t)node * 128 + lane * 4] = a0;
}

// ---------------------------------------------------------------------------
// GIN MLP: 176-row tile (2-wave packing: 285 blocks on 148 SMs), 256 threads,
// 11 rows x 8 cols per thread, f32x2 FMAs, both weight matrices prefetched.
//   t = relu(z @ Wa + ba);  h_out = relu(t @ Wb + bb)  -> g_h
// ---------------------------------------------------------------------------
#define ROWS 176
#define RPT  11    // rows per thread (16 ty groups x 11 = 176)
#define ZPAD 132   // zs row stride (floats): 528B, 16B-aligned
#define MLP_SMEM (size_t)((ROWS * ZPAD + 2 * 128 * 128) * sizeof(float))  // 224000B

__global__ __launch_bounds__(256) void mlp_kernel(
    const float* __restrict__ Wa, const float* __restrict__ ba,
    const float* __restrict__ Wb, const float* __restrict__ bb) {
    extern __shared__ float sm[];
    float* zs  = sm;                   // ROWS x 132
    float* wsa = sm + ROWS * ZPAD;     // 128 x 128 (Wa)
    float* wsb = wsa + 128 * 128;      // 128 x 128 (Wb, prefetched)

    const int tid = threadIdx.x;
    const int tx = tid & 15, ty = tid >> 4;
    const int row0 = blockIdx.x * ROWS;

    // Async load z tile + Wa + Wb
    const float4* z4 = (const float4*)g_agg;
    for (int i = tid; i < ROWS * 32; i += 256) {
        int r = i >> 5, c = i & 31;
        int gr = row0 + r;
        uint32_t dst = (uint32_t)__cvta_generic_to_shared(&zs[r * ZPAD + c * 4]);
        if (gr < N_NODES) cp_async16(dst, &z4[(size_t)gr * 32 + c]);
        else *(float4*)&zs[r * ZPAD + c * 4] = make_float4(0.f, 0.f, 0.f, 0.f);
    }
    const float4* wa4 = (const float4*)Wa;
    const float4* wb4 = (const float4*)Wb;
    for (int i = tid; i < 128 * 32; i += 256) {
        uint32_t dst = (uint32_t)__cvta_generic_to_shared(&wsa[(i >> 5) * 128 + (i & 31) * 4]);
        cp_async16(dst, &wa4[i]);
    }
    for (int i = tid; i < 128 * 32; i += 256) {
        uint32_t dst = (uint32_t)__cvta_generic_to_shared(&wsb[(i >> 5) * 128 + (i & 31) * 4]);
        cp_async16(dst, &wb4[i]);
    }
    CP_COMMIT();

    float bi[8], bi2[8];
    *(float4*)&bi[0]  = __ldg((const float4*)&ba[tx * 8]);
    *(float4*)&bi[4]  = __ldg((const float4*)&ba[tx * 8 + 4]);
    *(float4*)&bi2[0] = __ldg((const float4*)&bb[tx * 8]);
    *(float4*)&bi2[4] = __ldg((const float4*)&bb[tx * 8 + 4]);

    CP_WAIT0();
    __syncthreads();

    unsigned long long acc[RPT][4];
#pragma unroll
    for (int i = 0; i < RPT; i++)
#pragma unroll
        for (int j = 0; j < 4; j++) acc[i][j] = 0ull;

    // Stage 1: z @ Wa
#pragma unroll 2
    for (int k4 = 0; k4 < 32; k4++) {
        float4 a4[RPT];
#pragma unroll
        for (int i = 0; i < RPT; i++)
            a4[i] = *(const float4*)&zs[(ty * RPT + i) * ZPAD + k4 * 4];
#pragma unroll
        for (int kk = 0; kk < 4; kk++) {
            const float* wr = &wsa[(k4 * 4 + kk) * 128 + tx * 8];
            float4 bA = *(const float4*)&wr[0];
            float4 bB = *(const float4*)&wr[4];
            unsigned long long b0, b1, b2, b3;
            PACK2(b0, bA.x, bA.y); PACK2(b1, bA.z, bA.w);
            PACK2(b2, bB.x, bB.y); PACK2(b3, bB.z, bB.w);
#pragma unroll
            for (int i = 0; i < RPT; i++) {
                float a = (kk == 0) ? a4[i].x : (kk == 1) ? a4[i].y
                        : (kk == 2) ? a4[i].z : a4[i].w;
                unsigned long long a2; PACK2(a2, a, a);
                FMA2(acc[i][0], a2, b0); FMA2(acc[i][1], a2, b1);
                FMA2(acc[i][2], a2, b2); FMA2(acc[i][3], a2, b3);
            }
        }
    }
    __syncthreads();

    // t = relu(acc + ba) -> zs
#pragma unroll
    for (int i = 0; i < RPT; i++) {
        float t[8];
        UNPACK2(t[0], t[1], acc[i][0]);
        UNPACK2(t[2], t[3], acc[i][1]);
        UNPACK2(t[4], t[5], acc[i][2]);
        UNPACK2(t[6], t[7], acc[i][3]);
#pragma unroll
        for (int j = 0; j < 8; j++) t[j] = fmaxf(t[j] + bi[j], 0.f);
        *(float4*)&zs[(ty * RPT + i) * ZPAD + tx * 8] = *(float4*)&t[0];
        *(float4*)&zs[(ty * RPT + i) * ZPAD + tx * 8 + 4] = *(float4*)&t[4];
    }
    __syncthreads();

#pragma unroll
    for (int i = 0; i < RPT; i++)
#pragma unroll
        for (int j = 0; j < 4; j++) acc[i][j] = 0ull;

    // Stage 2: t @ Wb (prefetched)
#pragma unroll 2
    for (int k4 = 0; k4 < 32; k4++) {
        float4 a4[RPT];
#pragma unroll
        for (int i = 0; i < RPT; i++)
            a4[i] = *(const float4*)&zs[(ty * RPT + i) * ZPAD + k4 * 4];
#pragma unroll
        for (int kk = 0; kk < 4; kk++) {
            const float* wr = &wsb[(k4 * 4 + kk) * 128 + tx * 8];
            float4 bA = *(const float4*)&wr[0];
            float4 bB = *(const float4*)&wr[4];
            unsigned long long b0, b1, b2, b3;
            PACK2(b0, bA.x, bA.y); PACK2(b1, bA.z, bA.w);
            PACK2(b2, bB.x, bB.y); PACK2(b3, bB.z, bB.w);
#pragma unroll
            for (int i = 0; i < RPT; i++) {
                float a = (kk == 0) ? a4[i].x : (kk == 1) ? a4[i].y
                        : (kk == 2) ? a4[i].z : a4[i].w;
                unsigned long long a2; PACK2(a2, a, a);
                FMA2(acc[i][0], a2, b0); FMA2(acc[i][1], a2, b1);
                FMA2(acc[i][2], a2, b2); FMA2(acc[i][3], a2, b3);
            }
        }
    }

    // h_out = relu(acc + bb) -> g_h
#pragma unroll
    for (int i = 0; i < RPT; i++) {
        int gr = row0 + ty * RPT + i;
        if (gr < N_NODES) {
            float t[8];
            UNPACK2(t[0], t[1], acc[i][0]);
            UNPACK2(t[2], t[3], acc[i][1]);
            UNPACK2(t[4], t[5], acc[i][2]);
            UNPACK2(t[6], t[7], acc[i][3]);
#pragma unroll
            for (int j = 0; j < 8; j++) t[j] = fmaxf(t[j] + bi2[j], 0.f);
            float* o = g_h + (size_t)gr * 128 + tx * 8;
            *(float4*)&o[0] = *(float4*)&t[0];
            *(float4*)&o[4] = *(float4*)&t[4];
        }
    }
}

// ---------------------------------------------------------------------------
// Head: out = relu(h @ W1 + b1) @ W2 + b2    (128 -> 64 -> 2), f32x2 stage 1
// ---------------------------------------------------------------------------
#define HPAD 132
#define HEAD_SMEM (size_t)((64 * HPAD + 128 * 64 + 64 * 68) * sizeof(float))

__global__ __launch_bounds__(256) void head_kernel(
    const float* __restrict__ W1, const float* __restrict__ b1,
    const float* __restrict__ W2, const float* __restrict__ b2,
    float* __restrict__ out) {
    extern __shared__ float sm[];
    float* hs = sm;               // 64 x 132
    float* w1 = sm + 64 * HPAD;   // 128 x 64
    float* hid = w1 + 128 * 64;   // 64 x 68

    const int tid = threadIdx.x;
    const int tx = tid & 15, ty = tid >> 4;
    const int row0 = blockIdx.x * 64;

    const float4* h4 = (const float4*)g_h;
    for (int i = tid; i < 64 * 32; i += 256) {
        int r = i >> 5, c = i & 31;
        int gr = row0 + r;
        float4 v = make_float4(0.f, 0.f, 0.f, 0.f);
        if (gr < N_NODES) v = h4[(size_t)gr * 32 + c];
        *(float4*)&hs[r * HPAD + c * 4] = v;
    }
    const float4* w14 = (const float4*)W1;
    for (int i = tid; i < 128 * 16; i += 256)
        *(float4*)&w1[(i >> 4) * 64 + (i & 15) * 4] = w14[i];
    __syncthreads();

    unsigned long long acc[4][2];
#pragma unroll
    for (int i = 0; i < 4; i++) { acc[i][0] = 0ull; acc[i][1] = 0ull; }

#pragma unroll 2
    for (int k4 = 0; k4 < 32; k4++) {
        float4 a4[4];
#pragma unroll
        for (int i = 0; i < 4; i++)
            a4[i] = *(const float4*)&hs[(ty * 4 + i) * HPAD + k4 * 4];
#pragma unroll
        for (int kk = 0; kk < 4; kk++) {
            float4 bA = *(const float4*)&w1[(k4 * 4 + kk) * 64 + tx * 4];
            unsigned long long b0, b1;
            PACK2(b0, bA.x, bA.y); PACK2(b1, bA.z, bA.w);
#pragma unroll
            for (int i = 0; i < 4; i++) {
                float a = (kk == 0) ? a4[i].x : (kk == 1) ? a4[i].y
                        : (kk == 2) ? a4[i].z : a4[i].w;
                unsigned long long a2; PACK2(a2, a, a);
                FMA2(acc[i][0], a2, b0); FMA2(acc[i][1], a2, b1);
            }
        }
    }
    float bi[4];
    *(float4*)&bi[0] = *(const float4*)&b1[tx * 4];
#pragma unroll
    for (int i = 0; i < 4; i++) {
        float t[4];
        UNPACK2(t[0], t[1], acc[i][0]);
        UNPACK2(t[2], t[3], acc[i][1]);
#pragma unroll
        for (int j = 0; j < 4; j++) t[j] = fmaxf(t[j] + bi[j], 0.f);
        *(float4*)&hid[(ty * 4 + i) * 68 + tx * 4] = *(float4*)&t[0];
    }
    __syncthreads();

    if (tid < 128) {
        int r = tid >> 1, c = tid & 1;
        int gr = row0 + r;
        if (gr < N_NODES) {
            float s = __ldg(&b2[c]);
#pragma unroll 8
            for (int k = 0; k < 64; k++)
                s = fmaf(hid[r * 68 + k], __ldg(&W2[k * 2 + c]), s);
            out[(size_t)gr * 2 + c] = s;
        }
    }
}

// ---------------------------------------------------------------------------
extern "C" void kernel_launch(void* const* d_in, const int* in_sizes, int n_in,
                              void* d_out, int out_size) {
    const float* x   = (const float*)d_in[0];
    const void*  ei  = d_in[1];
    const float* eps = (const float*)d_in[2];
    const float* Wa  = (const float*)d_in[3];
    const float* ba  = (const float*)d_in[4];
    const float* Wb  = (const float*)d_in[5];
    const float* bb  = (const float*)d_in[6];
    const float* W1  = (const float*)d_in[7];
    const float* b1  = (const float*)d_in[8];
    const float* W2  = (const float*)d_in[9];
    const float* b2  = (const float*)d_in[10];
    float* out = (float*)d_out;

    cudaFuncSetAttribute(mlp_kernel, cudaFuncAttributeMaxDynamicSharedMemorySize,
                         (int)MLP_SMEM);
    cudaFuncSetAttribute(head_kernel, cudaFuncAttributeMaxDynamicSharedMemorySize,
                         (int)HEAD_SMEM);

    // Per-launch CSR build (edges constant across layers); no scan needed.
    zero_deg_kernel<<<(N_NODES + 255) / 256, 256>>>((const long long*)ei);
    hist_kernel<<<512, 256>>>(ei);
    alloc_kernel<<<(N_NODES + 255) / 256, 256>>>();
    fill_kernel<<<512, 256>>>(ei);

    const int gather_blocks = (N_NODES * 32 + 255) / 256;  // warp per node
    const int mlp_blocks = (N_NODES + ROWS - 1) / ROWS;    // 285 -> 2 waves
    const int head_blocks = (N_NODES + 63) / 64;           // 782

    for (int l = 0; l < 3; l++) {
        gather_kernel<<<gather_blocks, 256>>>(x, l > 0 ? 1 : 0, eps, l);
        mlp_kernel<<<mlp_blocks, 256, MLP_SMEM>>>(
            Wa + (size_t)l * HID * HID, ba + (size_t)l * HID,
            Wb + (size_t)l * HID * HID, bb + (size_t)l * HID);
    }
    head_kernel<<<head_blocks, 256, HEAD_SMEM>>>(W1, b1, W2, b2, out);
}

// round 8
// speedup vs baseline: 1.6915x; 1.0444x over previous
#include <cuda_runtime.h>
#include <cuda_bf16.h>
#include <cstdint>

#define N_NODES 50000
#define N_EDGES 800000
#define HID 128

// Persistent scratch (allocation-free rule: __device__ globals)
__device__ float g_agg[(size_t)N_NODES * HID];   // z = (1+eps)h + agg
__device__ float g_h[(size_t)N_NODES * HID];
__device__ int   g_deg[N_NODES];
__device__ int   g_off[N_NODES];
__device__ int   g_cursor[N_NODES];
__device__ int   g_csr[N_EDGES];
__device__ int   g_total;
__device__ int   g_is64;

// f32x2 packed-FMA helpers (head kernel)
#define FMA2(d, a, b) asm("fma.rn.f32x2 %0,%1,%2,%0;" : "+l"(d) : "l"(a), "l"(b))
#define PACK2(d, x, y) asm("mov.b64 %0,{%1,%2};" : "=l"(d) : "f"(x), "f"(y))
#define UNPACK2(x, y, d) asm("mov.b64 {%0,%1},%2;" : "=f"(x), "=f"(y) : "l"(d))

__device__ __forceinline__ void cp_async16(uint32_t saddr, const void* gptr) {
    asm volatile("cp.async.cg.shared.global [%0], [%1], 16;" ::"r"(saddr), "l"(gptr));
}
#define CP_COMMIT() asm volatile("cp.async.commit_group;")
#define CP_WAIT0()  asm volatile("cp.async.wait_group 0;")

__device__ __forceinline__ uint32_t smem_u32(const void* p) {
    return (uint32_t)__cvta_generic_to_shared(p);
}

#define LDMX4(r0, r1, r2, r3, a) \
    asm volatile("ldmatrix.sync.aligned.m8n8.x4.shared.b16 {%0,%1,%2,%3}, [%4];" \
                 : "=r"(r0), "=r"(r1), "=r"(r2), "=r"(r3) : "r"(a))

#define MMA16816(c, a, b0, b1) \
    asm volatile("mma.sync.aligned.m16n8k16.row.col.f32.bf16.bf16.f32 " \
                 "{%0,%1,%2,%3}, {%4,%5,%6,%7}, {%8,%9}, {%0,%1,%2,%3};" \
                 : "+f"((c)[0]), "+f"((c)[1]), "+f"((c)[2]), "+f"((c)[3]) \
                 : "r"((a)[0]), "r"((a)[1]), "r"((a)[2]), "r"((a)[3]), \
                   "r"(b0), "r"(b1))

// bf16 hi/lo split of two floats, packed bf16x2 (low half = first arg)
__device__ __forceinline__ void bf16_split2(float x0, float x1,
                                            uint32_t& hi, uint32_t& lo) {
    __nv_bfloat16 h0 = __float2bfloat16(x0);
    __nv_bfloat16 h1 = __float2bfloat16(x1);
    __nv_bfloat16 l0 = __float2bfloat16(x0 - __bfloat162float(h0));
    __nv_bfloat16 l1 = __float2bfloat16(x1 - __bfloat162float(h1));
    __nv_bfloat162 hp = __halves2bfloat162(h0, h1);
    __nv_bfloat162 lp = __halves2bfloat162(l0, l1);
    hi = *(uint32_t*)&hp;
    lo = *(uint32_t*)&lp;
}

// ---------------------------------------------------------------------------
// CSR build (unchanged from best)
// ---------------------------------------------------------------------------
__global__ void zero_deg_kernel(const long long* __restrict__ ei) {
    int i = blockIdx.x * blockDim.x + threadIdx.x;
    if (i < N_NODES) g_deg[i] = 0;
    if (i == 0) {
        g_total = 0;
        int ok = 1;
        for (int k = 0; k < 64; k++) {
            long long v = ei[k];
            if (v < 0 || v >= N_NODES) { ok = 0; break; }
        }
        g_is64 = ok;
    }
}

__global__ void hist_kernel(const void* __restrict__ ei) {
    const int is64 = g_is64;
    const long long* e64 = (const long long*)ei;
    const int* e32 = (const int*)ei;
    size_t i = (size_t)blockIdx.x * blockDim.x + threadIdx.x;
    const size_t stride = (size_t)gridDim.x * blockDim.x;
    for (size_t e = i; e < (size_t)N_EDGES; e += stride) {
        int dst = is64 ? (int)e64[N_EDGES + e] : e32[N_EDGES + e];
        atomicAdd(&g_deg[dst], 1);
    }
}

__global__ void alloc_kernel() {
    int i = blockIdx.x * blockDim.x + threadIdx.x;
    int lane = threadIdx.x & 31;
    int valid = (i < N_NODES);
    int d = valid ? g_deg[i] : 0;
    int inc = d;
#pragma unroll
    for (int o = 1; o < 32; o <<= 1) {
        int n = __shfl_up_sync(0xffffffffu, inc, o);
        if (lane >= o) inc += n;
    }
    int wsum = __shfl_sync(0xffffffffu, inc, 31);
    int base = 0;
    if (lane == 31) base = atomicAdd(&g_total, wsum);
    base = __shfl_sync(0xffffffffu, base, 31);
    if (valid) {
        int b = base + inc - d;
        g_off[i] = b;
        g_cursor[i] = b;
    }
}

__global__ void fill_kernel(const void* __restrict__ ei) {
    const int is64 = g_is64;
    const long long* e64 = (const long long*)ei;
    const int* e32 = (const int*)ei;
    size_t i = (size_t)blockIdx.x * blockDim.x + threadIdx.x;
    const size_t stride = (size_t)gridDim.x * blockDim.x;
    for (size_t e = i; e < (size_t)N_EDGES; e += stride) {
        int src, dst;
        if (is64) { src = (int)e64[e]; dst = (int)e64[N_EDGES + e]; }
        else      { src = e32[e];      dst = e32[N_EDGES + e]; }
        int pos = atomicAdd(&g_cursor[dst], 1);
        g_csr[pos] = src;
    }
}

// ---------------------------------------------------------------------------
// Gather (unchanged from best)
// ---------------------------------------------------------------------------
__global__ __launch_bounds__(256) void gather_kernel(
    const float* __restrict__ x, int use_gh,
    const float* __restrict__ eps, int l) {
    const float* h = use_gh ? g_h : x;
    const int node = (int)(((size_t)blockIdx.x * blockDim.x + threadIdx.x) >> 5);
    const int lane = threadIdx.x & 31;
    if (node >= N_NODES) return;
    const int s0 = g_off[node];
    const int s1 = s0 + g_deg[node];
    const float4* h4 = (const float4*)h;

    float4 a0 = make_float4(0.f, 0.f, 0.f, 0.f);
    float4 a1 = make_float4(0.f, 0.f, 0.f, 0.f);
    float4 a2 = make_float4(0.f, 0.f, 0.f, 0.f);
    float4 a3 = make_float4(0.f, 0.f, 0.f, 0.f);
    int i = s0;
    for (; i + 3 < s1; i += 4) {
        int sa = __ldg(&g_csr[i]);
        int sb = __ldg(&g_csr[i + 1]);
        int sc = __ldg(&g_csr[i + 2]);
        int sd = __ldg(&g_csr[i + 3]);
        float4 va = __ldg(&h4[(size_t)sa * 32 + lane]);
        float4 vb = __ldg(&h4[(size_t)sb * 32 + lane]);
        float4 vc = __ldg(&h4[(size_t)sc * 32 + lane]);
        float4 vd = __ldg(&h4[(size_t)sd * 32 + lane]);
        a0.x += va.x; a0.y += va.y; a0.z += va.z; a0.w += va.w;
        a1.x += vb.x; a1.y += vb.y; a1.z += vb.z; a1.w += vb.w;
        a2.x += vc.x; a2.y += vc.y; a2.z += vc.z; a2.w += vc.w;
        a3.x += vd.x; a3.y += vd.y; a3.z += vd.z; a3.w += vd.w;
    }
    for (; i < s1; i++) {
        int sa = __ldg(&g_csr[i]);
        float4 va = __ldg(&h4[(size_t)sa * 32 + lane]);
        a0.x += va.x; a0.y += va.y; a0.z += va.z; a0.w += va.w;
    }
    a0.x += a1.x + a2.x + a3.x;
    a0.y += a1.y + a2.y + a3.y;
    a0.z += a1.z + a2.z + a3.z;
    a0.w += a1.w + a2.w + a3.w;

    const float sc_ = 1.0f + eps[l];
    float4 hv = h4[(size_t)node * 32 + lane];
    a0.x = fmaf(sc_, hv.x, a0.x);
    a0.y = fmaf(sc_, hv.y, a0.y);
    a0.z = fmaf(sc_, hv.z, a0.z);
    a0.w = fmaf(sc_, hv.w, a0.w);
    *(float4*)&g_agg[(size_t)node * 128 + lane * 4] = a0;
}

// ---------------------------------------------------------------------------
// bf16-split HMMA MLP (mma.sync.m16n8k16), 176 rows/CTA, 11 warps.
//   z hi/lo in SMEM [m][k] (stride 136 bf16); W^T hi/lo [n][k] (stride 128,
//   XOR chunk swizzle); D = Ah*Bh + Al*Bh + Ah*Bl. No mid-stage barriers.
// ---------------------------------------------------------------------------
#define MROWS 176
#define MTHREADS 352
#define OFF_BA 0
#define OFF_BB 512
#define OFF_ZH 1024
#define OFF_ZL (OFF_ZH + MROWS * 272)        // 48896
#define OFF_WH1 (OFF_ZL + MROWS * 272)       // 96768
#define OFF_WL1 (OFF_WH1 + 32768)            // 129536
#define OFF_WH2 (OFF_WL1 + 32768)            // 162304
#define OFF_WL2 (OFF_WH2 + 32768)            // 195072
#define MLP_SMEM (OFF_WL2 + 32768)           // 227840

// W^T[n][k] swizzled byte offset (k even, stores/loads 4B or 16B chunks)
__device__ __forceinline__ uint32_t wswz(int n, int k) {
    uint32_t chunk = ((uint32_t)(k >> 3)) ^ (uint32_t)(n & 7);
    return (uint32_t)n * 256 + chunk * 16 + (uint32_t)(k & 7) * 2;
}

__global__ __launch_bounds__(MTHREADS) void mlp_mma_kernel(
    const float* __restrict__ Wa, const float* __restrict__ ba,
    const float* __restrict__ Wb, const float* __restrict__ bb) {
    extern __shared__ char smem[];
    float* s_ba = (float*)(smem + OFF_BA);
    float* s_bb = (float*)(smem + OFF_BB);

    const int tid = threadIdx.x;
    const int warp = tid >> 5;
    const int lane = tid & 31;
    const int row0 = blockIdx.x * MROWS;

    // ---- P0: biases; cp.async Wa -> scratchA (z region), Wb -> scratchB (WH2)
    if (tid < 128) { s_ba[tid] = __ldg(&ba[tid]); s_bb[tid] = __ldg(&bb[tid]); }
    const uint32_t scrA = smem_u32(smem + OFF_ZH);
    const uint32_t scrB = smem_u32(smem + OFF_WH2);
    for (int i = tid; i < 4096; i += MTHREADS)
        cp_async16(scrA + i * 16, (const char*)Wa + i * 16);
    for (int i = tid; i < 4096; i += MTHREADS)
        cp_async16(scrB + i * 16, (const char*)Wb + i * 16);
    CP_COMMIT();
    CP_WAIT0();
    __syncthreads();

    // ---- P1: convert Wa -> WH1/WL1; Wb via register stage (in-place region)
    const float* fA = (const float*)(smem + OFF_ZH);   // [k][n], stride 128
    const float* fB = (const float*)(smem + OFF_WH2);
    float rb0[24], rb1[24];
#pragma unroll
    for (int it = 0; it < 24; it++) {
        int pos = tid + it * MTHREADS;
        if (pos < 8192) {
            int n = pos >> 6, kp = pos & 63;
            rb0[it] = fB[(2 * kp) * 128 + n];
            rb1[it] = fB[(2 * kp + 1) * 128 + n];
        }
    }
#pragma unroll
    for (int it = 0; it < 24; it++) {
        int pos = tid + it * MTHREADS;
        if (pos < 8192) {
            int n = pos >> 6, kp = pos & 63, k = 2 * kp;
            uint32_t hi, lo;
            bf16_split2(fA[k * 128 + n], fA[(k + 1) * 128 + n], hi, lo);
            uint32_t b = wswz(n, k);
            *(uint32_t*)(smem + OFF_WH1 + b) = hi;
            *(uint32_t*)(smem + OFF_WL1 + b) = lo;
        }
    }
    __syncthreads();   // scrB reads done; safe to overwrite WH2/WL2
#pragma unroll
    for (int it = 0; it < 24; it++) {
        int pos = tid + it * MTHREADS;
        if (pos < 8192) {
            int n = pos >> 6, kp = pos & 63, k = 2 * kp;
            uint32_t hi, lo;
            bf16_split2(rb0[it], rb1[it], hi, lo);
            uint32_t b = wswz(n, k);
            *(uint32_t*)(smem + OFF_WH2 + b) = hi;
            *(uint32_t*)(smem + OFF_WL2 + b) = lo;
        }
    }
    __syncthreads();   // scratchA reads done too (all P1 reads complete)

    // ---- P2: z -> ZH/ZL (bf16 split), [m][k] stride 272B
    const float4* z4 = (const float4*)g_agg;
#pragma unroll
    for (int it = 0; it < 16; it++) {
        int i = tid + it * MTHREADS;           // 5632 = 16*352
        int r = i >> 5, c = i & 31;
        int gr = row0 + r;
        float4 v = (gr < N_NODES) ? __ldg(&z4[(size_t)gr * 32 + c])
                                  : make_float4(0.f, 0.f, 0.f, 0.f);
        uint32_t h0, l0, h1, l1;
        bf16_split2(v.x, v.y, h0, l0);
        bf16_split2(v.z, v.w, h1, l1);
        *(unsigned long long*)(smem + OFF_ZH + r * 272 + c * 8) =
            (unsigned long long)h0 | ((unsigned long long)h1 << 32);
        *(unsigned long long*)(smem + OFF_ZL + r * 272 + c * 8) =
            (unsigned long long)l0 | ((unsigned long long)l1 << 32);
    }
    __syncthreads();

    // ---- P3: two GEMM stages, warp-independent (warp owns rows 16w..16w+15)
    const uint32_t sbase = smem_u32(smem);
    const int a_m = 16 * warp + (lane & 15);
    const uint32_t a_koff = (uint32_t)((lane >> 4) * 16);  // bytes
    const int b_n = (lane & 7) + ((lane >> 4) << 3);
    const int b_kc = (lane >> 3) & 1;                       // k-half select

    float acc[16][4];
    uint32_t ah[4], al[4], bh[4], bl[4];

#pragma unroll
    for (int stage = 0; stage < 2; stage++) {
        const uint32_t WH = sbase + (stage == 0 ? OFF_WH1 : OFF_WH2);
        const uint32_t WL = sbase + (stage == 0 ? OFF_WL1 : OFF_WL2);
#pragma unroll
        for (int t = 0; t < 16; t++)
#pragma unroll
            for (int j = 0; j < 4; j++) acc[t][j] = 0.f;

#pragma unroll
        for (int ks = 0; ks < 8; ks++) {
            uint32_t aaddr = sbase + OFF_ZH + a_m * 272 + ks * 32 + a_koff;
            LDMX4(ah[0], ah[1], ah[2], ah[3], aaddr);
            aaddr += (OFF_ZL - OFF_ZH);
            LDMX4(al[0], al[1], al[2], al[3], aaddr);
#pragma unroll
            for (int np = 0; np < 8; np++) {
                int nrow = np * 16 + b_n;
                int kk = ks * 16 + b_kc * 8;
                uint32_t boff = wswz(nrow, kk);
                LDMX4(bh[0], bh[1], bh[2], bh[3], WH + boff);
                LDMX4(bl[0], bl[1], bl[2], bl[3], WL + boff);
                MMA16816(acc[2 * np], ah, bh[0], bh[1]);
                MMA16816(acc[2 * np], al, bh[0], bh[1]);
                MMA16816(acc[2 * np], ah, bl[0], bl[1]);
                MMA16816(acc[2 * np + 1], ah, bh[2], bh[3]);
                MMA16816(acc[2 * np + 1], al, bh[2], bh[3]);
                MMA16816(acc[2 * np + 1], ah, bl[2], bl[3]);
            }
        }

        const int m_r = 16 * warp + (lane >> 2);
        if (stage == 0) {
            // t = relu(acc + ba) -> re-split into ZH/ZL (own rows only)
#pragma unroll
            for (int nt = 0; nt < 16; nt++) {
                int col = nt * 8 + 2 * (lane & 3);
                float b0 = s_ba[col], b1 = s_ba[col + 1];
                float v0 = fmaxf(acc[nt][0] + b0, 0.f);
                float v1 = fmaxf(acc[nt][1] + b1, 0.f);
                float v2 = fmaxf(acc[nt][2] + b0, 0.f);
                float v3 = fmaxf(acc[nt][3] + b1, 0.f);
                uint32_t hi, lo;
                bf16_split2(v0, v1, hi, lo);
                *(uint32_t*)(smem + OFF_ZH + m_r * 272 + col * 2) = hi;
                *(uint32_t*)(smem + OFF_ZL + m_r * 272 + col * 2) = lo;
                bf16_split2(v2, v3, hi, lo);
                *(uint32_t*)(smem + OFF_ZH + (m_r + 8) * 272 + col * 2) = hi;
                *(uint32_t*)(smem + OFF_ZL + (m_r + 8) * 272 + col * 2) = lo;
            }
        } else {
            // h_out = relu(acc + bb) -> g_h
            int n0 = row0 + m_r, n1 = n0 + 8;
#pragma unroll
            for (int nt = 0; nt < 16; nt++) {
                int col = nt * 8 + 2 * (lane & 3);
                float b0 = s_bb[col], b1 = s_bb[col + 1];
                if (n0 < N_NODES) {
                    float2 o;
                    o.x = fmaxf(acc[nt][0] + b0, 0.f);
                    o.y = fmaxf(acc[nt][1] + b1, 0.f);
                    *(float2*)(g_h + (size_t)n0 * 128 + col) = o;
                }
                if (n1 < N_NODES) {
                    float2 o;
                    o.x = fmaxf(acc[nt][2] + b0, 0.f);
                    o.y = fmaxf(acc[nt][3] + b1, 0.f);
                    *(float2*)(g_h + (size_t)n1 * 128 + col) = o;
                }
            }
        }
    }
}

// ---------------------------------------------------------------------------
// Head: out = relu(h @ W1 + b1) @ W2 + b2    (128 -> 64 -> 2), f32x2 stage 1
// ---------------------------------------------------------------------------
#define HPAD 132
#define HEAD_SMEM (size_t)((64 * HPAD + 128 * 64 + 64 * 68) * sizeof(float))

__global__ __launch_bounds__(256) void head_kernel(
    const float* __restrict__ W1, const float* __restrict__ b1,
    const float* __restrict__ W2, const float* __restrict__ b2,
    float* __restrict__ out) {
    extern __shared__ float sm[];
    float* hs = sm;               // 64 x 132
    float* w1 = sm + 64 * HPAD;   // 128 x 64
    float* hid = w1 + 128 * 64;   // 64 x 68

    const int tid = threadIdx.x;
    const int tx = tid & 15, ty = tid >> 4;
    const int row0 = blockIdx.x * 64;

    const float4* h4 = (const float4*)g_h;
    for (int i = tid; i < 64 * 32; i += 256) {
        int r = i >> 5, c = i & 31;
        int gr = row0 + r;
        float4 v = make_float4(0.f, 0.f, 0.f, 0.f);
        if (gr < N_NODES) v = h4[(size_t)gr * 32 + c];
        *(float4*)&hs[r * HPAD + c * 4] = v;
    }
    const float4* w14 = (const float4*)W1;
    for (int i = tid; i < 128 * 16; i += 256)
        *(float4*)&w1[(i >> 4) * 64 + (i & 15) * 4] = w14[i];
    __syncthreads();

    unsigned long long acc[4][2];
#pragma unroll
    for (int i = 0; i < 4; i++) { acc[i][0] = 0ull; acc[i][1] = 0ull; }

#pragma unroll 2
    for (int k4 = 0; k4 < 32; k4++) {
        float4 a4[4];
#pragma unroll
        for (int i = 0; i < 4; i++)
            a4[i] = *(const float4*)&hs[(ty * 4 + i) * HPAD + k4 * 4];
#pragma unroll
        for (int kk = 0; kk < 4; kk++) {
            float4 bA = *(const float4*)&w1[(k4 * 4 + kk) * 64 + tx * 4];
            unsigned long long b0, b1;
            PACK2(b0, bA.x, bA.y); PACK2(b1, bA.z, bA.w);
#pragma unroll
            for (int i = 0; i < 4; i++) {
                float a = (kk == 0) ? a4[i].x : (kk == 1) ? a4[i].y
                        : (kk == 2) ? a4[i].z : a4[i].w;
                unsigned long long a2; PACK2(a2, a, a);
                FMA2(acc[i][0], a2, b0); FMA2(acc[i][1], a2, b1);
            }
        }
    }
    float bi[4];
    *(float4*)&bi[0] = *(const float4*)&b1[tx * 4];
#pragma unroll
    for (int i = 0; i < 4; i++) {
        float t[4];
        UNPACK2(t[0], t[1], acc[i][0]);
        UNPACK2(t[2], t[3], acc[i][1]);
#pragma unroll
        for (int j = 0; j < 4; j++) t[j] = fmaxf(t[j] + bi[j], 0.f);
        *(float4*)&hid[(ty * 4 + i) * 68 + tx * 4] = *(float4*)&t[0];
    }
    __syncthreads();

    if (tid < 128) {
        int r = tid >> 1, c = tid & 1;
        int gr = row0 + r;
        if (gr < N_NODES) {
            float s = __ldg(&b2[c]);
#pragma unroll 8
            for (int k = 0; k < 64; k++)
                s = fmaf(hid[r * 68 + k], __ldg(&W2[k * 2 + c]), s);
            out[(size_t)gr * 2 + c] = s;
        }
    }
}

// ---------------------------------------------------------------------------
extern "C" void kernel_launch(void* const* d_in, const int* in_sizes, int n_in,
                              void* d_out, int out_size) {
    const float* x   = (const float*)d_in[0];
    const void*  ei  = d_in[1];
    const float* eps = (const float*)d_in[2];
    const float* Wa  = (const float*)d_in[3];
    const float* ba  = (const float*)d_in[4];
    const float* Wb  = (const float*)d_in[5];
    const float* bb  = (const float*)d_in[6];
    const float* W1  = (const float*)d_in[7];
    const float* b1  = (const float*)d_in[8];
    const float* W2  = (const float*)d_in[9];
    const float* b2  = (const float*)d_in[10];
    float* out = (float*)d_out;

    cudaFuncSetAttribute(mlp_mma_kernel, cudaFuncAttributeMaxDynamicSharedMemorySize,
                         MLP_SMEM);
    cudaFuncSetAttribute(head_kernel, cudaFuncAttributeMaxDynamicSharedMemorySize,
                         (int)HEAD_SMEM);

    // Per-launch CSR build (edges constant across layers)
    zero_deg_kernel<<<(N_NODES + 255) / 256, 256>>>((const long long*)ei);
    hist_kernel<<<512, 256>>>(ei);
    alloc_kernel<<<(N_NODES + 255) / 256, 256>>>();
    fill_kernel<<<512, 256>>>(ei);

    const int gather_blocks = (N_NODES * 32 + 255) / 256;   // warp per node
    const int mlp_blocks = (N_NODES + MROWS - 1) / MROWS;   // 285 -> 2 waves
    const int head_blocks = (N_NODES + 63) / 64;            // 782

    for (int l = 0; l < 3; l++) {
        gather_kernel<<<gather_blocks, 256>>>(x, l > 0 ? 1 : 0, eps, l);
        mlp_mma_kernel<<<mlp_blocks, MTHREADS, MLP_SMEM>>>(
            Wa + (size_t)l * HID * HID, ba + (size_t)l * HID,
            Wb + (size_t)l * HID * HID, bb + (size_t)l * HID);
    }
    head_kernel<<<head_blocks, 256, HEAD_SMEM>>>(W1, b1, W2, b2, out);
}

// round 9
// speedup vs baseline: 2.0090x; 1.1877x over previous
#include <cuda_runtime.h>
#include <cuda_bf16.h>
#include <cstdint>

#define N_NODES 50000
#define N_EDGES 800000
#define HID 128

// Persistent scratch (allocation-free rule: __device__ globals)
__device__ float g_agg[(size_t)N_NODES * HID];   // z = (1+eps)h + agg
__device__ float g_h[(size_t)N_NODES * HID];
__device__ int   g_deg[N_NODES];
__device__ int   g_off[N_NODES];
__device__ int   g_cursor[N_NODES];
__device__ int   g_csr[N_EDGES];
__device__ int   g_total;
__device__ int   g_is64;
__device__ char  g_wt[3 * 4 * 32768];  // pre-swizzled bf16 W tiles: [l][WaH,WaL,WbH,WbL]

// f32x2 packed-FMA helpers (head kernel)
#define FMA2(d, a, b) asm("fma.rn.f32x2 %0,%1,%2,%0;" : "+l"(d) : "l"(a), "l"(b))
#define PACK2(d, x, y) asm("mov.b64 %0,{%1,%2};" : "=l"(d) : "f"(x), "f"(y))
#define UNPACK2(x, y, d) asm("mov.b64 {%0,%1},%2;" : "=f"(x), "=f"(y) : "l"(d))

__device__ __forceinline__ void cp_async16(uint32_t saddr, const void* gptr) {
    asm volatile("cp.async.cg.shared.global [%0], [%1], 16;" ::"r"(saddr), "l"(gptr));
}
#define CP_COMMIT() asm volatile("cp.async.commit_group;")
#define CP_WAIT0()  asm volatile("cp.async.wait_group 0;")

__device__ __forceinline__ uint32_t smem_u32(const void* p) {
    return (uint32_t)__cvta_generic_to_shared(p);
}

#define LDMX4(r0, r1, r2, r3, a) \
    asm volatile("ldmatrix.sync.aligned.m8n8.x4.shared.b16 {%0,%1,%2,%3}, [%4];" \
                 : "=r"(r0), "=r"(r1), "=r"(r2), "=r"(r3) : "r"(a))

#define MMA16816(c, a, b0, b1) \
    asm volatile("mma.sync.aligned.m16n8k16.row.col.f32.bf16.bf16.f32 " \
                 "{%0,%1,%2,%3}, {%4,%5,%6,%7}, {%8,%9}, {%0,%1,%2,%3};" \
                 : "+f"((c)[0]), "+f"((c)[1]), "+f"((c)[2]), "+f"((c)[3]) \
                 : "r"((a)[0]), "r"((a)[1]), "r"((a)[2]), "r"((a)[3]), \
                   "r"(b0), "r"(b1))

// bf16 hi/lo split of two floats, packed bf16x2
__device__ __forceinline__ void bf16_split2(float x0, float x1,
                                            uint32_t& hi, uint32_t& lo) {
    __nv_bfloat16 h0 = __float2bfloat16(x0);
    __nv_bfloat16 h1 = __float2bfloat16(x1);
    __nv_bfloat16 l0 = __float2bfloat16(x0 - __bfloat162float(h0));
    __nv_bfloat16 l1 = __float2bfloat16(x1 - __bfloat162float(h1));
    __nv_bfloat162 hp = __halves2bfloat162(h0, h1);
    __nv_bfloat162 lp = __halves2bfloat162(l0, l1);
    hi = *(uint32_t*)&hp;
    lo = *(uint32_t*)&lp;
}

// W^T[n][k] swizzled byte offset (k even; 4B/16B chunk aligned)
__device__ __forceinline__ uint32_t wswz(int n, int k) {
    uint32_t chunk = ((uint32_t)(k >> 3)) ^ (uint32_t)(n & 7);
    return (uint32_t)n * 256 + chunk * 16 + (uint32_t)(k & 7) * 2;
}

// ---------------------------------------------------------------------------
// One-shot weight conversion: fp32 W[k][n] -> pre-swizzled bf16 hi/lo tiles
// (byte-identical to the SMEM image the MLP kernel wants).
// ---------------------------------------------------------------------------
__global__ void wconv_kernel(const float* __restrict__ Wa,
                             const float* __restrict__ Wb) {
    int idx = blockIdx.x * blockDim.x + threadIdx.x;   // 49152 = 3*2*8192
    int l = idx / 16384;
    int rem = idx - l * 16384;
    int m = rem >> 13;            // 0 = Wa, 1 = Wb
    int pos = rem & 8191;
    int n = pos >> 6;
    int k = (pos & 63) * 2;
    const float* src = (m == 0 ? Wa : Wb) + (size_t)l * 16384;
    uint32_t hi, lo;
    bf16_split2(__ldg(&src[k * 128 + n]), __ldg(&src[(k + 1) * 128 + n]), hi, lo);
    uint32_t b = wswz(n, k);
    char* base = g_wt + ((size_t)l * 4 + m * 2) * 32768;
    *(uint32_t*)(base + b) = hi;
    *(uint32_t*)(base + 32768 + b) = lo;
}

// ---------------------------------------------------------------------------
// CSR build (unchanged from best)
// ---------------------------------------------------------------------------
__global__ void zero_deg_kernel(const long long* __restrict__ ei) {
    int i = blockIdx.x * blockDim.x + threadIdx.x;
    if (i < N_NODES) g_deg[i] = 0;
    if (i == 0) {
        g_total = 0;
        int ok = 1;
        for (int k = 0; k < 64; k++) {
            long long v = ei[k];
            if (v < 0 || v >= N_NODES) { ok = 0; break; }
        }
        g_is64 = ok;
    }
}

__global__ void hist_kernel(const void* __restrict__ ei) {
    const int is64 = g_is64;
    const long long* e64 = (const long long*)ei;
    const int* e32 = (const int*)ei;
    size_t i = (size_t)blockIdx.x * blockDim.x + threadIdx.x;
    const size_t stride = (size_t)gridDim.x * blockDim.x;
    for (size_t e = i; e < (size_t)N_EDGES; e += stride) {
        int dst = is64 ? (int)e64[N_EDGES + e] : e32[N_EDGES + e];
        atomicAdd(&g_deg[dst], 1);
    }
}

__global__ void alloc_kernel() {
    int i = blockIdx.x * blockDim.x + threadIdx.x;
    int lane = threadIdx.x & 31;
    int valid = (i < N_NODES);
    int d = valid ? g_deg[i] : 0;
    int inc = d;
#pragma unroll
    for (int o = 1; o < 32; o <<= 1) {
        int n = __shfl_up_sync(0xffffffffu, inc, o);
        if (lane >= o) inc += n;
    }
    int wsum = __shfl_sync(0xffffffffu, inc, 31);
    int base = 0;
    if (lane == 31) base = atomicAdd(&g_total, wsum);
    base = __shfl_sync(0xffffffffu, base, 31);
    if (valid) {
        int b = base + inc - d;
        g_off[i] = b;
        g_cursor[i] = b;
    }
}

__global__ void fill_kernel(const void* __restrict__ ei) {
    const int is64 = g_is64;
    const long long* e64 = (const long long*)ei;
    const int* e32 = (const int*)ei;
    size_t i = (size_t)blockIdx.x * blockDim.x + threadIdx.x;
    const size_t stride = (size_t)gridDim.x * blockDim.x;
    for (size_t e = i; e < (size_t)N_EDGES; e += stride) {
        int src, dst;
        if (is64) { src = (int)e64[e]; dst = (int)e64[N_EDGES + e]; }
        else      { src = e32[e];      dst = e32[N_EDGES + e]; }
        int pos = atomicAdd(&g_cursor[dst], 1);
        g_csr[pos] = src;
    }
}

// ---------------------------------------------------------------------------
// Gather (unchanged from best)
// ---------------------------------------------------------------------------
__global__ __launch_bounds__(256) void gather_kernel(
    const float* __restrict__ x, int use_gh,
    const float* __restrict__ eps, int l) {
    const float* h = use_gh ? g_h : x;
    const int node = (int)(((size_t)blockIdx.x * blockDim.x + threadIdx.x) >> 5);
    const int lane = threadIdx.x & 31;
    if (node >= N_NODES) return;
    const int s0 = g_off[node];
    const int s1 = s0 + g_deg[node];
    const float4* h4 = (const float4*)h;

    float4 a0 = make_float4(0.f, 0.f, 0.f, 0.f);
    float4 a1 = make_float4(0.f, 0.f, 0.f, 0.f);
    float4 a2 = make_float4(0.f, 0.f, 0.f, 0.f);
    float4 a3 = make_float4(0.f, 0.f, 0.f, 0.f);
    int i = s0;
    for (; i + 3 < s1; i += 4) {
        int sa = __ldg(&g_csr[i]);
        int sb = __ldg(&g_csr[i + 1]);
        int sc = __ldg(&g_csr[i + 2]);
        int sd = __ldg(&g_csr[i + 3]);
        float4 va = __ldg(&h4[(size_t)sa * 32 + lane]);
        float4 vb = __ldg(&h4[(size_t)sb * 32 + lane]);
        float4 vc = __ldg(&h4[(size_t)sc * 32 + lane]);
        float4 vd = __ldg(&h4[(size_t)sd * 32 + lane]);
        a0.x += va.x; a0.y += va.y; a0.z += va.z; a0.w += va.w;
        a1.x += vb.x; a1.y += vb.y; a1.z += vb.z; a1.w += vb.w;
        a2.x += vc.x; a2.y += vc.y; a2.z += vc.z; a2.w += vc.w;
        a3.x += vd.x; a3.y += vd.y; a3.z += vd.z; a3.w += vd.w;
    }
    for (; i < s1; i++) {
        int sa = __ldg(&g_csr[i]);
        float4 va = __ldg(&h4[(size_t)sa * 32 + lane]);
        a0.x += va.x; a0.y += va.y; a0.z += va.z; a0.w += va.w;
    }
    a0.x += a1.x + a2.x + a3.x;
    a0.y += a1.y + a2.y + a3.y;
    a0.z += a1.z + a2.z + a3.z;
    a0.w += a1.w + a2.w + a3.w;

    const float sc_ = 1.0f + eps[l];
    float4 hv = h4[(size_t)node * 32 + lane];
    a0.x = fmaf(sc_, hv.x, a0.x);
    a0.y = fmaf(sc_, hv.y, a0.y);
    a0.z = fmaf(sc_, hv.z, a0.z);
    a0.w = fmaf(sc_, hv.w, a0.w);
    *(float4*)&g_agg[(size_t)node * 128 + lane * 4] = a0;
}

// ---------------------------------------------------------------------------
// bf16-split HMMA MLP: 176 rows/CTA, 6 warps; warps 0-4 own 32 rows (2 m16
// slabs), warp 5 owns 16. B fragments amortized over 2 slabs. Weights arrive
// pre-swizzled from g_wt via linear cp.async. No mid-stage CTA barriers.
// ---------------------------------------------------------------------------
#define MROWS 176
#define MTHREADS 192
#define OFF_ZH 0
#define OFF_ZL 47872
#define OFF_W  95744                 // WH1,WL1,WH2,WL2 (4 x 32768)
#define OFF_BA 226816
#define OFF_BB 227328
#define MLP_SMEM 227840

__global__ __launch_bounds__(MTHREADS) void mlp_mma_kernel(
    int l, const float* __restrict__ ba, const float* __restrict__ bb) {
    extern __shared__ char smem[];
    float* s_ba = (float*)(smem + OFF_BA);
    float* s_bb = (float*)(smem + OFF_BB);

    const int tid = threadIdx.x;
    const int warp = tid >> 5;
    const int lane = tid & 31;
    const int row0 = blockIdx.x * MROWS;

    // P0: linear cp.async of pre-swizzled W tiles (128KB); biases
    const char* wsrc = g_wt + (size_t)l * 131072;
    const uint32_t wdst = smem_u32(smem + OFF_W);
    for (int i = tid; i < 8192; i += MTHREADS)
        cp_async16(wdst + i * 16, wsrc + i * 16);
    CP_COMMIT();
    if (tid < 128) { s_ba[tid] = __ldg(&ba[tid]); s_bb[tid] = __ldg(&bb[tid]); }

    // P1: z -> ZH/ZL bf16 split, [m][k] stride 272B
    const float4* z4 = (const float4*)g_agg;
    for (int i = tid; i < MROWS * 32; i += MTHREADS) {
        int r = i >> 5, c = i & 31;
        int gr = row0 + r;
        float4 v = (gr < N_NODES) ? __ldg(&z4[(size_t)gr * 32 + c])
                                  : make_float4(0.f, 0.f, 0.f, 0.f);
        uint32_t h0, l0, h1, l1;
        bf16_split2(v.x, v.y, h0, l0);
        bf16_split2(v.z, v.w, h1, l1);
        *(unsigned long long*)(smem + OFF_ZH + r * 272 + c * 8) =
            (unsigned long long)h0 | ((unsigned long long)h1 << 32);
        *(unsigned long long*)(smem + OFF_ZL + r * 272 + c * 8) =
            (unsigned long long)l0 | ((unsigned long long)l1 << 32);
    }
    CP_WAIT0();
    __syncthreads();

    // P2: GEMM stages, warp-independent
    const uint32_t sbase = smem_u32(smem);
    const int m0 = warp * 32;                       // warp5 -> 160
    const bool two = (warp < 5);
    const int a_m0 = m0 + (lane & 15);
    const uint32_t a_koff = (uint32_t)((lane >> 4) * 16);
    const int b_n = (lane & 7) + ((lane >> 4) << 3);
    const int b_kc = (lane >> 3) & 1;

    float acc0[16][4], acc1[16][4];
    uint32_t ah0[4], al0[4], ah1[4], al1[4], bh[4], bl[4];

#pragma unroll
    for (int stage = 0; stage < 2; stage++) {
        const uint32_t WH = sbase + OFF_W + (uint32_t)stage * 65536;
        const uint32_t WL = WH + 32768;
#pragma unroll
        for (int t = 0; t < 16; t++)
#pragma unroll
            for (int j = 0; j < 4; j++) { acc0[t][j] = 0.f; acc1[t][j] = 0.f; }

#pragma unroll
        for (int ks = 0; ks < 8; ks++) {
            uint32_t aaddr = sbase + OFF_ZH + a_m0 * 272 + ks * 32 + a_koff;
            LDMX4(ah0[0], ah0[1], ah0[2], ah0[3], aaddr);
            LDMX4(al0[0], al0[1], al0[2], al0[3], aaddr + 47872);
            if (two) {
                uint32_t aaddr1 = aaddr + 16 * 272;
                LDMX4(ah1[0], ah1[1], ah1[2], ah1[3], aaddr1);
                LDMX4(al1[0], al1[1], al1[2], al1[3], aaddr1 + 47872);
            }
#pragma unroll
            for (int np = 0; np < 8; np++) {
                uint32_t boff = wswz(np * 16 + b_n, ks * 16 + b_kc * 8);
                LDMX4(bh[0], bh[1], bh[2], bh[3], WH + boff);
                LDMX4(bl[0], bl[1], bl[2], bl[3], WL + boff);
                MMA16816(acc0[2 * np], ah0, bh[0], bh[1]);
                if (two) MMA16816(acc1[2 * np], ah1, bh[0], bh[1]);
                MMA16816(acc0[2 * np], al0, bh[0], bh[1]);
                if (two) MMA16816(acc1[2 * np], al1, bh[0], bh[1]);
                MMA16816(acc0[2 * np], ah0, bl[0], bl[1]);
                if (two) MMA16816(acc1[2 * np], ah1, bl[0], bl[1]);
                MMA16816(acc0[2 * np + 1], ah0, bh[2], bh[3]);
                if (two) MMA16816(acc1[2 * np + 1], ah1, bh[2], bh[3]);
                MMA16816(acc0[2 * np + 1], al0, bh[2], bh[3]);
                if (two) MMA16816(acc1[2 * np + 1], al1, bh[2], bh[3]);
                MMA16816(acc0[2 * np + 1], ah0, bl[2], bl[3]);
                if (two) MMA16816(acc1[2 * np + 1], ah1, bl[2], bl[3]);
            }
        }

        const int m_r = m0 + (lane >> 2);
        if (stage == 0) {
            // t = relu(acc + ba) -> re-split into ZH/ZL (own rows only)
#pragma unroll
            for (int nt = 0; nt < 16; nt++) {
                int col = nt * 8 + 2 * (lane & 3);
                float b0 = s_ba[col], b1 = s_ba[col + 1];
                uint32_t hi, lo;
                bf16_split2(fmaxf(acc0[nt][0] + b0, 0.f),
                            fmaxf(acc0[nt][1] + b1, 0.f), hi, lo);
                *(uint32_t*)(smem + OFF_ZH + m_r * 272 + col * 2) = hi;
                *(uint32_t*)(smem + OFF_ZL + m_r * 272 + col * 2) = lo;
                bf16_split2(fmaxf(acc0[nt][2] + b0, 0.f),
                            fmaxf(acc0[nt][3] + b1, 0.f), hi, lo);
                *(uint32_t*)(smem + OFF_ZH + (m_r + 8) * 272 + col * 2) = hi;
                *(uint32_t*)(smem + OFF_ZL + (m_r + 8) * 272 + col * 2) = lo;
                if (two) {
                    bf16_split2(fmaxf(acc1[nt][0] + b0, 0.f),
                                fmaxf(acc1[nt][1] + b1, 0.f), hi, lo);
                    *(uint32_t*)(smem + OFF_ZH + (m_r + 16) * 272 + col * 2) = hi;
                    *(uint32_t*)(smem + OFF_ZL + (m_r + 16) * 272 + col * 2) = lo;
                    bf16_split2(fmaxf(acc1[nt][2] + b0, 0.f),
                                fmaxf(acc1[nt][3] + b1, 0.f), hi, lo);
                    *(uint32_t*)(smem + OFF_ZH + (m_r + 24) * 272 + col * 2) = hi;
                    *(uint32_t*)(smem + OFF_ZL + (m_r + 24) * 272 + col * 2) = lo;
                }
            }
            __syncwarp();
        } else {
            // h_out = relu(acc + bb) -> g_h
            int n0 = row0 + m_r;
#pragma unroll
            for (int nt = 0; nt < 16; nt++) {
                int col = nt * 8 + 2 * (lane & 3);
                float b0 = s_bb[col], b1 = s_bb[col + 1];
                if (n0 < N_NODES) {
                    float2 o;
                    o.x = fmaxf(acc0[nt][0] + b0, 0.f);
                    o.y = fmaxf(acc0[nt][1] + b1, 0.f);
                    *(float2*)(g_h + (size_t)n0 * 128 + col) = o;
                }
                if (n0 + 8 < N_NODES) {
                    float2 o;
                    o.x = fmaxf(acc0[nt][2] + b0, 0.f);
                    o.y = fmaxf(acc0[nt][3] + b1, 0.f);
                    *(float2*)(g_h + (size_t)(n0 + 8) * 128 + col) = o;
                }
                if (two) {
                    if (n0 + 16 < N_NODES) {
                        float2 o;
                        o.x = fmaxf(acc1[nt][0] + b0, 0.f);
                        o.y = fmaxf(acc1[nt][1] + b1, 0.f);
                        *(float2*)(g_h + (size_t)(n0 + 16) * 128 + col) = o;
                    }
                    if (n0 + 24 < N_NODES) {
                        float2 o;
                        o.x = fmaxf(acc1[nt][2] + b0, 0.f);
                        o.y = fmaxf(acc1[nt][3] + b1, 0.f);
                        *(float2*)(g_h + (size_t)(n0 + 24) * 128 + col) = o;
                    }
                }
            }
        }
    }
}

// ---------------------------------------------------------------------------
// Head: out = relu(h @ W1 + b1) @ W2 + b2    (128 -> 64 -> 2), f32x2 stage 1
// ---------------------------------------------------------------------------
#define HPAD 132
#define HEAD_SMEM (size_t)((64 * HPAD + 128 * 64 + 64 * 68) * sizeof(float))

__global__ __launch_bounds__(256) void head_kernel(
    const float* __restrict__ W1, const float* __restrict__ b1,
    const float* __restrict__ W2, const float* __restrict__ b2,
    float* __restrict__ out) {
    extern __shared__ float sm[];
    float* hs = sm;               // 64 x 132
    float* w1 = sm + 64 * HPAD;   // 128 x 64
    float* hid = w1 + 128 * 64;   // 64 x 68

    const int tid = threadIdx.x;
    const int tx = tid & 15, ty = tid >> 4;
    const int row0 = blockIdx.x * 64;

    const float4* h4 = (const float4*)g_h;
    for (int i = tid; i < 64 * 32; i += 256) {
        int r = i >> 5, c = i & 31;
        int gr = row0 + r;
        float4 v = make_float4(0.f, 0.f, 0.f, 0.f);
        if (gr < N_NODES) v = h4[(size_t)gr * 32 + c];
        *(float4*)&hs[r * HPAD + c * 4] = v;
    }
    const float4* w14 = (const float4*)W1;
    for (int i = tid; i < 128 * 16; i += 256)
        *(float4*)&w1[(i >> 4) * 64 + (i & 15) * 4] = w14[i];
    __syncthreads();

    unsigned long long acc[4][2];
#pragma unroll
    for (int i = 0; i < 4; i++) { acc[i][0] = 0ull; acc[i][1] = 0ull; }

#pragma unroll 2
    for (int k4 = 0; k4 < 32; k4++) {
        float4 a4[4];
#pragma unroll
        for (int i = 0; i < 4; i++)
            a4[i] = *(const float4*)&hs[(ty * 4 + i) * HPAD + k4 * 4];
#pragma unroll
        for (int kk = 0; kk < 4; kk++) {
            float4 bA = *(const float4*)&w1[(k4 * 4 + kk) * 64 + tx * 4];
            unsigned long long b0, b1;
            PACK2(b0, bA.x, bA.y); PACK2(b1, bA.z, bA.w);
#pragma unroll
            for (int i = 0; i < 4; i++) {
                float a = (kk == 0) ? a4[i].x : (kk == 1) ? a4[i].y
                        : (kk == 2) ? a4[i].z : a4[i].w;
                unsigned long long a2; PACK2(a2, a, a);
                FMA2(acc[i][0], a2, b0); FMA2(acc[i][1], a2, b1);
            }
        }
    }
    float bi[4];
    *(float4*)&bi[0] = *(const float4*)&b1[tx * 4];
#pragma unroll
    for (int i = 0; i < 4; i++) {
        float t[4];
        UNPACK2(t[0], t[1], acc[i][0]);
        UNPACK2(t[2], t[3], acc[i][1]);
#pragma unroll
        for (int j = 0; j < 4; j++) t[j] = fmaxf(t[j] + bi[j], 0.f);
        *(float4*)&hid[(ty * 4 + i) * 68 + tx * 4] = *(float4*)&t[0];
    }
    __syncthreads();

    if (tid < 128) {
        int r = tid >> 1, c = tid & 1;
        int gr = row0 + r;
        if (gr < N_NODES) {
            float s = __ldg(&b2[c]);
#pragma unroll 8
            for (int k = 0; k < 64; k++)
                s = fmaf(hid[r * 68 + k], __ldg(&W2[k * 2 + c]), s);
            out[(size_t)gr * 2 + c] = s;
        }
    }
}

// ---------------------------------------------------------------------------
extern "C" void kernel_launch(void* const* d_in, const int* in_sizes, int n_in,
                              void* d_out, int out_size) {
    const float* x   = (const float*)d_in[0];
    const void*  ei  = d_in[1];
    const float* eps = (const float*)d_in[2];
    const float* Wa  = (const float*)d_in[3];
    const float* ba  = (const float*)d_in[4];
    const float* Wb  = (const float*)d_in[5];
    const float* bb  = (const float*)d_in[6];
    const float* W1  = (const float*)d_in[7];
    const float* b1  = (const float*)d_in[8];
    const float* W2  = (const float*)d_in[9];
    const float* b2  = (const float*)d_in[10];
    float* out = (float*)d_out;

    cudaFuncSetAttribute(mlp_mma_kernel, cudaFuncAttributeMaxDynamicSharedMemorySize,
                         MLP_SMEM);
    cudaFuncSetAttribute(head_kernel, cudaFuncAttributeMaxDynamicSharedMemorySize,
                         (int)HEAD_SMEM);

    // One-shot weight pre-swizzle + per-launch CSR build
    wconv_kernel<<<192, 256>>>(Wa, Wb);
    zero_deg_kernel<<<(N_NODES + 255) / 256, 256>>>((const long long*)ei);
    hist_kernel<<<512, 256>>>(ei);
    alloc_kernel<<<(N_NODES + 255) / 256, 256>>>();
    fill_kernel<<<512, 256>>>(ei);

    const int gather_blocks = (N_NODES * 32 + 255) / 256;   // warp per node
    const int mlp_blocks = (N_NODES + MROWS - 1) / MROWS;   // 285 -> 2 waves
    const int head_blocks = (N_NODES + 63) / 64;            // 782

    for (int l = 0; l < 3; l++) {
        gather_kernel<<<gather_blocks, 256>>>(x, l > 0 ? 1 : 0, eps, l);
        mlp_mma_kernel<<<mlp_blocks, MTHREADS, MLP_SMEM>>>(
            l, ba + (size_t)l * HID, bb + (size_t)l * HID);
    }
    head_kernel<<<head_blocks, 256, HEAD_SMEM>>>(W1, b1, W2, b2, out);
}

// round 10
// speedup vs baseline: 2.1253x; 1.0579x over previous
#include <cuda_runtime.h>
#include <cuda_bf16.h>
#include <cstdint>

#define N_NODES 50000
#define N_EDGES 800000
#define HID 128
#define ZROWS 50176   // padded rows for safe cp.async tails (zero-init .bss)

// Persistent scratch (allocation-free rule: __device__ globals)
__device__ float g_h[(size_t)N_NODES * HID];
__device__ char  g_zh[(size_t)ZROWS * 256];   // z hi, bf16 [node][128]
__device__ char  g_zl[(size_t)ZROWS * 256];   // z lo
__device__ int   g_deg[N_NODES];
__device__ int   g_off[N_NODES];
__device__ int   g_cursor[N_NODES];
__device__ int   g_csr[N_EDGES];
__device__ int   g_total;
__device__ int   g_is64;
__device__ char  g_wt[3 * 4 * 32768];  // pre-swizzled bf16 W tiles: [l][WaH,WaL,WbH,WbL]

// f32x2 packed-FMA helpers (head kernel)
#define FMA2(d, a, b) asm("fma.rn.f32x2 %0,%1,%2,%0;" : "+l"(d) : "l"(a), "l"(b))
#define PACK2(d, x, y) asm("mov.b64 %0,{%1,%2};" : "=l"(d) : "f"(x), "f"(y))
#define UNPACK2(x, y, d) asm("mov.b64 {%0,%1},%2;" : "=f"(x), "=f"(y) : "l"(d))

__device__ __forceinline__ void cp_async16(uint32_t saddr, const void* gptr) {
    asm volatile("cp.async.cg.shared.global [%0], [%1], 16;" ::"r"(saddr), "l"(gptr));
}
#define CP_COMMIT() asm volatile("cp.async.commit_group;")
#define CP_WAIT0()  asm volatile("cp.async.wait_group 0;")

__device__ __forceinline__ uint32_t smem_u32(const void* p) {
    return (uint32_t)__cvta_generic_to_shared(p);
}

#define LDMX4(r0, r1, r2, r3, a) \
    asm volatile("ldmatrix.sync.aligned.m8n8.x4.shared.b16 {%0,%1,%2,%3}, [%4];" \
                 : "=r"(r0), "=r"(r1), "=r"(r2), "=r"(r3) : "r"(a))

#define MMA16816(c, a, b0, b1) \
    asm volatile("mma.sync.aligned.m16n8k16.row.col.f32.bf16.bf16.f32 " \
                 "{%0,%1,%2,%3}, {%4,%5,%6,%7}, {%8,%9}, {%0,%1,%2,%3};" \
                 : "+f"((c)[0]), "+f"((c)[1]), "+f"((c)[2]), "+f"((c)[3]) \
                 : "r"((a)[0]), "r"((a)[1]), "r"((a)[2]), "r"((a)[3]), \
                   "r"(b0), "r"(b1))

// bf16 hi/lo split of two floats, packed bf16x2
__device__ __forceinline__ void bf16_split2(float x0, float x1,
                                            uint32_t& hi, uint32_t& lo) {
    __nv_bfloat16 h0 = __float2bfloat16(x0);
    __nv_bfloat16 h1 = __float2bfloat16(x1);
    __nv_bfloat16 l0 = __float2bfloat16(x0 - __bfloat162float(h0));
    __nv_bfloat16 l1 = __float2bfloat16(x1 - __bfloat162float(h1));
    __nv_bfloat162 hp = __halves2bfloat162(h0, h1);
    __nv_bfloat162 lp = __halves2bfloat162(l0, l1);
    hi = *(uint32_t*)&hp;
    lo = *(uint32_t*)&lp;
}

// W^T[n][k] swizzled byte offset (k even; 4B/16B chunk aligned)
__device__ __forceinline__ uint32_t wswz(int n, int k) {
    uint32_t chunk = ((uint32_t)(k >> 3)) ^ (uint32_t)(n & 7);
    return (uint32_t)n * 256 + chunk * 16 + (uint32_t)(k & 7) * 2;
}

// ---------------------------------------------------------------------------
// One-shot weight conversion: fp32 W[k][n] -> pre-swizzled bf16 hi/lo tiles
// ---------------------------------------------------------------------------
__global__ void wconv_kernel(const float* __restrict__ Wa,
                             const float* __restrict__ Wb) {
    int idx = blockIdx.x * blockDim.x + threadIdx.x;   // 49152 = 3*2*8192
    int l = idx / 16384;
    int rem = idx - l * 16384;
    int m = rem >> 13;            // 0 = Wa, 1 = Wb
    int pos = rem & 8191;
    int n = pos >> 6;
    int k = (pos & 63) * 2;
    const float* src = (m == 0 ? Wa : Wb) + (size_t)l * 16384;
    uint32_t hi, lo;
    bf16_split2(__ldg(&src[k * 128 + n]), __ldg(&src[(k + 1) * 128 + n]), hi, lo);
    uint32_t b = wswz(n, k);
    char* base = g_wt + ((size_t)l * 4 + m * 2) * 32768;
    *(uint32_t*)(base + b) = hi;
    *(uint32_t*)(base + 32768 + b) = lo;
}

// ---------------------------------------------------------------------------
// CSR build
// ---------------------------------------------------------------------------
__global__ void zero_deg_kernel(const long long* __restrict__ ei) {
    int i = blockIdx.x * blockDim.x + threadIdx.x;
    if (i < N_NODES) g_deg[i] = 0;
    if (i == 0) {
        g_total = 0;
        int ok = 1;
        for (int k = 0; k < 64; k++) {
            long long v = ei[k];
            if (v < 0 || v >= N_NODES) { ok = 0; break; }
        }
        g_is64 = ok;
    }
}

__global__ void hist_kernel(const void* __restrict__ ei) {
    const int is64 = g_is64;
    const long long* e64 = (const long long*)ei;
    const int* e32 = (const int*)ei;
    size_t i = (size_t)blockIdx.x * blockDim.x + threadIdx.x;
    const size_t stride = (size_t)gridDim.x * blockDim.x;
    for (size_t e = i; e < (size_t)N_EDGES; e += stride) {
        int dst = is64 ? (int)e64[N_EDGES + e] : e32[N_EDGES + e];
        atomicAdd(&g_deg[dst], 1);
    }
}

__global__ void alloc_kernel() {
    int i = blockIdx.x * blockDim.x + threadIdx.x;
    int lane = threadIdx.x & 31;
    int valid = (i < N_NODES);
    int d = valid ? g_deg[i] : 0;
    int inc = d;
#pragma unroll
    for (int o = 1; o < 32; o <<= 1) {
        int n = __shfl_up_sync(0xffffffffu, inc, o);
        if (lane >= o) inc += n;
    }
    int wsum = __shfl_sync(0xffffffffu, inc, 31);
    int base = 0;
    if (lane == 31) base = atomicAdd(&g_total, wsum);
    base = __shfl_sync(0xffffffffu, base, 31);
    if (valid) {
        int b = base + inc - d;
        g_off[i] = b;
        g_cursor[i] = b;
    }
}

__global__ void fill_kernel(const void* __restrict__ ei) {
    const int is64 = g_is64;
    const long long* e64 = (const long long*)ei;
    const int* e32 = (const int*)ei;
    size_t i = (size_t)blockIdx.x * blockDim.x + threadIdx.x;
    const size_t stride = (size_t)gridDim.x * blockDim.x;
    for (size_t e = i; e < (size_t)N_EDGES; e += stride) {
        int src, dst;
        if (is64) { src = (int)e64[e]; dst = (int)e64[N_EDGES + e]; }
        else      { src = e32[e];      dst = e32[N_EDGES + e]; }
        int pos = atomicAdd(&g_cursor[dst], 1);
        g_csr[pos] = src;
    }
}

// ---------------------------------------------------------------------------
// Gather: one warp per node; writes z directly as bf16 hi/lo split images.
//   z[node] = (1+eps[l]) * h[node] + sum_{s in N(node)} h[s] -> g_zh/g_zl
// ---------------------------------------------------------------------------
__global__ __launch_bounds__(256) void gather_kernel(
    const float* __restrict__ x, int use_gh,
    const float* __restrict__ eps, int l) {
    const float* h = use_gh ? g_h : x;
    const int node = (int)(((size_t)blockIdx.x * blockDim.x + threadIdx.x) >> 5);
    const int lane = threadIdx.x & 31;
    if (node >= N_NODES) return;
    const int s0 = g_off[node];
    const int s1 = s0 + g_deg[node];
    const float4* h4 = (const float4*)h;

    float4 a0 = make_float4(0.f, 0.f, 0.f, 0.f);
    float4 a1 = make_float4(0.f, 0.f, 0.f, 0.f);
    float4 a2 = make_float4(0.f, 0.f, 0.f, 0.f);
    float4 a3 = make_float4(0.f, 0.f, 0.f, 0.f);
    int i = s0;
    for (; i + 3 < s1; i += 4) {
        int sa = __ldg(&g_csr[i]);
        int sb = __ldg(&g_csr[i + 1]);
        int sc = __ldg(&g_csr[i + 2]);
        int sd = __ldg(&g_csr[i + 3]);
        float4 va = __ldg(&h4[(size_t)sa * 32 + lane]);
        float4 vb = __ldg(&h4[(size_t)sb * 32 + lane]);
        float4 vc = __ldg(&h4[(size_t)sc * 32 + lane]);
        float4 vd = __ldg(&h4[(size_t)sd * 32 + lane]);
        a0.x += va.x; a0.y += va.y; a0.z += va.z; a0.w += va.w;
        a1.x += vb.x; a1.y += vb.y; a1.z += vb.z; a1.w += vb.w;
        a2.x += vc.x; a2.y += vc.y; a2.z += vc.z; a2.w += vc.w;
        a3.x += vd.x; a3.y += vd.y; a3.z += vd.z; a3.w += vd.w;
    }
    for (; i < s1; i++) {
        int sa = __ldg(&g_csr[i]);
        float4 va = __ldg(&h4[(size_t)sa * 32 + lane]);
        a0.x += va.x; a0.y += va.y; a0.z += va.z; a0.w += va.w;
    }
    a0.x += a1.x + a2.x + a3.x;
    a0.y += a1.y + a2.y + a3.y;
    a0.z += a1.z + a2.z + a3.z;
    a0.w += a1.w + a2.w + a3.w;

    const float sc_ = 1.0f + eps[l];
    float4 hv = h4[(size_t)node * 32 + lane];
    a0.x = fmaf(sc_, hv.x, a0.x);
    a0.y = fmaf(sc_, hv.y, a0.y);
    a0.z = fmaf(sc_, hv.z, a0.z);
    a0.w = fmaf(sc_, hv.w, a0.w);

    uint32_t h0, l0, h1, l1;
    bf16_split2(a0.x, a0.y, h0, l0);
    bf16_split2(a0.z, a0.w, h1, l1);
    *(uint2*)(g_zh + (size_t)node * 256 + lane * 8) = make_uint2(h0, h1);
    *(uint2*)(g_zl + (size_t)node * 256 + lane * 8) = make_uint2(l0, l1);
}

// ---------------------------------------------------------------------------
// bf16-split HMMA MLP: 176 rows/CTA, 6 warps; z + W arrive pre-converted via
// linear cp.async (zero prologue ALU). No mid-stage CTA barriers.
// ---------------------------------------------------------------------------
#define MROWS 176
#define MTHREADS 192
#define OFF_ZH 0
#define OFF_ZL 47872
#define OFF_W  95744                 // WH1,WL1,WH2,WL2 (4 x 32768)
#define OFF_BA 226816
#define OFF_BB 227328
#define MLP_SMEM 227840

__global__ __launch_bounds__(MTHREADS) void mlp_mma_kernel(
    int l, const float* __restrict__ ba, const float* __restrict__ bb) {
    extern __shared__ char smem[];
    float* s_ba = (float*)(smem + OFF_BA);
    float* s_bb = (float*)(smem + OFF_BB);

    const int tid = threadIdx.x;
    const int warp = tid >> 5;
    const int lane = tid & 31;
    const int row0 = blockIdx.x * MROWS;
    const uint32_t sbase = smem_u32(smem);

    // P0: linear cp.async of W tiles (128KB) + z hi/lo tiles (89.6KB); biases
    const char* wsrc = g_wt + (size_t)l * 131072;
    for (int i = tid; i < 8192; i += MTHREADS)
        cp_async16(sbase + OFF_W + i * 16, wsrc + i * 16);
    for (int i = tid; i < MROWS * 16; i += MTHREADS) {   // 2816
        int r = i >> 4, c = i & 15;
        size_t goff = (size_t)(row0 + r) * 256 + c * 16;
        cp_async16(sbase + OFF_ZH + r * 272 + c * 16, g_zh + goff);
        cp_async16(sbase + OFF_ZL + r * 272 + c * 16, g_zl + goff);
    }
    CP_COMMIT();
    if (tid < 128) { s_ba[tid] = __ldg(&ba[tid]); s_bb[tid] = __ldg(&bb[tid]); }
    CP_WAIT0();
    __syncthreads();

    // P1: GEMM stages, warp-independent
    const int m0 = warp * 32;                       // warp5 -> 160
    const bool two = (warp < 5);
    const int a_m0 = m0 + (lane & 15);
    const uint32_t a_koff = (uint32_t)((lane >> 4) * 16);
    const int b_n = (lane & 7) + ((lane >> 4) << 3);
    const int b_kc = (lane >> 3) & 1;

    float acc0[16][4], acc1[16][4];
    uint32_t ah0[4], al0[4], ah1[4], al1[4], bh[4], bl[4];

#pragma unroll
    for (int stage = 0; stage < 2; stage++) {
        const uint32_t WH = sbase + OFF_W + (uint32_t)stage * 65536;
        const uint32_t WL = WH + 32768;
#pragma unroll
        for (int t = 0; t < 16; t++)
#pragma unroll
            for (int j = 0; j < 4; j++) { acc0[t][j] = 0.f; acc1[t][j] = 0.f; }

#pragma unroll
        for (int ks = 0; ks < 8; ks++) {
            uint32_t aaddr = sbase + OFF_ZH + a_m0 * 272 + ks * 32 + a_koff;
            LDMX4(ah0[0], ah0[1], ah0[2], ah0[3], aaddr);
            LDMX4(al0[0], al0[1], al0[2], al0[3], aaddr + 47872);
            if (two) {
                uint32_t aaddr1 = aaddr + 16 * 272;
                LDMX4(ah1[0], ah1[1], ah1[2], ah1[3], aaddr1);
                LDMX4(al1[0], al1[1], al1[2], al1[3], aaddr1 + 47872);
            }
#pragma unroll
            for (int np = 0; np < 8; np++) {
                uint32_t boff = wswz(np * 16 + b_n, ks * 16 + b_kc * 8);
                LDMX4(bh[0], bh[1], bh[2], bh[3], WH + boff);
                LDMX4(bl[0], bl[1], bl[2], bl[3], WL + boff);
                MMA16816(acc0[2 * np], ah0, bh[0], bh[1]);
                if (two) MMA16816(acc1[2 * np], ah1, bh[0], bh[1]);
                MMA16816(acc0[2 * np], al0, bh[0], bh[1]);
                if (two) MMA16816(acc1[2 * np], al1, bh[0], bh[1]);
                MMA16816(acc0[2 * np], ah0, bl[0], bl[1]);
                if (two) MMA16816(acc1[2 * np], ah1, bl[0], bl[1]);
                MMA16816(acc0[2 * np + 1], ah0, bh[2], bh[3]);
                if (two) MMA16816(acc1[2 * np + 1], ah1, bh[2], bh[3]);
                MMA16816(acc0[2 * np + 1], al0, bh[2], bh[3]);
                if (two) MMA16816(acc1[2 * np + 1], al1, bh[2], bh[3]);
                MMA16816(acc0[2 * np + 1], ah0, bl[2], bl[3]);
                if (two) MMA16816(acc1[2 * np + 1], ah1, bl[2], bl[3]);
            }
        }

        const int m_r = m0 + (lane >> 2);
        if (stage == 0) {
            // t = relu(acc + ba) -> re-split into ZH/ZL (own rows only)
#pragma unroll
            for (int nt = 0; nt < 16; nt++) {
                int col = nt * 8 + 2 * (lane & 3);
                float b0 = s_ba[col], b1 = s_ba[col + 1];
                uint32_t hi, lo;
                bf16_split2(fmaxf(acc0[nt][0] + b0, 0.f),
                            fmaxf(acc0[nt][1] + b1, 0.f), hi, lo);
                *(uint32_t*)(smem + OFF_ZH + m_r * 272 + col * 2) = hi;
                *(uint32_t*)(smem + OFF_ZL + m_r * 272 + col * 2) = lo;
                bf16_split2(fmaxf(acc0[nt][2] + b0, 0.f),
                            fmaxf(acc0[nt][3] + b1, 0.f), hi, lo);
                *(uint32_t*)(smem + OFF_ZH + (m_r + 8) * 272 + col * 2) = hi;
                *(uint32_t*)(smem + OFF_ZL + (m_r + 8) * 272 + col * 2) = lo;
                if (two) {
                    bf16_split2(fmaxf(acc1[nt][0] + b0, 0.f),
                                fmaxf(acc1[nt][1] + b1, 0.f), hi, lo);
                    *(uint32_t*)(smem + OFF_ZH + (m_r + 16) * 272 + col * 2) = hi;
                    *(uint32_t*)(smem + OFF_ZL + (m_r + 16) * 272 + col * 2) = lo;
                    bf16_split2(fmaxf(acc1[nt][2] + b0, 0.f),
                                fmaxf(acc1[nt][3] + b1, 0.f), hi, lo);
                    *(uint32_t*)(smem + OFF_ZH + (m_r + 24) * 272 + col * 2) = hi;
                    *(uint32_t*)(smem + OFF_ZL + (m_r + 24) * 272 + col * 2) = lo;
                }
            }
            __syncwarp();
        } else {
            // h_out = relu(acc + bb) -> g_h
            int n0 = row0 + m_r;
#pragma unroll
            for (int nt = 0; nt < 16; nt++) {
                int col = nt * 8 + 2 * (lane & 3);
                float b0 = s_bb[col], b1 = s_bb[col + 1];
                if (n0 < N_NODES) {
                    float2 o;
                    o.x = fmaxf(acc0[nt][0] + b0, 0.f);
                    o.y = fmaxf(acc0[nt][1] + b1, 0.f);
                    *(float2*)(g_h + (size_t)n0 * 128 + col) = o;
                }
                if (n0 + 8 < N_NODES) {
                    float2 o;
                    o.x = fmaxf(acc0[nt][2] + b0, 0.f);
                    o.y = fmaxf(acc0[nt][3] + b1, 0.f);
                    *(float2*)(g_h + (size_t)(n0 + 8) * 128 + col) = o;
                }
                if (two) {
                    if (n0 + 16 < N_NODES) {
                        float2 o;
                        o.x = fmaxf(acc1[nt][0] + b0, 0.f);
                        o.y = fmaxf(acc1[nt][1] + b1, 0.f);
                        *(float2*)(g_h + (size_t)(n0 + 16) * 128 + col) = o;
                    }
                    if (n0 + 24 < N_NODES) {
                        float2 o;
                        o.x = fmaxf(acc1[nt][2] + b0, 0.f);
                        o.y = fmaxf(acc1[nt][3] + b1, 0.f);
                        *(float2*)(g_h + (size_t)(n0 + 24) * 128 + col) = o;
                    }
                }
            }
        }
    }
}

// ---------------------------------------------------------------------------
// Head: out = relu(h @ W1 + b1) @ W2 + b2    (128 -> 64 -> 2), f32x2 stage 1
// ---------------------------------------------------------------------------
#define HPAD 132
#define HEAD_SMEM (size_t)((64 * HPAD + 128 * 64 + 64 * 68) * sizeof(float))

__global__ __launch_bounds__(256) void head_kernel(
    const float* __restrict__ W1, const float* __restrict__ b1,
    const float* __restrict__ W2, const float* __restrict__ b2,
    float* __restrict__ out) {
    extern __shared__ float sm[];
    float* hs = sm;               // 64 x 132
    float* w1 = sm + 64 * HPAD;   // 128 x 64
    float* hid = w1 + 128 * 64;   // 64 x 68

    const int tid = threadIdx.x;
    const int tx = tid & 15, ty = tid >> 4;
    const int row0 = blockIdx.x * 64;

    const float4* h4 = (const float4*)g_h;
    for (int i = tid; i < 64 * 32; i += 256) {
        int r = i >> 5, c = i & 31;
        int gr = row0 + r;
        float4 v = make_float4(0.f, 0.f, 0.f, 0.f);
        if (gr < N_NODES) v = h4[(size_t)gr * 32 + c];
        *(float4*)&hs[r * HPAD + c * 4] = v;
    }
    const float4* w14 = (const float4*)W1;
    for (int i = tid; i < 128 * 16; i += 256)
        *(float4*)&w1[(i >> 4) * 64 + (i & 15) * 4] = w14[i];
    __syncthreads();

    unsigned long long acc[4][2];
#pragma unroll
    for (int i = 0; i < 4; i++) { acc[i][0] = 0ull; acc[i][1] = 0ull; }

#pragma unroll 2
    for (int k4 = 0; k4 < 32; k4++) {
        float4 a4[4];
#pragma unroll
        for (int i = 0; i < 4; i++)
            a4[i] = *(const float4*)&hs[(ty * 4 + i) * HPAD + k4 * 4];
#pragma unroll
        for (int kk = 0; kk < 4; kk++) {
            float4 bA = *(const float4*)&w1[(k4 * 4 + kk) * 64 + tx * 4];
            unsigned long long b0, b1;
            PACK2(b0, bA.x, bA.y); PACK2(b1, bA.z, bA.w);
#pragma unroll
            for (int i = 0; i < 4; i++) {
                float a = (kk == 0) ? a4[i].x : (kk == 1) ? a4[i].y
                        : (kk == 2) ? a4[i].z : a4[i].w;
                unsigned long long a2; PACK2(a2, a, a);
                FMA2(acc[i][0], a2, b0); FMA2(acc[i][1], a2, b1);
            }
        }
    }
    float bi[4];
    *(float4*)&bi[0] = *(const float4*)&b1[tx * 4];
#pragma unroll
    for (int i = 0; i < 4; i++) {
        float t[4];
        UNPACK2(t[0], t[1], acc[i][0]);
        UNPACK2(t[2], t[3], acc[i][1]);
#pragma unroll
        for (int j = 0; j < 4; j++) t[j] = fmaxf(t[j] + bi[j], 0.f);
        *(float4*)&hid[(ty * 4 + i) * 68 + tx * 4] = *(float4*)&t[0];
    }
    __syncthreads();

    if (tid < 128) {
        int r = tid >> 1, c = tid & 1;
        int gr = row0 + r;
        if (gr < N_NODES) {
            float s = __ldg(&b2[c]);
#pragma unroll 8
            for (int k = 0; k < 64; k++)
                s = fmaf(hid[r * 68 + k], __ldg(&W2[k * 2 + c]), s);
            out[(size_t)gr * 2 + c] = s;
        }
    }
}

// ---------------------------------------------------------------------------
extern "C" void kernel_launch(void* const* d_in, const int* in_sizes, int n_in,
                              void* d_out, int out_size) {
    const float* x   = (const float*)d_in[0];
    const void*  ei  = d_in[1];
    const float* eps = (const float*)d_in[2];
    const float* Wa  = (const float*)d_in[3];
    const float* ba  = (const float*)d_in[4];
    const float* Wb  = (const float*)d_in[5];
    const float* bb  = (const float*)d_in[6];
    const float* W1  = (const float*)d_in[7];
    const float* b1  = (const float*)d_in[8];
    const float* W2  = (const float*)d_in[9];
    const float* b2  = (const float*)d_in[10];
    float* out = (float*)d_out;

    cudaFuncSetAttribute(mlp_mma_kernel, cudaFuncAttributeMaxDynamicSharedMemorySize,
                         MLP_SMEM);
    cudaFuncSetAttribute(head_kernel, cudaFuncAttributeMaxDynamicSharedMemorySize,
                         (int)HEAD_SMEM);

    // One-shot weight pre-swizzle + per-launch CSR build
    wconv_kernel<<<192, 256>>>(Wa, Wb);
    zero_deg_kernel<<<(N_NODES + 255) / 256, 256>>>((const long long*)ei);
    hist_kernel<<<1024, 256>>>(ei);
    alloc_kernel<<<(N_NODES + 255) / 256, 256>>>();
    fill_kernel<<<1024, 256>>>(ei);

    const int gather_blocks = (N_NODES * 32 + 255) / 256;   // warp per node
    const int mlp_blocks = (N_NODES + MROWS - 1) / MROWS;   // 285 -> 2 waves
    const int head_blocks = (N_NODES + 63) / 64;            // 782

    for (int l = 0; l < 3; l++) {
        gather_kernel<<<gather_blocks, 256>>>(x, l > 0 ? 1 : 0, eps, l);
        mlp_mma_kernel<<<mlp_blocks, MTHREADS, MLP_SMEM>>>(
            l, ba + (size_t)l * HID, bb + (size_t)l * HID);
    }
    head_kernel<<<head_blocks, 256, HEAD_SMEM>>>(W1, b1, W2, b2, out);
}

// round 11
// speedup vs baseline: 2.2396x; 1.0538x over previous
#include <cuda_runtime.h>
#include <cuda_bf16.h>
#include <cstdint>

#define N_NODES 50000
#define N_EDGES 800000
#define HID 128
#define ZROWS 50176   // padded rows for safe cp.async tails (zero-init .bss)

// Persistent scratch (allocation-free rule: __device__ globals)
__device__ float g_h[(size_t)N_NODES * HID];
__device__ char  g_zh[(size_t)ZROWS * 256];   // z hi, bf16 [node][128]
__device__ char  g_zl[(size_t)ZROWS * 256];   // z lo
__device__ int   g_deg[N_NODES];
__device__ int   g_off[N_NODES];
__device__ int   g_cursor[N_NODES];
__device__ int   g_csr[N_EDGES];
__device__ int   g_total;
__device__ int   g_is64;
// pre-swizzled bf16 tiles: [l][WaH,WaL,WbH,WbL] + W1H,W1L (16KB each)
__device__ char  g_wt[3 * 131072 + 32768];

__device__ __forceinline__ void cp_async16(uint32_t saddr, const void* gptr) {
    asm volatile("cp.async.cg.shared.global [%0], [%1], 16;" ::"r"(saddr), "l"(gptr));
}
#define CP_COMMIT() asm volatile("cp.async.commit_group;")
#define CP_WAIT0()  asm volatile("cp.async.wait_group 0;")

__device__ __forceinline__ uint32_t smem_u32(const void* p) {
    return (uint32_t)__cvta_generic_to_shared(p);
}

#define LDMX4(r0, r1, r2, r3, a) \
    asm volatile("ldmatrix.sync.aligned.m8n8.x4.shared.b16 {%0,%1,%2,%3}, [%4];" \
                 : "=r"(r0), "=r"(r1), "=r"(r2), "=r"(r3) : "r"(a))

#define MMA16816(c, a, b0, b1) \
    asm volatile("mma.sync.aligned.m16n8k16.row.col.f32.bf16.bf16.f32 " \
                 "{%0,%1,%2,%3}, {%4,%5,%6,%7}, {%8,%9}, {%0,%1,%2,%3};" \
                 : "+f"((c)[0]), "+f"((c)[1]), "+f"((c)[2]), "+f"((c)[3]) \
                 : "r"((a)[0]), "r"((a)[1]), "r"((a)[2]), "r"((a)[3]), \
                   "r"(b0), "r"(b1))

// bf16 hi/lo split of two floats, packed bf16x2
__device__ __forceinline__ void bf16_split2(float x0, float x1,
                                            uint32_t& hi, uint32_t& lo) {
    __nv_bfloat16 h0 = __float2bfloat16(x0);
    __nv_bfloat16 h1 = __float2bfloat16(x1);
    __nv_bfloat16 l0 = __float2bfloat16(x0 - __bfloat162float(h0));
    __nv_bfloat16 l1 = __float2bfloat16(x1 - __bfloat162float(h1));
    __nv_bfloat162 hp = __halves2bfloat162(h0, h1);
    __nv_bfloat162 lp = __halves2bfloat162(l0, l1);
    hi = *(uint32_t*)&hp;
    lo = *(uint32_t*)&lp;
}

// W^T[n][k] swizzled byte offset (k even; 4B/16B chunk aligned)
__device__ __forceinline__ uint32_t wswz(int n, int k) {
    uint32_t chunk = ((uint32_t)(k >> 3)) ^ (uint32_t)(n & 7);
    return (uint32_t)n * 256 + chunk * 16 + (uint32_t)(k & 7) * 2;
}

// ---------------------------------------------------------------------------
// One-shot weight conversion: fp32 W[k][n] -> pre-swizzled bf16 hi/lo tiles.
// idx < 49152: layer Wa/Wb.  idx >= 49152: head W1 (128x64).
// ---------------------------------------------------------------------------
__global__ void wconv_kernel(const float* __restrict__ Wa,
                             const float* __restrict__ Wb,
                             const float* __restrict__ W1) {
    int idx = blockIdx.x * blockDim.x + threadIdx.x;   // 53248 total
    if (idx < 49152) {
        int l = idx / 16384;
        int rem = idx - l * 16384;
        int m = rem >> 13;            // 0 = Wa, 1 = Wb
        int pos = rem & 8191;
        int n = pos >> 6;
        int k = (pos & 63) * 2;
        const float* src = (m == 0 ? Wa : Wb) + (size_t)l * 16384;
        uint32_t hi, lo;
        bf16_split2(__ldg(&src[k * 128 + n]), __ldg(&src[(k + 1) * 128 + n]), hi, lo);
        uint32_t b = wswz(n, k);
        char* base = g_wt + ((size_t)l * 4 + m * 2) * 32768;
        *(uint32_t*)(base + b) = hi;
        *(uint32_t*)(base + 32768 + b) = lo;
    } else {
        int pos = idx - 49152;        // 0..4095
        int n = pos >> 6;             // 0..63
        int k = (pos & 63) * 2;
        uint32_t hi, lo;
        bf16_split2(__ldg(&W1[k * 64 + n]), __ldg(&W1[(k + 1) * 64 + n]), hi, lo);
        uint32_t b = wswz(n, k);
        char* base = g_wt + 393216;
        *(uint32_t*)(base + b) = hi;
        *(uint32_t*)(base + 16384 + b) = lo;
    }
}

// ---------------------------------------------------------------------------
// CSR build
// ---------------------------------------------------------------------------
__global__ void zero_deg_kernel(const long long* __restrict__ ei) {
    int i = blockIdx.x * blockDim.x + threadIdx.x;
    if (i < N_NODES) g_deg[i] = 0;
    if (i == 0) {
        g_total = 0;
        int ok = 1;
        for (int k = 0; k < 64; k++) {
            long long v = ei[k];
            if (v < 0 || v >= N_NODES) { ok = 0; break; }
        }
        g_is64 = ok;
    }
}

__global__ void hist_kernel(const void* __restrict__ ei) {
    const int is64 = g_is64;
    const long long* e64 = (const long long*)ei;
    const int* e32 = (const int*)ei;
    size_t i = (size_t)blockIdx.x * blockDim.x + threadIdx.x;
    const size_t stride = (size_t)gridDim.x * blockDim.x;
    for (size_t e = i; e < (size_t)N_EDGES; e += stride) {
        int dst = is64 ? (int)e64[N_EDGES + e] : e32[N_EDGES + e];
        atomicAdd(&g_deg[dst], 1);
    }
}

__global__ void alloc_kernel() {
    int i = blockIdx.x * blockDim.x + threadIdx.x;
    int lane = threadIdx.x & 31;
    int valid = (i < N_NODES);
    int d = valid ? g_deg[i] : 0;
    int inc = d;
#pragma unroll
    for (int o = 1; o < 32; o <<= 1) {
        int n = __shfl_up_sync(0xffffffffu, inc, o);
        if (lane >= o) inc += n;
    }
    int wsum = __shfl_sync(0xffffffffu, inc, 31);
    int base = 0;
    if (lane == 31) base = atomicAdd(&g_total, wsum);
    base = __shfl_sync(0xffffffffu, base, 31);
    if (valid) {
        int b = base + inc - d;
        g_off[i] = b;
        g_cursor[i] = b;
    }
}

__global__ void fill_kernel(const void* __restrict__ ei) {
    const int is64 = g_is64;
    const long long* e64 = (const long long*)ei;
    const int* e32 = (const int*)ei;
    size_t i = (size_t)blockIdx.x * blockDim.x + threadIdx.x;
    const size_t stride = (size_t)gridDim.x * blockDim.x;
    for (size_t e = i; e < (size_t)N_EDGES; e += stride) {
        int src, dst;
        if (is64) { src = (int)e64[e]; dst = (int)e64[N_EDGES + e]; }
        else      { src = e32[e];      dst = e32[N_EDGES + e]; }
        int pos = atomicAdd(&g_cursor[dst], 1);
        g_csr[pos] = src;
    }
}

// ---------------------------------------------------------------------------
// Gather: one warp per node; writes z directly as bf16 hi/lo split images.
// ---------------------------------------------------------------------------
__global__ __launch_bounds__(256) void gather_kernel(
    const float* __restrict__ x, int use_gh,
    const float* __restrict__ eps, int l) {
    const float* h = use_gh ? g_h : x;
    const int node = (int)(((size_t)blockIdx.x * blockDim.x + threadIdx.x) >> 5);
    const int lane = threadIdx.x & 31;
    if (node >= N_NODES) return;
    const int s0 = g_off[node];
    const int s1 = s0 + g_deg[node];
    const float4* h4 = (const float4*)h;

    float4 a0 = make_float4(0.f, 0.f, 0.f, 0.f);
    float4 a1 = make_float4(0.f, 0.f, 0.f, 0.f);
    float4 a2 = make_float4(0.f, 0.f, 0.f, 0.f);
    float4 a3 = make_float4(0.f, 0.f, 0.f, 0.f);
    int i = s0;
    for (; i + 3 < s1; i += 4) {
        int sa = __ldg(&g_csr[i]);
        int sb = __ldg(&g_csr[i + 1]);
        int sc = __ldg(&g_csr[i + 2]);
        int sd = __ldg(&g_csr[i + 3]);
        float4 va = __ldg(&h4[(size_t)sa * 32 + lane]);
        float4 vb = __ldg(&h4[(size_t)sb * 32 + lane]);
        float4 vc = __ldg(&h4[(size_t)sc * 32 + lane]);
        float4 vd = __ldg(&h4[(size_t)sd * 32 + lane]);
        a0.x += va.x; a0.y += va.y; a0.z += va.z; a0.w += va.w;
        a1.x += vb.x; a1.y += vb.y; a1.z += vb.z; a1.w += vb.w;
        a2.x += vc.x; a2.y += vc.y; a2.z += vc.z; a2.w += vc.w;
        a3.x += vd.x; a3.y += vd.y; a3.z += vd.z; a3.w += vd.w;
    }
    for (; i < s1; i++) {
        int sa = __ldg(&g_csr[i]);
        float4 va = __ldg(&h4[(size_t)sa * 32 + lane]);
        a0.x += va.x; a0.y += va.y; a0.z += va.z; a0.w += va.w;
    }
    a0.x += a1.x + a2.x + a3.x;
    a0.y += a1.y + a2.y + a3.y;
    a0.z += a1.z + a2.z + a3.z;
    a0.w += a1.w + a2.w + a3.w;

    const float sc_ = 1.0f + eps[l];
    float4 hv = h4[(size_t)node * 32 + lane];
    a0.x = fmaf(sc_, hv.x, a0.x);
    a0.y = fmaf(sc_, hv.y, a0.y);
    a0.z = fmaf(sc_, hv.z, a0.z);
    a0.w = fmaf(sc_, hv.w, a0.w);

    uint32_t h0, l0, h1, l1;
    bf16_split2(a0.x, a0.y, h0, l0);
    bf16_split2(a0.z, a0.w, h1, l1);
    *(uint2*)(g_zh + (size_t)node * 256 + lane * 8) = make_uint2(h0, h1);
    *(uint2*)(g_zl + (size_t)node * 256 + lane * 8) = make_uint2(l0, l1);
}

// ---------------------------------------------------------------------------
// bf16-split HMMA MLP: 176 rows/CTA, 6 warps. Last layer fuses the head:
// stage-3 MMA vs W1 (N=64) + quad-shfl W2 reduction -> out. No head kernel.
// ---------------------------------------------------------------------------
#define MROWS 176
#define MTHREADS 192
#define OFF_ZH 0
#define OFF_ZL 47872
#define OFF_W  95744                 // WH1,WL1,WH2,WL2 (4 x 32768)
#define OFF_BA 226816
#define OFF_BB 227328
#define OFF_B1 227840                // head b1 (64 f32)
#define OFF_W2 228096                // head W2 (64x2 f32)
#define MLP_SMEM 228608

template<int NP>
__device__ __forceinline__ void gemm_stage(
    const uint32_t sbase, const uint32_t WH, const uint32_t WL,
    int a_m0, uint32_t a_koff, int b_n, int b_kc, bool two,
    float acc0[][4], float acc1[][4]) {
    uint32_t ah0[4], al0[4], ah1[4], al1[4], bh[4], bl[4];
#pragma unroll
    for (int t = 0; t < 2 * NP; t++)
#pragma unroll
        for (int j = 0; j < 4; j++) { acc0[t][j] = 0.f; acc1[t][j] = 0.f; }
#pragma unroll
    for (int ks = 0; ks < 8; ks++) {
        uint32_t aaddr = sbase + OFF_ZH + a_m0 * 272 + ks * 32 + a_koff;
        LDMX4(ah0[0], ah0[1], ah0[2], ah0[3], aaddr);
        LDMX4(al0[0], al0[1], al0[2], al0[3], aaddr + (OFF_ZL - OFF_ZH));
        if (two) {
            uint32_t aaddr1 = aaddr + 16 * 272;
            LDMX4(ah1[0], ah1[1], ah1[2], ah1[3], aaddr1);
            LDMX4(al1[0], al1[1], al1[2], al1[3], aaddr1 + (OFF_ZL - OFF_ZH));
        }
#pragma unroll
        for (int np = 0; np < NP; np++) {
            uint32_t boff = wswz(np * 16 + b_n, ks * 16 + b_kc * 8);
            LDMX4(bh[0], bh[1], bh[2], bh[3], WH + boff);
            LDMX4(bl[0], bl[1], bl[2], bl[3], WL + boff);
            MMA16816(acc0[2 * np], ah0, bh[0], bh[1]);
            if (two) MMA16816(acc1[2 * np], ah1, bh[0], bh[1]);
            MMA16816(acc0[2 * np], al0, bh[0], bh[1]);
            if (two) MMA16816(acc1[2 * np], al1, bh[0], bh[1]);
            MMA16816(acc0[2 * np], ah0, bl[0], bl[1]);
            if (two) MMA16816(acc1[2 * np], ah1, bl[0], bl[1]);
            MMA16816(acc0[2 * np + 1], ah0, bh[2], bh[3]);
            if (two) MMA16816(acc1[2 * np + 1], ah1, bh[2], bh[3]);
            MMA16816(acc0[2 * np + 1], al0, bh[2], bh[3]);
            if (two) MMA16816(acc1[2 * np + 1], al1, bh[2], bh[3]);
            MMA16816(acc0[2 * np + 1], ah0, bl[2], bl[3]);
            if (two) MMA16816(acc1[2 * np + 1], ah1, bl[2], bl[3]);
        }
    }
}

__global__ __launch_bounds__(MTHREADS) void mlp_mma_kernel(
    int l, int last,
    const float* __restrict__ ba, const float* __restrict__ bb,
    const float* __restrict__ b1, const float* __restrict__ W2,
    const float* __restrict__ b2, float* __restrict__ out) {
    extern __shared__ char smem[];
    float* s_ba = (float*)(smem + OFF_BA);
    float* s_bb = (float*)(smem + OFF_BB);
    float* s_b1 = (float*)(smem + OFF_B1);
    float* s_w2 = (float*)(smem + OFF_W2);

    const int tid = threadIdx.x;
    const int warp = tid >> 5;
    const int lane = tid & 31;
    const int row0 = blockIdx.x * MROWS;
    const uint32_t sbase = smem_u32(smem);

    // P0: linear cp.async of W tiles (128KB) + z hi/lo tiles (89.6KB); biases
    const char* wsrc = g_wt + (size_t)l * 131072;
    for (int i = tid; i < 8192; i += MTHREADS)
        cp_async16(sbase + OFF_W + i * 16, wsrc + i * 16);
    for (int i = tid; i < MROWS * 16; i += MTHREADS) {   // 2816
        int r = i >> 4, c = i & 15;
        size_t goff = (size_t)(row0 + r) * 256 + c * 16;
        cp_async16(sbase + OFF_ZH + r * 272 + c * 16, g_zh + goff);
        cp_async16(sbase + OFF_ZL + r * 272 + c * 16, g_zl + goff);
    }
    CP_COMMIT();
    if (tid < 128) { s_ba[tid] = __ldg(&ba[tid]); s_bb[tid] = __ldg(&bb[tid]); }
    float b2_0 = 0.f, b2_1 = 0.f;
    if (last) {
        if (tid < 64) s_b1[tid] = __ldg(&b1[tid]);
        if (tid < 128) s_w2[tid] = __ldg(&W2[tid]);
        b2_0 = __ldg(&b2[0]); b2_1 = __ldg(&b2[1]);
    }
    CP_WAIT0();
    __syncthreads();

    const int m0 = warp * 32;                       // warp5 -> 160
    const bool two = (warp < 5);
    const int a_m0 = m0 + (lane & 15);
    const uint32_t a_koff = (uint32_t)((lane >> 4) * 16);
    const int b_n = (lane & 7) + ((lane >> 4) << 3);
    const int b_kc = (lane >> 3) & 1;
    const int m_r = m0 + (lane >> 2);

    float acc0[16][4], acc1[16][4];

    // ---- Stage 1: z @ Wa
    gemm_stage<8>(sbase, sbase + OFF_W, sbase + OFF_W + 32768,
                  a_m0, a_koff, b_n, b_kc, two, acc0, acc1);
    // t = relu(acc + ba) -> re-split into ZH/ZL (own rows only)
#pragma unroll
    for (int nt = 0; nt < 16; nt++) {
        int col = nt * 8 + 2 * (lane & 3);
        float b0 = s_ba[col], b1v = s_ba[col + 1];
        uint32_t hi, lo;
        bf16_split2(fmaxf(acc0[nt][0] + b0, 0.f),
                    fmaxf(acc0[nt][1] + b1v, 0.f), hi, lo);
        *(uint32_t*)(smem + OFF_ZH + m_r * 272 + col * 2) = hi;
        *(uint32_t*)(smem + OFF_ZL + m_r * 272 + col * 2) = lo;
        bf16_split2(fmaxf(acc0[nt][2] + b0, 0.f),
                    fmaxf(acc0[nt][3] + b1v, 0.f), hi, lo);
        *(uint32_t*)(smem + OFF_ZH + (m_r + 8) * 272 + col * 2) = hi;
        *(uint32_t*)(smem + OFF_ZL + (m_r + 8) * 272 + col * 2) = lo;
        if (two) {
            bf16_split2(fmaxf(acc1[nt][0] + b0, 0.f),
                        fmaxf(acc1[nt][1] + b1v, 0.f), hi, lo);
            *(uint32_t*)(smem + OFF_ZH + (m_r + 16) * 272 + col * 2) = hi;
            *(uint32_t*)(smem + OFF_ZL + (m_r + 16) * 272 + col * 2) = lo;
            bf16_split2(fmaxf(acc1[nt][2] + b0, 0.f),
                        fmaxf(acc1[nt][3] + b1v, 0.f), hi, lo);
            *(uint32_t*)(smem + OFF_ZH + (m_r + 24) * 272 + col * 2) = hi;
            *(uint32_t*)(smem + OFF_ZL + (m_r + 24) * 272 + col * 2) = lo;
        }
    }
    __syncwarp();

    // Last layer: WH1/WL1 region is dead after stage 1 -> prefetch W1 tiles
    // under stage-2 compute (uniform branch, CTA-wide barrier).
    if (last) {
        __syncthreads();
        const char* w1src = g_wt + 393216;
        for (int i = tid; i < 2048; i += MTHREADS)
            cp_async16(sbase + OFF_W + i * 16, w1src + i * 16);
        CP_COMMIT();
    }

    // ---- Stage 2: t @ Wb
    gemm_stage<8>(sbase, sbase + OFF_W + 65536, sbase + OFF_W + 98304,
                  a_m0, a_koff, b_n, b_kc, two, acc0, acc1);

    if (!last) {
        // h_out = relu(acc + bb) -> g_h
        int n0 = row0 + m_r;
#pragma unroll
        for (int nt = 0; nt < 16; nt++) {
            int col = nt * 8 + 2 * (lane & 3);
            float b0 = s_bb[col], b1v = s_bb[col + 1];
            if (n0 < N_NODES) {
                float2 o;
                o.x = fmaxf(acc0[nt][0] + b0, 0.f);
                o.y = fmaxf(acc0[nt][1] + b1v, 0.f);
                *(float2*)(g_h + (size_t)n0 * 128 + col) = o;
            }
            if (n0 + 8 < N_NODES) {
                float2 o;
                o.x = fmaxf(acc0[nt][2] + b0, 0.f);
                o.y = fmaxf(acc0[nt][3] + b1v, 0.f);
                *(float2*)(g_h + (size_t)(n0 + 8) * 128 + col) = o;
            }
            if (two) {
                if (n0 + 16 < N_NODES) {
                    float2 o;
                    o.x = fmaxf(acc1[nt][0] + b0, 0.f);
                    o.y = fmaxf(acc1[nt][1] + b1v, 0.f);
                    *(float2*)(g_h + (size_t)(n0 + 16) * 128 + col) = o;
                }
                if (n0 + 24 < N_NODES) {
                    float2 o;
                    o.x = fmaxf(acc1[nt][2] + b0, 0.f);
                    o.y = fmaxf(acc1[nt][3] + b1v, 0.f);
                    *(float2*)(g_h + (size_t)(n0 + 24) * 128 + col) = o;
                }
            }
        }
        return;
    }

    // ---- Last layer: h = relu(acc + bb) -> ZH/ZL (own rows), then head.
#pragma unroll
    for (int nt = 0; nt < 16; nt++) {
        int col = nt * 8 + 2 * (lane & 3);
        float b0 = s_bb[col], b1v = s_bb[col + 1];
        uint32_t hi, lo;
        bf16_split2(fmaxf(acc0[nt][0] + b0, 0.f),
                    fmaxf(acc0[nt][1] + b1v, 0.f), hi, lo);
        *(uint32_t*)(smem + OFF_ZH + m_r * 272 + col * 2) = hi;
        *(uint32_t*)(smem + OFF_ZL + m_r * 272 + col * 2) = lo;
        bf16_split2(fmaxf(acc0[nt][2] + b0, 0.f),
                    fmaxf(acc0[nt][3] + b1v, 0.f), hi, lo);
        *(uint32_t*)(smem + OFF_ZH + (m_r + 8) * 272 + col * 2) = hi;
        *(uint32_t*)(smem + OFF_ZL + (m_r + 8) * 272 + col * 2) = lo;
        if (two) {
            bf16_split2(fmaxf(acc1[nt][0] + b0, 0.f),
                        fmaxf(acc1[nt][1] + b1v, 0.f), hi, lo);
            *(uint32_t*)(smem + OFF_ZH + (m_r + 16) * 272 + col * 2) = hi;
            *(uint32_t*)(smem + OFF_ZL + (m_r + 16) * 272 + col * 2) = lo;
            bf16_split2(fmaxf(acc1[nt][2] + b0, 0.f),
                        fmaxf(acc1[nt][3] + b1v, 0.f), hi, lo);
            *(uint32_t*)(smem + OFF_ZH + (m_r + 24) * 272 + col * 2) = hi;
            *(uint32_t*)(smem + OFF_ZL + (m_r + 24) * 272 + col * 2) = lo;
        }
    }
    CP_WAIT0();
    __syncthreads();   // W1 tiles visible CTA-wide; own-row ZH writes ordered

    // ---- Stage 3: hid_pre = h @ W1 (N=64)
    gemm_stage<4>(sbase, sbase + OFF_W, sbase + OFF_W + 16384,
                  a_m0, a_koff, b_n, b_kc, two, acc0, acc1);

    // head epilogue: hid = relu(acc + b1); out = hid @ W2 + b2 (quad reduce)
    const int nrr = two ? 4 : 2;
    for (int rr = 0; rr < nrr; rr++) {
        float (*A)[4] = (rr < 2) ? acc0 : acc1;
        const int i0 = (rr & 1) ? 2 : 0;
        float p0 = 0.f, p1 = 0.f;
#pragma unroll
        for (int nt = 0; nt < 8; nt++) {
            int c = nt * 8 + 2 * (lane & 3);
            float v0 = fmaxf(A[nt][i0] + s_b1[c], 0.f);
            float v1 = fmaxf(A[nt][i0 + 1] + s_b1[c + 1], 0.f);
            p0 = fmaf(v0, s_w2[2 * c], fmaf(v1, s_w2[2 * c + 2], p0));
            p1 = fmaf(v0, s_w2[2 * c + 1], fmaf(v1, s_w2[2 * c + 3], p1));
        }
        p0 += __shfl_xor_sync(0xffffffffu, p0, 1);
        p0 += __shfl_xor_sync(0xffffffffu, p0, 2);
        p1 += __shfl_xor_sync(0xffffffffu, p1, 1);
        p1 += __shfl_xor_sync(0xffffffffu, p1, 2);
        int row = row0 + m_r + ((rr & 1) ? 8 : 0) + ((rr >= 2) ? 16 : 0);
        if ((lane & 3) == 0 && row < N_NODES) {
            float2 o;
            o.x = p0 + b2_0;
            o.y = p1 + b2_1;
            *(float2*)(out + (size_t)row * 2) = o;
        }
    }
}

// ---------------------------------------------------------------------------
extern "C" void kernel_launch(void* const* d_in, const int* in_sizes, int n_in,
                              void* d_out, int out_size) {
    const float* x   = (const float*)d_in[0];
    const void*  ei  = d_in[1];
    const float* eps = (const float*)d_in[2];
    const float* Wa  = (const float*)d_in[3];
    const float* ba  = (const float*)d_in[4];
    const float* Wb  = (const float*)d_in[5];
    const float* bb  = (const float*)d_in[6];
    const float* W1  = (const float*)d_in[7];
    const float* b1  = (const float*)d_in[8];
    const float* W2  = (const float*)d_in[9];
    const float* b2  = (const float*)d_in[10];
    float* out = (float*)d_out;

    cudaFuncSetAttribute(mlp_mma_kernel, cudaFuncAttributeMaxDynamicSharedMemorySize,
                         MLP_SMEM);

    // One-shot weight pre-swizzle (Wa/Wb/W1) + per-launch CSR build
    wconv_kernel<<<208, 256>>>(Wa, Wb, W1);
    zero_deg_kernel<<<(N_NODES + 255) / 256, 256>>>((const long long*)ei);
    hist_kernel<<<1024, 256>>>(ei);
    alloc_kernel<<<(N_NODES + 255) / 256, 256>>>();
    fill_kernel<<<1024, 256>>>(ei);

    const int gather_blocks = (N_NODES * 32 + 255) / 256;   // warp per node
    const int mlp_blocks = (N_NODES + MROWS - 1) / MROWS;   // 285 -> 2 waves

    for (int l = 0; l < 3; l++) {
        gather_kernel<<<gather_blocks, 256>>>(x, l > 0 ? 1 : 0, eps, l);
        mlp_mma_kernel<<<mlp_blocks, MTHREADS, MLP_SMEM>>>(
            l, (l == 2) ? 1 : 0,
            ba + (size_t)l * HID, bb + (size_t)l * HID,
            b1, W2, b2, out);
    }
}

// round 12
// speedup vs baseline: 2.2746x; 1.0156x over previous
#include <cuda_runtime.h>
#include <cuda_bf16.h>
#include <cstdint>

#define N_NODES 50000
#define N_EDGES 800000
#define HID 128
#define ZROWS 50176   // padded rows for safe cp.async tails (zero-init .bss)

// Persistent scratch (allocation-free rule: __device__ globals)
__device__ float g_h[(size_t)N_NODES * HID];
__device__ char  g_zh[(size_t)ZROWS * 256];   // z hi, bf16 [node][128]
__device__ char  g_zl[(size_t)ZROWS * 256];   // z lo
__device__ int   g_deg[N_NODES];
__device__ int   g_off[N_NODES];
__device__ int   g_cursor[N_NODES];
__device__ int   g_csr[N_EDGES];
__device__ int   g_total;
__device__ int   g_is64;
// pre-swizzled bf16 tiles: [l][WaH,WaL,WbH,WbL] + W1H,W1L (16KB each)
__device__ char  g_wt[3 * 131072 + 32768];

__device__ __forceinline__ void cp_async16(uint32_t saddr, const void* gptr) {
    asm volatile("cp.async.cg.shared.global [%0], [%1], 16;" ::"r"(saddr), "l"(gptr));
}
#define CP_COMMIT() asm volatile("cp.async.commit_group;")
#define CP_WAIT0()  asm volatile("cp.async.wait_group 0;")

__device__ __forceinline__ uint32_t smem_u32(const void* p) {
    return (uint32_t)__cvta_generic_to_shared(p);
}

#define LDMX4(r0, r1, r2, r3, a) \
    asm volatile("ldmatrix.sync.aligned.m8n8.x4.shared.b16 {%0,%1,%2,%3}, [%4];" \
                 : "=r"(r0), "=r"(r1), "=r"(r2), "=r"(r3) : "r"(a))

#define MMA16816(c, a, b0, b1) \
    asm volatile("mma.sync.aligned.m16n8k16.row.col.f32.bf16.bf16.f32 " \
                 "{%0,%1,%2,%3}, {%4,%5,%6,%7}, {%8,%9}, {%0,%1,%2,%3};" \
                 : "+f"((c)[0]), "+f"((c)[1]), "+f"((c)[2]), "+f"((c)[3]) \
                 : "r"((a)[0]), "r"((a)[1]), "r"((a)[2]), "r"((a)[3]), \
                   "r"(b0), "r"(b1))

// bf16 hi/lo split of two floats, packed bf16x2
__device__ __forceinline__ void bf16_split2(float x0, float x1,
                                            uint32_t& hi, uint32_t& lo) {
    __nv_bfloat16 h0 = __float2bfloat16(x0);
    __nv_bfloat16 h1 = __float2bfloat16(x1);
    __nv_bfloat16 l0 = __float2bfloat16(x0 - __bfloat162float(h0));
    __nv_bfloat16 l1 = __float2bfloat16(x1 - __bfloat162float(h1));
    __nv_bfloat162 hp = __halves2bfloat162(h0, h1);
    __nv_bfloat162 lp = __halves2bfloat162(l0, l1);
    hi = *(uint32_t*)&hp;
    lo = *(uint32_t*)&lp;
}

// W^T[n][k] swizzled byte offset (k even; 4B/16B chunk aligned)
__device__ __forceinline__ uint32_t wswz(int n, int k) {
    uint32_t chunk = ((uint32_t)(k >> 3)) ^ (uint32_t)(n & 7);
    return (uint32_t)n * 256 + chunk * 16 + (uint32_t)(k & 7) * 2;
}

// ---------------------------------------------------------------------------
// init: zero degrees + dtype detect (idx < 50000) and one-shot weight
// pre-swizzle (50000 <= idx < 103248): fp32 W -> bf16 hi/lo swizzled tiles.
// ---------------------------------------------------------------------------
__global__ void init_kernel(const long long* __restrict__ ei,
                            const float* __restrict__ Wa,
                            const float* __restrict__ Wb,
                            const float* __restrict__ W1) {
    int idx = blockIdx.x * blockDim.x + threadIdx.x;
    if (idx < N_NODES) {
        g_deg[idx] = 0;
        if (idx == 0) {
            g_total = 0;
            int ok = 1;
            for (int k = 0; k < 64; k++) {
                long long v = ei[k];
                if (v < 0 || v >= N_NODES) { ok = 0; break; }
            }
            g_is64 = ok;
        }
        return;
    }
    int w = idx - N_NODES;          // 0 .. 53247
    if (w < 49152) {
        int l = w / 16384;
        int rem = w - l * 16384;
        int m = rem >> 13;          // 0 = Wa, 1 = Wb
        int pos = rem & 8191;
        int n = pos >> 6;
        int k = (pos & 63) * 2;
        const float* src = (m == 0 ? Wa : Wb) + (size_t)l * 16384;
        uint32_t hi, lo;
        bf16_split2(__ldg(&src[k * 128 + n]), __ldg(&src[(k + 1) * 128 + n]), hi, lo);
        uint32_t b = wswz(n, k);
        char* base = g_wt + ((size_t)l * 4 + m * 2) * 32768;
        *(uint32_t*)(base + b) = hi;
        *(uint32_t*)(base + 32768 + b) = lo;
    } else if (w < 53248) {
        int pos = w - 49152;        // 0..4095
        int n = pos >> 6;
        int k = (pos & 63) * 2;
        uint32_t hi, lo;
        bf16_split2(__ldg(&W1[k * 64 + n]), __ldg(&W1[(k + 1) * 64 + n]), hi, lo);
        uint32_t b = wswz(n, k);
        char* base = g_wt + 393216;
        *(uint32_t*)(base + b) = hi;
        *(uint32_t*)(base + 16384 + b) = lo;
    }
}

// ---------------------------------------------------------------------------
// CSR build: vectorized histogram + warp-agg base alloc + vectorized fill.
// Exactly 4 edges per thread (N_EDGES % 4 == 0), loop-free.
// ---------------------------------------------------------------------------
__global__ void hist_kernel(const void* __restrict__ ei) {
    int t = blockIdx.x * blockDim.x + threadIdx.x;
    if (t * 4 >= N_EDGES) return;
    int d0, d1, d2, d3;
    if (g_is64) {
        const longlong2* p = (const longlong2*)((const long long*)ei + N_EDGES) + t * 2;
        longlong2 a = __ldg(p), b = __ldg(p + 1);
        d0 = (int)a.x; d1 = (int)a.y; d2 = (int)b.x; d3 = (int)b.y;
    } else {
        int4 d = __ldg((const int4*)((const int*)ei + N_EDGES) + t);
        d0 = d.x; d1 = d.y; d2 = d.z; d3 = d.w;
    }
    atomicAdd(&g_deg[d0], 1);
    atomicAdd(&g_deg[d1], 1);
    atomicAdd(&g_deg[d2], 1);
    atomicAdd(&g_deg[d3], 1);
}

// Segment bases need only be disjoint, not ordered: warp shfl-scan + one
// atomicAdd per warp on a global cursor.
__global__ void alloc_kernel() {
    int i = blockIdx.x * blockDim.x + threadIdx.x;
    int lane = threadIdx.x & 31;
    int valid = (i < N_NODES);
    int d = valid ? g_deg[i] : 0;
    int inc = d;
#pragma unroll
    for (int o = 1; o < 32; o <<= 1) {
        int n = __shfl_up_sync(0xffffffffu, inc, o);
        if (lane >= o) inc += n;
    }
    int wsum = __shfl_sync(0xffffffffu, inc, 31);
    int base = 0;
    if (lane == 31) base = atomicAdd(&g_total, wsum);
    base = __shfl_sync(0xffffffffu, base, 31);
    if (valid) {
        int b = base + inc - d;
        g_off[i] = b;
        g_cursor[i] = b;
    }
}

__global__ void fill_kernel(const void* __restrict__ ei) {
    int t = blockIdx.x * blockDim.x + threadIdx.x;
    if (t * 4 >= N_EDGES) return;
    int s0, s1, s2, s3, d0, d1, d2, d3;
    if (g_is64) {
        const longlong2* ps = (const longlong2*)ei + t * 2;
        const longlong2* pd = (const longlong2*)((const long long*)ei + N_EDGES) + t * 2;
        longlong2 sa = __ldg(ps), sb = __ldg(ps + 1);
        longlong2 da = __ldg(pd), db = __ldg(pd + 1);
        s0 = (int)sa.x; s1 = (int)sa.y; s2 = (int)sb.x; s3 = (int)sb.y;
        d0 = (int)da.x; d1 = (int)da.y; d2 = (int)db.x; d3 = (int)db.y;
    } else {
        int4 s = __ldg((const int4*)ei + t);
        int4 d = __ldg((const int4*)((const int*)ei + N_EDGES) + t);
        s0 = s.x; s1 = s.y; s2 = s.z; s3 = s.w;
        d0 = d.x; d1 = d.y; d2 = d.z; d3 = d.w;
    }
    g_csr[atomicAdd(&g_cursor[d0], 1)] = s0;
    g_csr[atomicAdd(&g_cursor[d1], 1)] = s1;
    g_csr[atomicAdd(&g_cursor[d2], 1)] = s2;
    g_csr[atomicAdd(&g_cursor[d3], 1)] = s3;
}

// ---------------------------------------------------------------------------
// Gather: one warp per node; writes z directly as bf16 hi/lo split images.
// ---------------------------------------------------------------------------
__global__ __launch_bounds__(256) void gather_kernel(
    const float* __restrict__ x, int use_gh,
    const float* __restrict__ eps, int l) {
    const float* h = use_gh ? g_h : x;
    const int node = (int)(((size_t)blockIdx.x * blockDim.x + threadIdx.x) >> 5);
    const int lane = threadIdx.x & 31;
    if (node >= N_NODES) return;
    const int s0 = g_off[node];
    const int s1 = s0 + g_deg[node];
    const float4* h4 = (const float4*)h;

    float4 a0 = make_float4(0.f, 0.f, 0.f, 0.f);
    float4 a1 = make_float4(0.f, 0.f, 0.f, 0.f);
    float4 a2 = make_float4(0.f, 0.f, 0.f, 0.f);
    float4 a3 = make_float4(0.f, 0.f, 0.f, 0.f);
    int i = s0;
    for (; i + 3 < s1; i += 4) {
        int sa = __ldg(&g_csr[i]);
        int sb = __ldg(&g_csr[i + 1]);
        int sc = __ldg(&g_csr[i + 2]);
        int sd = __ldg(&g_csr[i + 3]);
        float4 va = __ldg(&h4[(size_t)sa * 32 + lane]);
        float4 vb = __ldg(&h4[(size_t)sb * 32 + lane]);
        float4 vc = __ldg(&h4[(size_t)sc * 32 + lane]);
        float4 vd = __ldg(&h4[(size_t)sd * 32 + lane]);
        a0.x += va.x; a0.y += va.y; a0.z += va.z; a0.w += va.w;
        a1.x += vb.x; a1.y += vb.y; a1.z += vb.z; a1.w += vb.w;
        a2.x += vc.x; a2.y += vc.y; a2.z += vc.z; a2.w += vc.w;
        a3.x += vd.x; a3.y += vd.y; a3.z += vd.z; a3.w += vd.w;
    }
    for (; i < s1; i++) {
        int sa = __ldg(&g_csr[i]);
        float4 va = __ldg(&h4[(size_t)sa * 32 + lane]);
        a0.x += va.x; a0.y += va.y; a0.z += va.z; a0.w += va.w;
    }
    a0.x += a1.x + a2.x + a3.x;
    a0.y += a1.y + a2.y + a3.y;
    a0.z += a1.z + a2.z + a3.z;
    a0.w += a1.w + a2.w + a3.w;

    const float sc_ = 1.0f + eps[l];
    float4 hv = h4[(size_t)node * 32 + lane];
    a0.x = fmaf(sc_, hv.x, a0.x);
    a0.y = fmaf(sc_, hv.y, a0.y);
    a0.z = fmaf(sc_, hv.z, a0.z);
    a0.w = fmaf(sc_, hv.w, a0.w);

    uint32_t h0, l0, h1, l1;
    bf16_split2(a0.x, a0.y, h0, l0);
    bf16_split2(a0.z, a0.w, h1, l1);
    *(uint2*)(g_zh + (size_t)node * 256 + lane * 8) = make_uint2(h0, h1);
    *(uint2*)(g_zl + (size_t)node * 256 + lane * 8) = make_uint2(l0, l1);
}

// ---------------------------------------------------------------------------
// bf16-split HMMA MLP: 176 rows/CTA, 6 warps. Last layer fuses the head:
// stage-3 MMA vs W1 (N=64) + quad-shfl W2 reduction -> out. No head kernel.
// ---------------------------------------------------------------------------
#define MROWS 176
#define MTHREADS 192
#define OFF_ZH 0
#define OFF_ZL 47872
#define OFF_W  95744                 // WH1,WL1,WH2,WL2 (4 x 32768)
#define OFF_BA 226816
#define OFF_BB 227328
#define OFF_B1 227840                // head b1 (64 f32)
#define OFF_W2 228096                // head W2 (64x2 f32)
#define MLP_SMEM 228608

template<int NP>
__device__ __forceinline__ void gemm_stage(
    const uint32_t sbase, const uint32_t WH, const uint32_t WL,
    int a_m0, uint32_t a_koff, int b_n, int b_kc, bool two,
    float acc0[][4], float acc1[][4]) {
    uint32_t ah0[4], al0[4], ah1[4], al1[4], bh[4], bl[4];
#pragma unroll
    for (int t = 0; t < 2 * NP; t++)
#pragma unroll
        for (int j = 0; j < 4; j++) { acc0[t][j] = 0.f; acc1[t][j] = 0.f; }
#pragma unroll
    for (int ks = 0; ks < 8; ks++) {
        uint32_t aaddr = sbase + OFF_ZH + a_m0 * 272 + ks * 32 + a_koff;
        LDMX4(ah0[0], ah0[1], ah0[2], ah0[3], aaddr);
        LDMX4(al0[0], al0[1], al0[2], al0[3], aaddr + (OFF_ZL - OFF_ZH));
        if (two) {
            uint32_t aaddr1 = aaddr + 16 * 272;
            LDMX4(ah1[0], ah1[1], ah1[2], ah1[3], aaddr1);
            LDMX4(al1[0], al1[1], al1[2], al1[3], aaddr1 + (OFF_ZL - OFF_ZH));
        }
#pragma unroll
        for (int np = 0; np < NP; np++) {
            uint32_t boff = wswz(np * 16 + b_n, ks * 16 + b_kc * 8);
            LDMX4(bh[0], bh[1], bh[2], bh[3], WH + boff);
            LDMX4(bl[0], bl[1], bl[2], bl[3], WL + boff);
            MMA16816(acc0[2 * np], ah0, bh[0], bh[1]);
            if (two) MMA16816(acc1[2 * np], ah1, bh[0], bh[1]);
            MMA16816(acc0[2 * np], al0, bh[0], bh[1]);
            if (two) MMA16816(acc1[2 * np], al1, bh[0], bh[1]);
            MMA16816(acc0[2 * np], ah0, bl[0], bl[1]);
            if (two) MMA16816(acc1[2 * np], ah1, bl[0], bl[1]);
            MMA16816(acc0[2 * np + 1], ah0, bh[2], bh[3]);
            if (two) MMA16816(acc1[2 * np + 1], ah1, bh[2], bh[3]);
            MMA16816(acc0[2 * np + 1], al0, bh[2], bh[3]);
            if (two) MMA16816(acc1[2 * np + 1], al1, bh[2], bh[3]);
            MMA16816(acc0[2 * np + 1], ah0, bl[2], bl[3]);
            if (two) MMA16816(acc1[2 * np + 1], ah1, bl[2], bl[3]);
        }
    }
}

__global__ __launch_bounds__(MTHREADS) void mlp_mma_kernel(
    int l, int last,
    const float* __restrict__ ba, const float* __restrict__ bb,
    const float* __restrict__ b1, const float* __restrict__ W2,
    const float* __restrict__ b2, float* __restrict__ out) {
    extern __shared__ char smem[];
    float* s_ba = (float*)(smem + OFF_BA);
    float* s_bb = (float*)(smem + OFF_BB);
    float* s_b1 = (float*)(smem + OFF_B1);
    float* s_w2 = (float*)(smem + OFF_W2);

    const int tid = threadIdx.x;
    const int warp = tid >> 5;
    const int lane = tid & 31;
    const int row0 = blockIdx.x * MROWS;
    const uint32_t sbase = smem_u32(smem);

    // P0: linear cp.async of W tiles (128KB) + z hi/lo tiles (89.6KB); biases
    const char* wsrc = g_wt + (size_t)l * 131072;
    for (int i = tid; i < 8192; i += MTHREADS)
        cp_async16(sbase + OFF_W + i * 16, wsrc + i * 16);
    for (int i = tid; i < MROWS * 16; i += MTHREADS) {   // 2816
        int r = i >> 4, c = i & 15;
        size_t goff = (size_t)(row0 + r) * 256 + c * 16;
        cp_async16(sbase + OFF_ZH + r * 272 + c * 16, g_zh + goff);
        cp_async16(sbase + OFF_ZL + r * 272 + c * 16, g_zl + goff);
    }
    CP_COMMIT();
    if (tid < 128) { s_ba[tid] = __ldg(&ba[tid]); s_bb[tid] = __ldg(&bb[tid]); }
    float b2_0 = 0.f, b2_1 = 0.f;
    if (last) {
        if (tid < 64) s_b1[tid] = __ldg(&b1[tid]);
        if (tid < 128) s_w2[tid] = __ldg(&W2[tid]);
        b2_0 = __ldg(&b2[0]); b2_1 = __ldg(&b2[1]);
    }
    CP_WAIT0();
    __syncthreads();

    const int m0 = warp * 32;                       // warp5 -> 160
    const bool two = (warp < 5);
    const int a_m0 = m0 + (lane & 15);
    const uint32_t a_koff = (uint32_t)((lane >> 4) * 16);
    const int b_n = (lane & 7) + ((lane >> 4) << 3);
    const int b_kc = (lane >> 3) & 1;
    const int m_r = m0 + (lane >> 2);

    float acc0[16][4], acc1[16][4];

    // ---- Stage 1: z @ Wa
    gemm_stage<8>(sbase, sbase + OFF_W, sbase + OFF_W + 32768,
                  a_m0, a_koff, b_n, b_kc, two, acc0, acc1);
    // t = relu(acc + ba) -> re-split into ZH/ZL (own rows only)
#pragma unroll
    for (int nt = 0; nt < 16; nt++) {
        int col = nt * 8 + 2 * (lane & 3);
        float b0 = s_ba[col], b1v = s_ba[col + 1];
        uint32_t hi, lo;
        bf16_split2(fmaxf(acc0[nt][0] + b0, 0.f),
                    fmaxf(acc0[nt][1] + b1v, 0.f), hi, lo);
        *(uint32_t*)(smem + OFF_ZH + m_r * 272 + col * 2) = hi;
        *(uint32_t*)(smem + OFF_ZL + m_r * 272 + col * 2) = lo;
        bf16_split2(fmaxf(acc0[nt][2] + b0, 0.f),
                    fmaxf(acc0[nt][3] + b1v, 0.f), hi, lo);
        *(uint32_t*)(smem + OFF_ZH + (m_r + 8) * 272 + col * 2) = hi;
        *(uint32_t*)(smem + OFF_ZL + (m_r + 8) * 272 + col * 2) = lo;
        if (two) {
            bf16_split2(fmaxf(acc1[nt][0] + b0, 0.f),
                        fmaxf(acc1[nt][1] + b1v, 0.f), hi, lo);
            *(uint32_t*)(smem + OFF_ZH + (m_r + 16) * 272 + col * 2) = hi;
            *(uint32_t*)(smem + OFF_ZL + (m_r + 16) * 272 + col * 2) = lo;
            bf16_split2(fmaxf(acc1[nt][2] + b0, 0.f),
                        fmaxf(acc1[nt][3] + b1v, 0.f), hi, lo);
            *(uint32_t*)(smem + OFF_ZH + (m_r + 24) * 272 + col * 2) = hi;
            *(uint32_t*)(smem + OFF_ZL + (m_r + 24) * 272 + col * 2) = lo;
        }
    }
    __syncwarp();

    // Last layer: WH1/WL1 region is dead after stage 1 -> prefetch W1 tiles
    // under stage-2 compute (uniform branch, CTA-wide barrier).
    if (last) {
        __syncthreads();
        const char* w1src = g_wt + 393216;
        for (int i = tid; i < 2048; i += MTHREADS)
            cp_async16(sbase + OFF_W + i * 16, w1src + i * 16);
        CP_COMMIT();
    }

    // ---- Stage 2: t @ Wb
    gemm_stage<8>(sbase, sbase + OFF_W + 65536, sbase + OFF_W + 98304,
                  a_m0, a_koff, b_n, b_kc, two, acc0, acc1);

    if (!last) {
        // h_out = relu(acc + bb) -> g_h
        int n0 = row0 + m_r;
#pragma unroll
        for (int nt = 0; nt < 16; nt++) {
            int col = nt * 8 + 2 * (lane & 3);
            float b0 = s_bb[col], b1v = s_bb[col + 1];
            if (n0 < N_NODES) {
                float2 o;
                o.x = fmaxf(acc0[nt][0] + b0, 0.f);
                o.y = fmaxf(acc0[nt][1] + b1v, 0.f);
                *(float2*)(g_h + (size_t)n0 * 128 + col) = o;
            }
            if (n0 + 8 < N_NODES) {
                float2 o;
                o.x = fmaxf(acc0[nt][2] + b0, 0.f);
                o.y = fmaxf(acc0[nt][3] + b1v, 0.f);
                *(float2*)(g_h + (size_t)(n0 + 8) * 128 + col) = o;
            }
            if (two) {
                if (n0 + 16 < N_NODES) {
                    float2 o;
                    o.x = fmaxf(acc1[nt][0] + b0, 0.f);
                    o.y = fmaxf(acc1[nt][1] + b1v, 0.f);
                    *(float2*)(g_h + (size_t)(n0 + 16) * 128 + col) = o;
                }
                if (n0 + 24 < N_NODES) {
                    float2 o;
                    o.x = fmaxf(acc1[nt][2] + b0, 0.f);
                    o.y = fmaxf(acc1[nt][3] + b1v, 0.f);
                    *(float2*)(g_h + (size_t)(n0 + 24) * 128 + col) = o;
                }
            }
        }
        return;
    }

    // ---- Last layer: h = relu(acc + bb) -> ZH/ZL (own rows), then head.
#pragma unroll
    for (int nt = 0; nt < 16; nt++) {
        int col = nt * 8 + 2 * (lane & 3);
        float b0 = s_bb[col], b1v = s_bb[col + 1];
        uint32_t hi, lo;
        bf16_split2(fmaxf(acc0[nt][0] + b0, 0.f),
                    fmaxf(acc0[nt][1] + b1v, 0.f), hi, lo);
        *(uint32_t*)(smem + OFF_ZH + m_r * 272 + col * 2) = hi;
        *(uint32_t*)(smem + OFF_ZL + m_r * 272 + col * 2) = lo;
        bf16_split2(fmaxf(acc0[nt][2] + b0, 0.f),
                    fmaxf(acc0[nt][3] + b1v, 0.f), hi, lo);
        *(uint32_t*)(smem + OFF_ZH + (m_r + 8) * 272 + col * 2) = hi;
        *(uint32_t*)(smem + OFF_ZL + (m_r + 8) * 272 + col * 2) = lo;
        if (two) {
            bf16_split2(fmaxf(acc1[nt][0] + b0, 0.f),
                        fmaxf(acc1[nt][1] + b1v, 0.f), hi, lo);
            *(uint32_t*)(smem + OFF_ZH + (m_r + 16) * 272 + col * 2) = hi;
            *(uint32_t*)(smem + OFF_ZL + (m_r + 16) * 272 + col * 2) = lo;
            bf16_split2(fmaxf(acc1[nt][2] + b0, 0.f),
                        fmaxf(acc1[nt][3] + b1v, 0.f), hi, lo);
            *(uint32_t*)(smem + OFF_ZH + (m_r + 24) * 272 + col * 2) = hi;
            *(uint32_t*)(smem + OFF_ZL + (m_r + 24) * 272 + col * 2) = lo;
        }
    }
    CP_WAIT0();
    __syncthreads();   // W1 tiles visible CTA-wide; own-row ZH writes ordered

    // ---- Stage 3: hid_pre = h @ W1 (N=64)
    gemm_stage<4>(sbase, sbase + OFF_W, sbase + OFF_W + 16384,
                  a_m0, a_koff, b_n, b_kc, two, acc0, acc1);

    // head epilogue: hid = relu(acc + b1); out = hid @ W2 + b2 (quad reduce)
    const int nrr = two ? 4 : 2;
    for (int rr = 0; rr < nrr; rr++) {
        float (*A)[4] = (rr < 2) ? acc0 : acc1;
        const int i0 = (rr & 1) ? 2 : 0;
        float p0 = 0.f, p1 = 0.f;
#pragma unroll
        for (int nt = 0; nt < 8; nt++) {
            int c = nt * 8 + 2 * (lane & 3);
            float v0 = fmaxf(A[nt][i0] + s_b1[c], 0.f);
            float v1 = fmaxf(A[nt][i0 + 1] + s_b1[c + 1], 0.f);
            p0 = fmaf(v0, s_w2[2 * c], fmaf(v1, s_w2[2 * c + 2], p0));
            p1 = fmaf(v0, s_w2[2 * c + 1], fmaf(v1, s_w2[2 * c + 3], p1));
        }
        p0 += __shfl_xor_sync(0xffffffffu, p0, 1);
        p0 += __shfl_xor_sync(0xffffffffu, p0, 2);
        p1 += __shfl_xor_sync(0xffffffffu, p1, 1);
        p1 += __shfl_xor_sync(0xffffffffu, p1, 2);
        int row = row0 + m_r + ((rr & 1) ? 8 : 0) + ((rr >= 2) ? 16 : 0);
        if ((lane & 3) == 0 && row < N_NODES) {
            float2 o;
            o.x = p0 + b2_0;
            o.y = p1 + b2_1;
            *(float2*)(out + (size_t)row * 2) = o;
        }
    }
}

// ---------------------------------------------------------------------------
extern "C" void kernel_launch(void* const* d_in, const int* in_sizes, int n_in,
                              void* d_out, int out_size) {
    const float* x   = (const float*)d_in[0];
    const void*  ei  = d_in[1];
    const float* eps = (const float*)d_in[2];
    const float* Wa  = (const float*)d_in[3];
    const float* ba  = (const float*)d_in[4];
    const float* Wb  = (const float*)d_in[5];
    const float* bb  = (const float*)d_in[6];
    const float* W1  = (const float*)d_in[7];
    const float* b1  = (const float*)d_in[8];
    const float* W2  = (const float*)d_in[9];
    const float* b2  = (const float*)d_in[10];
    float* out = (float*)d_out;

    cudaFuncSetAttribute(mlp_mma_kernel, cudaFuncAttributeMaxDynamicSharedMemorySize,
                         MLP_SMEM);

    // init (zero deg + dtype detect + weight pre-swizzle), then CSR build
    const int init_blocks = (N_NODES + 53248 + 255) / 256;     // 404
    const int edge_blocks = (N_EDGES / 4 + 255) / 256;         // 782
    init_kernel<<<init_blocks, 256>>>((const long long*)ei, Wa, Wb, W1);
    hist_kernel<<<edge_blocks, 256>>>(ei);
    alloc_kernel<<<(N_NODES + 255) / 256, 256>>>();
    fill_kernel<<<edge_blocks, 256>>>(ei);

    const int gather_blocks = (N_NODES * 32 + 255) / 256;   // warp per node
    const int mlp_blocks = (N_NODES + MROWS - 1) / MROWS;   // 285 -> 2 waves

    for (int l = 0; l < 3; l++) {
        gather_kernel<<<gather_blocks, 256>>>(x, l > 0 ? 1 : 0, eps, l);
        mlp_mma_kernel<<<mlp_blocks, MTHREADS, MLP_SMEM>>>(
            l, (l == 2) ? 1 : 0,
            ba + (size_t)l * HID, bb + (size_t)l * HID,
            b1, W2, b2, out);
    }
}

// round 13
// speedup vs baseline: 2.3065x; 1.0140x over previous
#include <cuda_runtime.h>
#include <cuda_bf16.h>
#include <cstdint>

#define N_NODES 50000
#define N_EDGES 800000
#define HID 128
#define ZROWS 50176   // padded rows for safe cp.async tails (zero-init .bss)

// Persistent scratch (allocation-free rule: __device__ globals)
__device__ float g_h[(size_t)N_NODES * HID];
__device__ char  g_zh[(size_t)ZROWS * 256];   // z hi, bf16 [node][128]
__device__ char  g_zl[(size_t)ZROWS * 256];   // z lo
__device__ int   g_deg[N_NODES];
__device__ int   g_off[N_NODES];
__device__ int   g_cursor[N_NODES];
__device__ int   g_csr[N_EDGES];
__device__ int   g_total;
__device__ int   g_is64;
// pre-swizzled bf16 tiles: [l][WaH,WaL,WbH,WbL] + W1H,W1L (16KB each)
__device__ char  g_wt[3 * 131072 + 32768];

// PDL: trigger dependent-grid launch / wait for predecessor completion
#define PDL_LAUNCH() asm volatile("griddepcontrol.launch_dependents;")
#define PDL_WAIT()   asm volatile("griddepcontrol.wait;" ::: "memory")

__device__ __forceinline__ void cp_async16(uint32_t saddr, const void* gptr) {
    asm volatile("cp.async.cg.shared.global [%0], [%1], 16;" ::"r"(saddr), "l"(gptr));
}
#define CP_COMMIT() asm volatile("cp.async.commit_group;")
#define CP_WAIT0()  asm volatile("cp.async.wait_group 0;")

__device__ __forceinline__ uint32_t smem_u32(const void* p) {
    return (uint32_t)__cvta_generic_to_shared(p);
}

#define LDMX4(r0, r1, r2, r3, a) \
    asm volatile("ldmatrix.sync.aligned.m8n8.x4.shared.b16 {%0,%1,%2,%3}, [%4];" \
                 : "=r"(r0), "=r"(r1), "=r"(r2), "=r"(r3) : "r"(a))

#define MMA16816(c, a, b0, b1) \
    asm volatile("mma.sync.aligned.m16n8k16.row.col.f32.bf16.bf16.f32 " \
                 "{%0,%1,%2,%3}, {%4,%5,%6,%7}, {%8,%9}, {%0,%1,%2,%3};" \
                 : "+f"((c)[0]), "+f"((c)[1]), "+f"((c)[2]), "+f"((c)[3]) \
                 : "r"((a)[0]), "r"((a)[1]), "r"((a)[2]), "r"((a)[3]), \
                   "r"(b0), "r"(b1))

// bf16 hi/lo split of two floats, packed bf16x2
__device__ __forceinline__ void bf16_split2(float x0, float x1,
                                            uint32_t& hi, uint32_t& lo) {
    __nv_bfloat16 h0 = __float2bfloat16(x0);
    __nv_bfloat16 h1 = __float2bfloat16(x1);
    __nv_bfloat16 l0 = __float2bfloat16(x0 - __bfloat162float(h0));
    __nv_bfloat16 l1 = __float2bfloat16(x1 - __bfloat162float(h1));
    __nv_bfloat162 hp = __halves2bfloat162(h0, h1);
    __nv_bfloat162 lp = __halves2bfloat162(l0, l1);
    hi = *(uint32_t*)&hp;
    lo = *(uint32_t*)&lp;
}

// W^T[n][k] swizzled byte offset (k even; 4B/16B chunk aligned)
__device__ __forceinline__ uint32_t wswz(int n, int k) {
    uint32_t chunk = ((uint32_t)(k >> 3)) ^ (uint32_t)(n & 7);
    return (uint32_t)n * 256 + chunk * 16 + (uint32_t)(k & 7) * 2;
}

// ---------------------------------------------------------------------------
// init: zero degrees + dtype detect (idx < 50000) and one-shot weight
// pre-swizzle: fp32 W -> bf16 hi/lo swizzled tiles.
// ---------------------------------------------------------------------------
__global__ void init_kernel(const long long* __restrict__ ei,
                            const float* __restrict__ Wa,
                            const float* __restrict__ Wb,
                            const float* __restrict__ W1) {
    PDL_LAUNCH();
    int idx = blockIdx.x * blockDim.x + threadIdx.x;
    if (idx < N_NODES) {
        g_deg[idx] = 0;
        if (idx == 0) {
            g_total = 0;
            int ok = 1;
            for (int k = 0; k < 64; k++) {
                long long v = ei[k];
                if (v < 0 || v >= N_NODES) { ok = 0; break; }
            }
            g_is64 = ok;
        }
        return;
    }
    int w = idx - N_NODES;          // 0 .. 53247
    if (w < 49152) {
        int l = w / 16384;
        int rem = w - l * 16384;
        int m = rem >> 13;          // 0 = Wa, 1 = Wb
        int pos = rem & 8191;
        int n = pos >> 6;
        int k = (pos & 63) * 2;
        const float* src = (m == 0 ? Wa : Wb) + (size_t)l * 16384;
        uint32_t hi, lo;
        bf16_split2(__ldg(&src[k * 128 + n]), __ldg(&src[(k + 1) * 128 + n]), hi, lo);
        uint32_t b = wswz(n, k);
        char* base = g_wt + ((size_t)l * 4 + m * 2) * 32768;
        *(uint32_t*)(base + b) = hi;
        *(uint32_t*)(base + 32768 + b) = lo;
    } else if (w < 53248) {
        int pos = w - 49152;        // 0..4095
        int n = pos >> 6;
        int k = (pos & 63) * 2;
        uint32_t hi, lo;
        bf16_split2(__ldg(&W1[k * 64 + n]), __ldg(&W1[(k + 1) * 64 + n]), hi, lo);
        uint32_t b = wswz(n, k);
        char* base = g_wt + 393216;
        *(uint32_t*)(base + b) = hi;
        *(uint32_t*)(base + 16384 + b) = lo;
    }
}

// ---------------------------------------------------------------------------
// CSR build: vectorized histogram + warp-agg base alloc + vectorized fill.
// ---------------------------------------------------------------------------
__global__ void hist_kernel(const void* __restrict__ ei) {
    PDL_LAUNCH();
    PDL_WAIT();
    int t = blockIdx.x * blockDim.x + threadIdx.x;
    if (t * 4 >= N_EDGES) return;
    int d0, d1, d2, d3;
    if (g_is64) {
        const longlong2* p = (const longlong2*)((const long long*)ei + N_EDGES) + t * 2;
        longlong2 a = __ldg(p), b = __ldg(p + 1);
        d0 = (int)a.x; d1 = (int)a.y; d2 = (int)b.x; d3 = (int)b.y;
    } else {
        int4 d = __ldg((const int4*)((const int*)ei + N_EDGES) + t);
        d0 = d.x; d1 = d.y; d2 = d.z; d3 = d.w;
    }
    atomicAdd(&g_deg[d0], 1);
    atomicAdd(&g_deg[d1], 1);
    atomicAdd(&g_deg[d2], 1);
    atomicAdd(&g_deg[d3], 1);
}

__global__ void alloc_kernel() {
    PDL_LAUNCH();
    PDL_WAIT();
    int i = blockIdx.x * blockDim.x + threadIdx.x;
    int lane = threadIdx.x & 31;
    int valid = (i < N_NODES);
    int d = valid ? g_deg[i] : 0;
    int inc = d;
#pragma unroll
    for (int o = 1; o < 32; o <<= 1) {
        int n = __shfl_up_sync(0xffffffffu, inc, o);
        if (lane >= o) inc += n;
    }
    int wsum = __shfl_sync(0xffffffffu, inc, 31);
    int base = 0;
    if (lane == 31) base = atomicAdd(&g_total, wsum);
    base = __shfl_sync(0xffffffffu, base, 31);
    if (valid) {
        int b = base + inc - d;
        g_off[i] = b;
        g_cursor[i] = b;
    }
}

__global__ void fill_kernel(const void* __restrict__ ei) {
    PDL_LAUNCH();
    PDL_WAIT();
    int t = blockIdx.x * blockDim.x + threadIdx.x;
    if (t * 4 >= N_EDGES) return;
    int s0, s1, s2, s3, d0, d1, d2, d3;
    if (g_is64) {
        const longlong2* ps = (const longlong2*)ei + t * 2;
        const longlong2* pd = (const longlong2*)((const long long*)ei + N_EDGES) + t * 2;
        longlong2 sa = __ldg(ps), sb = __ldg(ps + 1);
        longlong2 da = __ldg(pd), db = __ldg(pd + 1);
        s0 = (int)sa.x; s1 = (int)sa.y; s2 = (int)sb.x; s3 = (int)sb.y;
        d0 = (int)da.x; d1 = (int)da.y; d2 = (int)db.x; d3 = (int)db.y;
    } else {
        int4 s = __ldg((const int4*)ei + t);
        int4 d = __ldg((const int4*)((const int*)ei + N_EDGES) + t);
        s0 = s.x; s1 = s.y; s2 = s.z; s3 = s.w;
        d0 = d.x; d1 = d.y; d2 = d.z; d3 = d.w;
    }
    g_csr[atomicAdd(&g_cursor[d0], 1)] = s0;
    g_csr[atomicAdd(&g_cursor[d1], 1)] = s1;
    g_csr[atomicAdd(&g_cursor[d2], 1)] = s2;
    g_csr[atomicAdd(&g_cursor[d3], 1)] = s3;
}

// ---------------------------------------------------------------------------
// Gather: one warp per node; writes z directly as bf16 hi/lo split images.
// ---------------------------------------------------------------------------
__global__ __launch_bounds__(256) void gather_kernel(
    const float* __restrict__ x, int use_gh,
    const float* __restrict__ eps, int l) {
    PDL_LAUNCH();
    PDL_WAIT();
    const float* h = use_gh ? g_h : x;
    const int node = (int)(((size_t)blockIdx.x * blockDim.x + threadIdx.x) >> 5);
    const int lane = threadIdx.x & 31;
    if (node >= N_NODES) return;
    const int s0 = g_off[node];
    const int s1 = s0 + g_deg[node];
    const float4* h4 = (const float4*)h;

    float4 a0 = make_float4(0.f, 0.f, 0.f, 0.f);
    float4 a1 = make_float4(0.f, 0.f, 0.f, 0.f);
    float4 a2 = make_float4(0.f, 0.f, 0.f, 0.f);
    float4 a3 = make_float4(0.f, 0.f, 0.f, 0.f);
    int i = s0;
    for (; i + 3 < s1; i += 4) {
        int sa = __ldg(&g_csr[i]);
        int sb = __ldg(&g_csr[i + 1]);
        int sc = __ldg(&g_csr[i + 2]);
        int sd = __ldg(&g_csr[i + 3]);
        float4 va = __ldg(&h4[(size_t)sa * 32 + lane]);
        float4 vb = __ldg(&h4[(size_t)sb * 32 + lane]);
        float4 vc = __ldg(&h4[(size_t)sc * 32 + lane]);
        float4 vd = __ldg(&h4[(size_t)sd * 32 + lane]);
        a0.x += va.x; a0.y += va.y; a0.z += va.z; a0.w += va.w;
        a1.x += vb.x; a1.y += vb.y; a1.z += vb.z; a1.w += vb.w;
        a2.x += vc.x; a2.y += vc.y; a2.z += vc.z; a2.w += vc.w;
        a3.x += vd.x; a3.y += vd.y; a3.z += vd.z; a3.w += vd.w;
    }
    for (; i < s1; i++) {
        int sa = __ldg(&g_csr[i]);
        float4 va = __ldg(&h4[(size_t)sa * 32 + lane]);
        a0.x += va.x; a0.y += va.y; a0.z += va.z; a0.w += va.w;
    }
    a0.x += a1.x + a2.x + a3.x;
    a0.y += a1.y + a2.y + a3.y;
    a0.z += a1.z + a2.z + a3.z;
    a0.w += a1.w + a2.w + a3.w;

    const float sc_ = 1.0f + eps[l];
    float4 hv = h4[(size_t)node * 32 + lane];
    a0.x = fmaf(sc_, hv.x, a0.x);
    a0.y = fmaf(sc_, hv.y, a0.y);
    a0.z = fmaf(sc_, hv.z, a0.z);
    a0.w = fmaf(sc_, hv.w, a0.w);

    uint32_t h0, l0, h1, l1;
    bf16_split2(a0.x, a0.y, h0, l0);
    bf16_split2(a0.z, a0.w, h1, l1);
    *(uint2*)(g_zh + (size_t)node * 256 + lane * 8) = make_uint2(h0, h1);
    *(uint2*)(g_zl + (size_t)node * 256 + lane * 8) = make_uint2(l0, l1);
}

// ---------------------------------------------------------------------------
// bf16-split HMMA MLP: 176 rows/CTA, 6 warps. Last layer fuses the head.
// PDL: weight cp.async + bias loads issued BEFORE the wait (inputs only);
// z loads after (depend on gather).
// ---------------------------------------------------------------------------
#define MROWS 176
#define MTHREADS 192
#define OFF_ZH 0
#define OFF_ZL 47872
#define OFF_W  95744                 // WH1,WL1,WH2,WL2 (4 x 32768)
#define OFF_BA 226816
#define OFF_BB 227328
#define OFF_B1 227840                // head b1 (64 f32)
#define OFF_W2 228096                // head W2 (64x2 f32)
#define MLP_SMEM 228608

template<int NP>
__device__ __forceinline__ void gemm_stage(
    const uint32_t sbase, const uint32_t WH, const uint32_t WL,
    int a_m0, uint32_t a_koff, int b_n, int b_kc, bool two,
    float acc0[][4], float acc1[][4]) {
    uint32_t ah0[4], al0[4], ah1[4], al1[4], bh[4], bl[4];
#pragma unroll
    for (int t = 0; t < 2 * NP; t++)
#pragma unroll
        for (int j = 0; j < 4; j++) { acc0[t][j] = 0.f; acc1[t][j] = 0.f; }
#pragma unroll
    for (int ks = 0; ks < 8; ks++) {
        uint32_t aaddr = sbase + OFF_ZH + a_m0 * 272 + ks * 32 + a_koff;
        LDMX4(ah0[0], ah0[1], ah0[2], ah0[3], aaddr);
        LDMX4(al0[0], al0[1], al0[2], al0[3], aaddr + (OFF_ZL - OFF_ZH));
        if (two) {
            uint32_t aaddr1 = aaddr + 16 * 272;
            LDMX4(ah1[0], ah1[1], ah1[2], ah1[3], aaddr1);
            LDMX4(al1[0], al1[1], al1[2], al1[3], aaddr1 + (OFF_ZL - OFF_ZH));
        }
#pragma unroll
        for (int np = 0; np < NP; np++) {
            uint32_t boff = wswz(np * 16 + b_n, ks * 16 + b_kc * 8);
            LDMX4(bh[0], bh[1], bh[2], bh[3], WH + boff);
            LDMX4(bl[0], bl[1], bl[2], bl[3], WL + boff);
            MMA16816(acc0[2 * np], ah0, bh[0], bh[1]);
            if (two) MMA16816(acc1[2 * np], ah1, bh[0], bh[1]);
            MMA16816(acc0[2 * np], al0, bh[0], bh[1]);
            if (two) MMA16816(acc1[2 * np], al1, bh[0], bh[1]);
            MMA16816(acc0[2 * np], ah0, bl[0], bl[1]);
            if (two) MMA16816(acc1[2 * np], ah1, bl[0], bl[1]);
            MMA16816(acc0[2 * np + 1], ah0, bh[2], bh[3]);
            if (two) MMA16816(acc1[2 * np + 1], ah1, bh[2], bh[3]);
            MMA16816(acc0[2 * np + 1], al0, bh[2], bh[3]);
            if (two) MMA16816(acc1[2 * np + 1], al1, bh[2], bh[3]);
            MMA16816(acc0[2 * np + 1], ah0, bl[2], bl[3]);
            if (two) MMA16816(acc1[2 * np + 1], ah1, bl[2], bl[3]);
        }
    }
}

__global__ __launch_bounds__(MTHREADS) void mlp_mma_kernel(
    int l, int last,
    const float* __restrict__ ba, const float* __restrict__ bb,
    const float* __restrict__ b1, const float* __restrict__ W2,
    const float* __restrict__ b2, float* __restrict__ out) {
    extern __shared__ char smem[];
    float* s_ba = (float*)(smem + OFF_BA);
    float* s_bb = (float*)(smem + OFF_BB);
    float* s_b1 = (float*)(smem + OFF_B1);
    float* s_w2 = (float*)(smem + OFF_W2);

    const int tid = threadIdx.x;
    const int warp = tid >> 5;
    const int lane = tid & 31;
    const int row0 = blockIdx.x * MROWS;
    const uint32_t sbase = smem_u32(smem);

    PDL_LAUNCH();

    // P0a (pre-wait, inputs only): weight tiles (128KB) + biases
    const char* wsrc = g_wt + (size_t)l * 131072;
    for (int i = tid; i < 8192; i += MTHREADS)
        cp_async16(sbase + OFF_W + i * 16, wsrc + i * 16);
    if (tid < 128) { s_ba[tid] = __ldg(&ba[tid]); s_bb[tid] = __ldg(&bb[tid]); }
    float b2_0 = 0.f, b2_1 = 0.f;
    if (last) {
        if (tid < 64) s_b1[tid] = __ldg(&b1[tid]);
        if (tid < 128) s_w2[tid] = __ldg(&W2[tid]);
        b2_0 = __ldg(&b2[0]); b2_1 = __ldg(&b2[1]);
    }

    PDL_WAIT();   // gather output (g_zh/g_zl) now visible

    // P0b: z hi/lo tiles (89.6KB)
    for (int i = tid; i < MROWS * 16; i += MTHREADS) {   // 2816
        int r = i >> 4, c = i & 15;
        size_t goff = (size_t)(row0 + r) * 256 + c * 16;
        cp_async16(sbase + OFF_ZH + r * 272 + c * 16, g_zh + goff);
        cp_async16(sbase + OFF_ZL + r * 272 + c * 16, g_zl + goff);
    }
    CP_COMMIT();
    CP_WAIT0();
    __syncthreads();

    const int m0 = warp * 32;                       // warp5 -> 160
    const bool two = (warp < 5);
    const int a_m0 = m0 + (lane & 15);
    const uint32_t a_koff = (uint32_t)((lane >> 4) * 16);
    const int b_n = (lane & 7) + ((lane >> 4) << 3);
    const int b_kc = (lane >> 3) & 1;
    const int m_r = m0 + (lane >> 2);

    float acc0[16][4], acc1[16][4];

    // ---- Stage 1: z @ Wa
    gemm_stage<8>(sbase, sbase + OFF_W, sbase + OFF_W + 32768,
                  a_m0, a_koff, b_n, b_kc, two, acc0, acc1);
    // t = relu(acc + ba) -> re-split into ZH/ZL (own rows only)
#pragma unroll
    for (int nt = 0; nt < 16; nt++) {
        int col = nt * 8 + 2 * (lane & 3);
        float b0 = s_ba[col], b1v = s_ba[col + 1];
        uint32_t hi, lo;
        bf16_split2(fmaxf(acc0[nt][0] + b0, 0.f),
                    fmaxf(acc0[nt][1] + b1v, 0.f), hi, lo);
        *(uint32_t*)(smem + OFF_ZH + m_r * 272 + col * 2) = hi;
        *(uint32_t*)(smem + OFF_ZL + m_r * 272 + col * 2) = lo;
        bf16_split2(fmaxf(acc0[nt][2] + b0, 0.f),
                    fmaxf(acc0[nt][3] + b1v, 0.f), hi, lo);
        *(uint32_t*)(smem + OFF_ZH + (m_r + 8) * 272 + col * 2) = hi;
        *(uint32_t*)(smem + OFF_ZL + (m_r + 8) * 272 + col * 2) = lo;
        if (two) {
            bf16_split2(fmaxf(acc1[nt][0] + b0, 0.f),
                        fmaxf(acc1[nt][1] + b1v, 0.f), hi, lo);
            *(uint32_t*)(smem + OFF_ZH + (m_r + 16) * 272 + col * 2) = hi;
            *(uint32_t*)(smem + OFF_ZL + (m_r + 16) * 272 + col * 2) = lo;
            bf16_split2(fmaxf(acc1[nt][2] + b0, 0.f),
                        fmaxf(acc1[nt][3] + b1v, 0.f), hi, lo);
            *(uint32_t*)(smem + OFF_ZH + (m_r + 24) * 272 + col * 2) = hi;
            *(uint32_t*)(smem + OFF_ZL + (m_r + 24) * 272 + col * 2) = lo;
        }
    }
    __syncwarp();

    // Last layer: WH1/WL1 region is dead after stage 1 -> prefetch W1 tiles
    if (last) {
        __syncthreads();
        const char* w1src = g_wt + 393216;
        for (int i = tid; i < 2048; i += MTHREADS)
            cp_async16(sbase + OFF_W + i * 16, w1src + i * 16);
        CP_COMMIT();
    }

    // ---- Stage 2: t @ Wb
    gemm_stage<8>(sbase, sbase + OFF_W + 65536, sbase + OFF_W + 98304,
                  a_m0, a_koff, b_n, b_kc, two, acc0, acc1);

    if (!last) {
        // h_out = relu(acc + bb) -> g_h
        int n0 = row0 + m_r;
#pragma unroll
        for (int nt = 0; nt < 16; nt++) {
            int col = nt * 8 + 2 * (lane & 3);
            float b0 = s_bb[col], b1v = s_bb[col + 1];
            if (n0 < N_NODES) {
                float2 o;
                o.x = fmaxf(acc0[nt][0] + b0, 0.f);
                o.y = fmaxf(acc0[nt][1] + b1v, 0.f);
                *(float2*)(g_h + (size_t)n0 * 128 + col) = o;
            }
            if (n0 + 8 < N_NODES) {
                float2 o;
                o.x = fmaxf(acc0[nt][2] + b0, 0.f);
                o.y = fmaxf(acc0[nt][3] + b1v, 0.f);
                *(float2*)(g_h + (size_t)(n0 + 8) * 128 + col) = o;
            }
            if (two) {
                if (n0 + 16 < N_NODES) {
                    float2 o;
                    o.x = fmaxf(acc1[nt][0] + b0, 0.f);
                    o.y = fmaxf(acc1[nt][1] + b1v, 0.f);
                    *(float2*)(g_h + (size_t)(n0 + 16) * 128 + col) = o;
                }
                if (n0 + 24 < N_NODES) {
                    float2 o;
                    o.x = fmaxf(acc1[nt][2] + b0, 0.f);
                    o.y = fmaxf(acc1[nt][3] + b1v, 0.f);
                    *(float2*)(g_h + (size_t)(n0 + 24) * 128 + col) = o;
                }
            }
        }
        return;
    }

    // ---- Last layer: h = relu(acc + bb) -> ZH/ZL (own rows), then head.
#pragma unroll
    for (int nt = 0; nt < 16; nt++) {
        int col = nt * 8 + 2 * (lane & 3);
        float b0 = s_bb[col], b1v = s_bb[col + 1];
        uint32_t hi, lo;
        bf16_split2(fmaxf(acc0[nt][0] + b0, 0.f),
                    fmaxf(acc0[nt][1] + b1v, 0.f), hi, lo);
        *(uint32_t*)(smem + OFF_ZH + m_r * 272 + col * 2) = hi;
        *(uint32_t*)(smem + OFF_ZL + m_r * 272 + col * 2) = lo;
        bf16_split2(fmaxf(acc0[nt][2] + b0, 0.f),
                    fmaxf(acc0[nt][3] + b1v, 0.f), hi, lo);
        *(uint32_t*)(smem + OFF_ZH + (m_r + 8) * 272 + col * 2) = hi;
        *(uint32_t*)(smem + OFF_ZL + (m_r + 8) * 272 + col * 2) = lo;
        if (two) {
            bf16_split2(fmaxf(acc1[nt][0] + b0, 0.f),
                        fmaxf(acc1[nt][1] + b1v, 0.f), hi, lo);
            *(uint32_t*)(smem + OFF_ZH + (m_r + 16) * 272 + col * 2) = hi;
            *(uint32_t*)(smem + OFF_ZL + (m_r + 16) * 272 + col * 2) = lo;
            bf16_split2(fmaxf(acc1[nt][2] + b0, 0.f),
                        fmaxf(acc1[nt][3] + b1v, 0.f), hi, lo);
            *(uint32_t*)(smem + OFF_ZH + (m_r + 24) * 272 + col * 2) = hi;
            *(uint32_t*)(smem + OFF_ZL + (m_r + 24) * 272 + col * 2) = lo;
        }
    }
    CP_WAIT0();
    __syncthreads();   // W1 tiles visible CTA-wide; own-row ZH writes ordered

    // ---- Stage 3: hid_pre = h @ W1 (N=64)
    gemm_stage<4>(sbase, sbase + OFF_W, sbase + OFF_W + 16384,
                  a_m0, a_koff, b_n, b_kc, two, acc0, acc1);

    // head epilogue: hid = relu(acc + b1); out = hid @ W2 + b2 (quad reduce)
    const int nrr = two ? 4 : 2;
    for (int rr = 0; rr < nrr; rr++) {
        float (*A)[4] = (rr < 2) ? acc0 : acc1;
        const int i0 = (rr & 1) ? 2 : 0;
        float p0 = 0.f, p1 = 0.f;
#pragma unroll
        for (int nt = 0; nt < 8; nt++) {
            int c = nt * 8 + 2 * (lane & 3);
            float v0 = fmaxf(A[nt][i0] + s_b1[c], 0.f);
            float v1 = fmaxf(A[nt][i0 + 1] + s_b1[c + 1], 0.f);
            p0 = fmaf(v0, s_w2[2 * c], fmaf(v1, s_w2[2 * c + 2], p0));
            p1 = fmaf(v0, s_w2[2 * c + 1], fmaf(v1, s_w2[2 * c + 3], p1));
        }
        p0 += __shfl_xor_sync(0xffffffffu, p0, 1);
        p0 += __shfl_xor_sync(0xffffffffu, p0, 2);
        p1 += __shfl_xor_sync(0xffffffffu, p1, 1);
        p1 += __shfl_xor_sync(0xffffffffu, p1, 2);
        int row = row0 + m_r + ((rr & 1) ? 8 : 0) + ((rr >= 2) ? 16 : 0);
        if ((lane & 3) == 0 && row < N_NODES) {
            float2 o;
            o.x = p0 + b2_0;
            o.y = p1 + b2_1;
            *(float2*)(out + (size_t)row * 2) = o;
        }
    }
}

// ---------------------------------------------------------------------------
// Host: all launches after the first use PDL stream serialization.
// ---------------------------------------------------------------------------
template <typename F, typename... Args>
static inline void launch_pdl(F* f, int grid, int block, size_t smem,
                              Args... args) {
    cudaLaunchConfig_t cfg = {};
    cfg.gridDim = dim3((unsigned)grid, 1, 1);
    cfg.blockDim = dim3((unsigned)block, 1, 1);
    cfg.dynamicSmemBytes = smem;
    cudaLaunchAttribute attr[1];
    attr[0].id = cudaLaunchAttributeProgrammaticStreamSerialization;
    attr[0].val.programmaticStreamSerializationAllowed = 1;
    cfg.attrs = attr;
    cfg.numAttrs = 1;
    cudaLaunchKernelEx(&cfg, f, args...);
}

extern "C" void kernel_launch(void* const* d_in, const int* in_sizes, int n_in,
                              void* d_out, int out_size) {
    const float* x   = (const float*)d_in[0];
    const void*  ei  = d_in[1];
    const float* eps = (const float*)d_in[2];
    const float* Wa  = (const float*)d_in[3];
    const float* ba  = (const float*)d_in[4];
    const float* Wb  = (const float*)d_in[5];
    const float* bb  = (const float*)d_in[6];
    const float* W1  = (const float*)d_in[7];
    const float* b1  = (const float*)d_in[8];
    const float* W2  = (const float*)d_in[9];
    const float* b2  = (const float*)d_in[10];
    float* out = (float*)d_out;

    cudaFuncSetAttribute(mlp_mma_kernel, cudaFuncAttributeMaxDynamicSharedMemorySize,
                         MLP_SMEM);

    const int init_blocks = (N_NODES + 53248 + 255) / 256;     // 404
    const int edge_blocks = (N_EDGES / 4 + 255) / 256;         // 782
    const int gather_blocks = (N_NODES * 32 + 255) / 256;      // warp per node
    const int mlp_blocks = (N_NODES + MROWS - 1) / MROWS;      // 285 -> 2 waves

    init_kernel<<<init_blocks, 256>>>((const long long*)ei, Wa, Wb, W1);
    launch_pdl(hist_kernel, edge_blocks, 256, 0, ei);
    launch_pdl(alloc_kernel, (N_NODES + 255) / 256, 256, 0);
    launch_pdl(fill_kernel, edge_blocks, 256, 0, ei);

    for (int l = 0; l < 3; l++) {
        launch_pdl(gather_kernel, gather_blocks, 256, 0,
                   x, l > 0 ? 1 : 0, eps, l);
        launch_pdl(mlp_mma_kernel, mlp_blocks, MTHREADS, (size_t)MLP_SMEM,
                   l, (l == 2) ? 1 : 0,
                   (const float*)(ba + (size_t)l * HID),
                   (const float*)(bb + (size_t)l * HID),
                   b1, W2, b2, out);
    }
}